// round 9
// baseline (speedup 1.0000x reference)
#include <cuda_runtime.h>

#define Nn 30000
#define Ee 480000
#define FULLMASK 0xffffffffu

typedef unsigned long long ull;

// packed fp32x2 helpers (Blackwell FFMA2 path — PTX only)
#define PACK2(d, lo, hi) asm("mov.b64 %0, {%1, %2};" : "=l"(d) : "f"(lo), "f"(hi))
#define UNPACK2(lo, hi, s) asm("mov.b64 {%0, %1}, %2;" : "=f"(lo), "=f"(hi) : "l"(s))
#define FMA2(acc, a, b) asm("fma.rn.f32x2 %0, %1, %2, %0;" : "+l"(acc) : "l"(a), "l"(b))

// float <-> order-preserving uint (exact; makes integer atomicMax a float max)
__device__ __forceinline__ unsigned ord_enc(float x) {
    unsigned b = __float_as_uint(x);
    return (b & 0x80000000u) ? ~b : (b | 0x80000000u);
}
__device__ __forceinline__ float ord_dec(unsigned k) {
    return (k & 0x80000000u) ? __uint_as_float(k & 0x7fffffffu) : __uint_as_float(~k);
}

// ---------------- scratch (static device allocations; no cudaMalloc) ----------------
__device__ __align__(16) float g_geom[Ee * 4];   // r, ux, uy, uz
__device__ __align__(16) float g_m0[Ee * 32];
__device__ __align__(16) float g_w[Ee * 64];     // layer0: [E][32] float2 (w3*f0s, w5*f0s)
__device__ __align__(16) float g_logit[Ee * 4];
__device__ __align__(16) float g_kt[Nn * 128];   // permuted: [(c>>3)*32 + h*8 + (c&7)]
__device__ __align__(16) unsigned g_mxbits[Nn * 4];  // per (node, head) running max (encoded)
__device__ float g_f0[Nn * 32];
__device__ float g_f1[Nn * 96];    // planar [n][3][32]
__device__ float g_f2[Nn * 160];   // planar [n][5][32]
__device__ float g_agg[Nn * 288];  // planar [n][9][32]
__device__ int g_deg[Nn];
__device__ int g_off[Nn + 1];
__device__ int g_cur[Nn];
__device__ int g_eid[Ee];

// kt permutation: value for (head h, channel c) stored at (c>>3)*32 + h*8 + (c&7)
__device__ __forceinline__ int kt_perm(int h, int c) {
    return ((c >> 3) << 5) + (h << 3) + (c & 7);
}

// ---------------- 1) init: copy f0, zero deg, init mx, kt for layer 0 (warp per node) ----------------
__global__ __launch_bounds__(256) void init_kt_kernel(const float* __restrict__ node_l0,
                                                      const float* __restrict__ Wq,
                                                      const float* __restrict__ Wk) {
    __shared__ float sWq[1024];    // [c][j]
    __shared__ float sWkT[1024];   // [j][c]
    int tid = threadIdx.x;
    for (int i = tid; i < 1024; i += 256) {
        sWq[i] = Wq[i];
        int c = i >> 5, j = i & 31;
        sWkT[j * 32 + c] = Wk[i];
    }
    __syncthreads();
    int warp = tid >> 5, lane = tid & 31;
    int n = blockIdx.x * 8 + warp;
    if (n >= Nn) return;
    float f = node_l0[(size_t)n * 32 + lane];
    g_f0[(size_t)n * 32 + lane] = f;
    if (lane == 0) g_deg[n] = 0;
    if (lane < 4) g_mxbits[n * 4 + lane] = 0u;   // encoded -inf floor for layer-0 max
    float q = 0.f;
#pragma unroll
    for (int c = 0; c < 32; c++) {
        float fc = __shfl_sync(FULLMASK, f, c);
        q = fmaf(fc, sWq[c * 32 + lane], q);
    }
#pragma unroll
    for (int h = 0; h < 4; h++) {
        float kt = 0.f;
#pragma unroll
        for (int d = 0; d < 8; d++) {
            float qd = __shfl_sync(FULLMASK, q, h * 8 + d);
            kt = fmaf(qd, sWkT[(h * 8 + d) * 32 + lane], kt);
        }
        g_kt[(size_t)n * 128 + kt_perm(h, lane)] = kt;
    }
}

// ---------------- 2) geometry + degree histogram ----------------
__global__ void geom_hist_kernel(const float* __restrict__ pos,
                                 const int* __restrict__ esrc,
                                 const int* __restrict__ edst) {
    int e = blockIdx.x * blockDim.x + threadIdx.x;
    if (e >= Ee) return;
    int s = esrc[e], d = edst[e];
    float rx = pos[d * 3 + 0] - pos[s * 3 + 0];
    float ry = pos[d * 3 + 1] - pos[s * 3 + 1];
    float rz = pos[d * 3 + 2] - pos[s * 3 + 2];
    float r = sqrtf(rx * rx + ry * ry + rz * rz + 1e-8f);
    float inv = 1.0f / r;
    ((float4*)g_geom)[e] = make_float4(r, rx * inv, ry * inv, rz * inv);
    atomicAdd(&g_deg[d], 1);
}

// ---------------- 3) exclusive scan (writes g_off and g_cur) ----------------
__global__ void scan_kernel() {
    __shared__ int sp[1024];
    const int CH = 30;
    int t = threadIdx.x;
    int loc[CH];
    int base = t * CH;
    int s = 0;
#pragma unroll
    for (int i = 0; i < CH; i++) {
        int idx = base + i;
        int v = (idx < Nn) ? g_deg[idx] : 0;
        loc[i] = v;
        s += v;
    }
    sp[t] = s;
    __syncthreads();
    for (int off = 1; off < 1024; off <<= 1) {
        int v = (t >= off) ? sp[t - off] : 0;
        __syncthreads();
        sp[t] += v;
        __syncthreads();
    }
    int run = (t == 0) ? 0 : sp[t - 1];
#pragma unroll
    for (int i = 0; i < CH; i++) {
        int idx = base + i;
        if (idx < Nn) { g_off[idx] = run; g_cur[idx] = run; run += loc[i]; }
    }
    if (t == 1023) g_off[Nn] = sp[1023];
}

// ---------------- 4/7) edge kernel: warp per 8 edges ----------------
// FIRST (layer0): planes = (w0, w3, w5); stores m0 + (w3*f0s, w5*f0s); fused CSR scatter.
// !FIRST (layer1): planes = (w0, w1, w2); stores m0 only (agg1/agg2 dead).
// Both: fused per-(dst,head) running max via integer atomicMax (exact float max).
template <bool FIRST>
__global__ __launch_bounds__(256) void edge_kernel(
    const float* __restrict__ edge_feat, const int* __restrict__ esrc,
    const int* __restrict__ edst, const float* __restrict__ Wr1,
    const float* __restrict__ br1, const float* __restrict__ Wr2) {
    __shared__ __align__(16) float sWr1[33 * 32];
    __shared__ float sbr1[32];
    __shared__ float sWp0[1024];   // [j][c] plane 0 (w0)
    __shared__ float sWp1[1024];   // plane 1 (w3 | w1)
    __shared__ float sWp2[1024];   // plane 2 (w5 | w2)
    __shared__ __align__(16) float sstage[8][256];  // [warp][i*8+k]
    int tid = threadIdx.x;
    for (int i = tid; i < 33 * 32; i += 256) sWr1[i] = Wr1[i];
    if (tid < 32) sbr1[tid] = br1[tid];
    const int off1 = FIRST ? 96 : 32, off2 = FIRST ? 160 : 64;
    for (int i = tid; i < 1024; i += 256) {
        int j = i >> 5, c = i & 31;
        const float* row = Wr2 + j * 224;
        sWp0[i] = row[c];
        sWp1[i] = row[off1 + c];
        sWp2[i] = row[off2 + c];
    }
    __syncthreads();
    int lane = tid & 31, warp = tid >> 5;
    int e0 = blockIdx.x * 64 + warp * 8;   // Ee % 64 == 0
    float* sst = sstage[warp];

    float t0, t1, t2, t3, t4, t5, t6, t7;
    t0 = edge_feat[(size_t)(e0 + 0) * 32 + lane];
    t1 = edge_feat[(size_t)(e0 + 1) * 32 + lane];
    t2 = edge_feat[(size_t)(e0 + 2) * 32 + lane];
    t3 = edge_feat[(size_t)(e0 + 3) * 32 + lane];
    t4 = edge_feat[(size_t)(e0 + 4) * 32 + lane];
    t5 = edge_feat[(size_t)(e0 + 5) * 32 + lane];
    t6 = edge_feat[(size_t)(e0 + 6) * 32 + lane];
    t7 = edge_feat[(size_t)(e0 + 7) * 32 + lane];
    {
        float4* sp = (float4*)(sst + lane * 8);
        sp[0] = make_float4(t0, t1, t2, t3);
        sp[1] = make_float4(t4, t5, t6, t7);
    }
    __syncwarp();

    float bia = sbr1[lane], w0l = sWr1[lane];
    t0 = fmaf(g_geom[(size_t)(e0 + 0) * 4], w0l, bia);
    t1 = fmaf(g_geom[(size_t)(e0 + 1) * 4], w0l, bia);
    t2 = fmaf(g_geom[(size_t)(e0 + 2) * 4], w0l, bia);
    t3 = fmaf(g_geom[(size_t)(e0 + 3) * 4], w0l, bia);
    t4 = fmaf(g_geom[(size_t)(e0 + 4) * 4], w0l, bia);
    t5 = fmaf(g_geom[(size_t)(e0 + 5) * 4], w0l, bia);
    t6 = fmaf(g_geom[(size_t)(e0 + 6) * 4], w0l, bia);
    t7 = fmaf(g_geom[(size_t)(e0 + 7) * 4], w0l, bia);
    ull h01, h23, h45, h67;
    PACK2(h01, t0, t1); PACK2(h23, t2, t3); PACK2(h45, t4, t5); PACK2(h67, t6, t7);
#pragma unroll
    for (int i = 0; i < 32; i++) {
        const ulonglong2* xp = (const ulonglong2*)(sst + i * 8);
        ulonglong2 xa = xp[0], xb = xp[1];   // LDS.128 x2 (broadcast)
        float wc = sWr1[(i + 1) * 32 + lane];
        ull wd; PACK2(wd, wc, wc);
        FMA2(h01, xa.x, wd); FMA2(h23, xa.y, wd); FMA2(h45, xb.x, wd); FMA2(h67, xb.y, wd);
    }
    UNPACK2(t0, t1, h01); UNPACK2(t2, t3, h23); UNPACK2(t4, t5, h45); UNPACK2(t6, t7, h67);
    t0 = fmaxf(t0, 0.f); t1 = fmaxf(t1, 0.f); t2 = fmaxf(t2, 0.f); t3 = fmaxf(t3, 0.f);
    t4 = fmaxf(t4, 0.f); t5 = fmaxf(t5, 0.f); t6 = fmaxf(t6, 0.f); t7 = fmaxf(t7, 0.f);
    __syncwarp();
    {
        float4* sp = (float4*)(sst + lane * 8);
        sp[0] = make_float4(t0, t1, t2, t3);
        sp[1] = make_float4(t4, t5, t6, t7);
    }
    __syncwarp();

    ull a0[4] = {0, 0, 0, 0}, a1[4] = {0, 0, 0, 0}, a2[4] = {0, 0, 0, 0};
#pragma unroll
    for (int j = 0; j < 32; j++) {
        const ulonglong2* hp = (const ulonglong2*)(sst + j * 8);
        ulonglong2 ha = hp[0], hb = hp[1];   // LDS.128 x2 (broadcast)
        float w0c = sWp0[j * 32 + lane];     // 3 scalar LDS.32 (1 wf each)
        float w1c = sWp1[j * 32 + lane];
        float w2c = sWp2[j * 32 + lane];
        ull p0, p1, p2;
        PACK2(p0, w0c, w0c); PACK2(p1, w1c, w1c); PACK2(p2, w2c, w2c);
        FMA2(a0[0], ha.x, p0); FMA2(a0[1], ha.y, p0); FMA2(a0[2], hb.x, p0); FMA2(a0[3], hb.y, p0);
        FMA2(a1[0], ha.x, p1); FMA2(a1[1], ha.y, p1); FMA2(a1[2], hb.x, p1); FMA2(a1[3], hb.y, p1);
        FMA2(a2[0], ha.x, p2); FMA2(a2[1], ha.y, p2); FMA2(a2[2], hb.x, p2); FMA2(a2[3], hb.y, p2);
    }

    int sub = lane & 7;
#pragma unroll
    for (int q2 = 0; q2 < 4; q2++) {
        float W0a, W0b, W1a, W1b, W2a, W2b;
        UNPACK2(W0a, W0b, a0[q2]);
        UNPACK2(W1a, W1b, a1[q2]);
        UNPACK2(W2a, W2b, a2[q2]);
#pragma unroll
        for (int kk = 0; kk < 2; kk++) {
            int e = e0 + q2 * 2 + kk;
            float W0 = kk ? W0b : W0a, W1 = kk ? W1b : W1a, W2 = kk ? W2b : W2a;
            int src = esrc[e], dst = edst[e];
            float f0s = g_f0[(size_t)src * 32 + lane];
            float m0;
            if (FIRST) {
                m0 = W0 * f0s;
                ((float2*)g_w)[(size_t)e * 32 + lane] = make_float2(W1 * f0s, W2 * f0s);
            } else {
                float4 gm = ((const float4*)g_geom)[e];
                float ux = gm.y, uy = gm.z, uz = gm.w;
                const float* f1p = &g_f1[(size_t)src * 96];
                const float* f2p = &g_f2[(size_t)src * 160];
                float d1 = f1p[lane] * ux + f1p[32 + lane] * uy + f1p[64 + lane] * uz;
                float s0 = ux * uy, s1 = uy * uz, s2 = 3.f * uz * uz - 1.f;
                float s3 = ux * uz, s4 = ux * ux - uy * uy;
                float d2 = f2p[lane] * s0 + f2p[32 + lane] * s1 + f2p[64 + lane] * s2 +
                           f2p[96 + lane] * s3 + f2p[128 + lane] * s4;
                m0 = fmaf(W1, d1, fmaf(W2, d2, W0 * f0s));
            }
            g_m0[(size_t)e * 32 + lane] = m0;
            const float* ktp = &g_kt[(size_t)dst * 128];
            float v = 0.f;
#pragma unroll
            for (int k2 = 0; k2 < 4; k2++) {
                float mc = __shfl_sync(FULLMASK, m0, sub + 8 * k2);
                v = fmaf(mc, ktp[k2 * 32 + lane], v);
            }
            v += __shfl_xor_sync(FULLMASK, v, 1);
            v += __shfl_xor_sync(FULLMASK, v, 2);
            v += __shfl_xor_sync(FULLMASK, v, 4);
            if (sub == 0) {
                float lg = v * 0.35355339059327373f;
                g_logit[(size_t)e * 4 + (lane >> 3)] = lg;
                atomicMax(&g_mxbits[dst * 4 + (lane >> 3)], ord_enc(lg));
            }
            if (FIRST && lane == 0) {   // fused CSR scatter (order within segment irrelevant)
                int p = atomicAdd(&g_cur[dst], 1);
                g_eid[p] = e;
            }
        }
    }
}

// ---------------- 5) layer-0 aggregation: SINGLE pass (max precomputed) ----------------
__global__ __launch_bounds__(256) void agg_l0_kernel() {
    int tid = threadIdx.x;
    int lane = tid & 31;
    int n = blockIdx.x * 8 + (tid >> 5);
    if (n >= Nn) return;
    int beg = g_off[n], end = g_off[n + 1];
    int grp = lane >> 3;
    float mx = ord_dec(g_mxbits[n * 4 + grp]);

    float den = 0.f;
    float a0 = 0.f, a10 = 0.f, a11 = 0.f, a12 = 0.f;
    float a20 = 0.f, a21 = 0.f, a22 = 0.f, a23 = 0.f, a24 = 0.f;
#pragma unroll 2
    for (int i = beg; i < end; i++) {
        int eid = g_eid[i];
        float ee = __expf(g_logit[(size_t)eid * 4 + grp] - mx);
        den += ee;
        float m0 = g_m0[(size_t)eid * 32 + lane];
        float4 gm = ((const float4*)g_geom)[eid];
        float ux = gm.y, uy = gm.z, uz = gm.w;
        a0 = fmaf(ee, m0, a0);
        float y0 = ux * uy, y1 = uy * uz, y2 = 3.f * uz * uz - 1.f;
        float y3 = ux * uz, y4 = ux * ux - uy * uy;
        float2 w = ((const float2*)g_w)[(size_t)eid * 32 + lane];
        float wf3 = w.x * ee, wf5 = w.y * ee;
        a10 = fmaf(wf3, ux, a10); a11 = fmaf(wf3, uy, a11); a12 = fmaf(wf3, uz, a12);
        a20 = fmaf(wf5, y0, a20); a21 = fmaf(wf5, y1, a21); a22 = fmaf(wf5, y2, a22);
        a23 = fmaf(wf5, y3, a23); a24 = fmaf(wf5, y4, a24);
    }
    float dinv = 1.f / (den + 1e-8f);
    float* ag = &g_agg[(size_t)n * 288];   // planar [9][32]
    ag[0 * 32 + lane] = a0 * dinv;
    ag[1 * 32 + lane] = a10 * dinv; ag[2 * 32 + lane] = a11 * dinv; ag[3 * 32 + lane] = a12 * dinv;
    ag[4 * 32 + lane] = a20 * dinv; ag[5 * 32 + lane] = a21 * dinv; ag[6 * 32 + lane] = a22 * dinv;
    ag[7 * 32 + lane] = a23 * dinv; ag[8 * 32 + lane] = a24 * dinv;
}

// ---------------- 6) layer-0 update (writes f0,f1,f2 planar) + kt + mx-reinit for layer 1 ----------------
__global__ __launch_bounds__(256) void update_l0_kt_kernel(
    const float* __restrict__ Ws0, const float* __restrict__ Ws1,
    const float* __restrict__ Ws2, const float* __restrict__ Wsk,
    const float* __restrict__ Wq, const float* __restrict__ Wk) {
    __shared__ __align__(16) float s0[1024], s1[1024], s2[1024], sk[1024];
    __shared__ float sWq[1024], sWkT[1024];
    __shared__ __align__(16) float sag[8][384];   // [c][12] padded
    int tid = threadIdx.x;
    for (int i = tid; i < 1024; i += 256) {
        s0[i] = Ws0[i]; s1[i] = Ws1[i]; s2[i] = Ws2[i]; sk[i] = Wsk[i];
        sWq[i] = Wq[i];
        int c = i >> 5, j = i & 31;
        sWkT[j * 32 + c] = Wk[i];
    }
    __syncthreads();
    int warp = tid >> 5, lane = tid & 31;
    int n = blockIdx.x * 8 + warp;
    if (n >= Nn) return;
    if (lane < 4) g_mxbits[n * 4 + lane] = 0u;   // reinit for layer-1 max
    float f = g_f0[(size_t)n * 32 + lane];
    {
        const float* ag = &g_agg[(size_t)n * 288];
#pragma unroll
        for (int s = 0; s < 9; s++)
            sag[warp][lane * 12 + s] = ag[s * 32 + lane];
    }
    __syncwarp();
    float o0 = 0.f, o10 = 0.f, o11 = 0.f, o12 = 0.f;
    float o20 = 0.f, o21 = 0.f, o22 = 0.f, o23 = 0.f, o24 = 0.f;
#pragma unroll 4
    for (int c = 0; c < 32; c++) {
        const float* ac = &sag[warp][c * 12];
        float4 A0 = *(const float4*)ac;
        float4 A1 = *(const float4*)(ac + 4);
        float A8 = ac[8];
        float fc = __shfl_sync(FULLMASK, f, c);
        o0 += A0.x * s0[c * 32 + lane] + fc * sk[c * 32 + lane];
        float w1 = s1[c * 32 + lane];
        o10 += A0.y * w1; o11 += A0.z * w1; o12 += A0.w * w1;
        float w2 = s2[c * 32 + lane];
        o20 += A1.x * w2; o21 += A1.y * w2; o22 += A1.z * w2;
        o23 += A1.w * w2; o24 += A8 * w2;
    }
    g_f0[(size_t)n * 32 + lane] = o0;
    float* f1w = &g_f1[(size_t)n * 96];
    f1w[0 * 32 + lane] = o10; f1w[1 * 32 + lane] = o11; f1w[2 * 32 + lane] = o12;
    float* f2w = &g_f2[(size_t)n * 160];
    f2w[0 * 32 + lane] = o20; f2w[1 * 32 + lane] = o21; f2w[2 * 32 + lane] = o22;
    f2w[3 * 32 + lane] = o23; f2w[4 * 32 + lane] = o24;
    float q = 0.f;
#pragma unroll
    for (int c = 0; c < 32; c++) {
        float fc = __shfl_sync(FULLMASK, o0, c);
        q = fmaf(fc, sWq[c * 32 + lane], q);
    }
#pragma unroll
    for (int h = 0; h < 4; h++) {
        float kt = 0.f;
#pragma unroll
        for (int d = 0; d < 8; d++) {
            float qd = __shfl_sync(FULLMASK, q, h * 8 + d);
            kt = fmaf(qd, sWkT[(h * 8 + d) * 32 + lane], kt);
        }
        g_kt[(size_t)n * 128 + kt_perm(h, lane)] = kt;
    }
}

// ---------------- 8) fused layer-1 aggregation (single pass) + f0 update + output ----------------
__global__ __launch_bounds__(256) void agg_update_out_kernel(
    const float* __restrict__ Ws0, const float* __restrict__ Wsk,
    const float* __restrict__ Wout, const float* __restrict__ Wc,
    float* __restrict__ out) {
    __shared__ __align__(16) float s0[1024], sk[1024], sWo[1024];
    __shared__ float sWc[480];
    int tid = threadIdx.x;
    for (int i = tid; i < 1024; i += 256) {
        s0[i] = Ws0[i]; sk[i] = Wsk[i]; sWo[i] = Wout[i];
    }
    for (int i = tid; i < 480; i += 256) sWc[i] = Wc[i];
    __syncthreads();
    int warp = tid >> 5, lane = tid & 31;
    int n = blockIdx.x * 8 + warp;
    if (n >= Nn) return;
    int beg = g_off[n], end = g_off[n + 1];
    int grp = lane >> 3;
    float mx = ord_dec(g_mxbits[n * 4 + grp]);

    float den = 0.f, a0 = 0.f;
#pragma unroll 2
    for (int i = beg; i < end; i++) {
        int eid = g_eid[i];
        float ee = __expf(g_logit[(size_t)eid * 4 + grp] - mx);
        den += ee;
        a0 = fmaf(ee, g_m0[(size_t)eid * 32 + lane], a0);
    }
    float a = a0 / (den + 1e-8f);   // agg0[n][lane], stays in registers

    float f = g_f0[(size_t)n * 32 + lane];
    float o0 = 0.f;
#pragma unroll
    for (int c = 0; c < 32; c++) {
        float fc = __shfl_sync(FULLMASK, f, c);
        float ac = __shfl_sync(FULLMASK, a, c);
        o0 += ac * s0[c * 32 + lane] + fc * sk[c * 32 + lane];
    }
    float hs = 0.f;
#pragma unroll
    for (int c = 0; c < 32; c++) {
        float oc = __shfl_sync(FULLMASK, o0, c);
        hs = fmaf(oc, sWo[c * 32 + lane], hs);
    }
    out[(size_t)n * 32 + lane] = hs;
    float cacc = 0.f;
#pragma unroll
    for (int j = 0; j < 32; j++) {
        float hj = __shfl_sync(FULLMASK, hs, j);
        if (lane < 15) cacc = fmaf(hj, sWc[j * 15 + lane], cacc);
    }
    if (lane < 15) out[(size_t)Nn * 32 + (size_t)n * 15 + lane] = cacc;
}

// ---------------- launch ----------------
extern "C" void kernel_launch(void* const* d_in, const int* in_sizes, int n_in,
                              void* d_out, int out_size) {
    const float* pos       = (const float*)d_in[0];
    const float* node_l0   = (const float*)d_in[1];
    const float* edge_feat = (const float*)d_in[2];
    const int*   esrc      = (const int*)d_in[3];
    const int*   edst      = (const int*)d_in[4];
    const float* Wr1       = (const float*)d_in[5];
    const float* br1       = (const float*)d_in[6];
    const float* Wr2       = (const float*)d_in[7];
    const float* Wq        = (const float*)d_in[8];
    const float* Wk        = (const float*)d_in[9];
    const float* Ws0       = (const float*)d_in[10];
    const float* Ws1       = (const float*)d_in[11];
    const float* Ws2       = (const float*)d_in[12];
    const float* Wsk       = (const float*)d_in[13];
    const float* Wout      = (const float*)d_in[14];
    const float* Wc        = (const float*)d_in[15];
    float* out = (float*)d_out;

    const int NODE_BLKS = (Nn + 7) / 8;
    const int EDGE_BLKS = Ee / 64;   // warp per 8 edges, 8 warps / block

    init_kt_kernel<<<NODE_BLKS, 256>>>(node_l0, Wq, Wk);                           // 1
    geom_hist_kernel<<<(Ee + 255) / 256, 256>>>(pos, esrc, edst);                  // 2
    scan_kernel<<<1, 1024>>>();                                                    // 3
    edge_kernel<true><<<EDGE_BLKS, 256>>>(edge_feat, esrc, edst, Wr1, br1, Wr2);   // 4 (profiled; fused scatter+max)
    agg_l0_kernel<<<NODE_BLKS, 256>>>();                                           // 5
    update_l0_kt_kernel<<<NODE_BLKS, 256>>>(Ws0, Ws1, Ws2, Wsk,
                                            Wq + 1024, Wk + 1024);                 // 6
    edge_kernel<false><<<EDGE_BLKS, 256>>>(edge_feat, esrc, edst, Wr1 + 1056,
                                           br1 + 32, Wr2 + 7168);                  // 7
    agg_update_out_kernel<<<NODE_BLKS, 256>>>(Ws0 + 1024, Wsk + 1024, Wout, Wc, out); // 8
}

// round 10
// speedup vs baseline: 1.0474x; 1.0474x over previous
#include <cuda_runtime.h>

#define Nn 30000
#define Ee 480000
#define FULLMASK 0xffffffffu

typedef unsigned long long ull;

// packed fp32x2 helpers (Blackwell FFMA2 path — PTX only)
#define PACK2(d, lo, hi) asm("mov.b64 %0, {%1, %2};" : "=l"(d) : "f"(lo), "f"(hi))
#define UNPACK2(lo, hi, s) asm("mov.b64 {%0, %1}, %2;" : "=f"(lo), "=f"(hi) : "l"(s))
#define FMA2(acc, a, b) asm("fma.rn.f32x2 %0, %1, %2, %0;" : "+l"(acc) : "l"(a), "l"(b))

// ---------------- scratch (static device allocations; no cudaMalloc) ----------------
__device__ __align__(16) float g_geom[Ee * 4];   // r, ux, uy, uz
__device__ __align__(16) float g_m0[Ee * 32];
__device__ __align__(16) float g_w[Ee * 64];     // layer0: [E][32] float2 (w3*f0s, w5*f0s)
__device__ __align__(16) float g_logit[Ee * 4];
__device__ __align__(16) float g_kt[Nn * 128];   // permuted + pre-scaled by 1/sqrt(8)
__device__ float g_f0[Nn * 32];
__device__ float g_f1[Nn * 96];    // planar [n][3][32]
__device__ float g_f2[Nn * 160];   // planar [n][5][32]
__device__ float g_agg[Nn * 288];  // planar [n][9][32]
__device__ int g_deg[Nn];
__device__ int g_off[Nn + 1];
__device__ int g_cur[Nn];
__device__ int g_eid[Ee];

// kt permutation: value for (head h, channel c) stored at (c>>3)*32 + h*8 + (c&7)
__device__ __forceinline__ int kt_perm(int h, int c) {
    return ((c >> 3) << 5) + (h << 3) + (c & 7);
}

#define LOGIT_SCALE 0.35355339059327373f   // 1/sqrt(8), folded into kt

// ---------------- 1) init: copy f0, zero deg, kt for layer 0 (warp per node) ----------------
__global__ __launch_bounds__(256) void init_kt_kernel(const float* __restrict__ node_l0,
                                                      const float* __restrict__ Wq,
                                                      const float* __restrict__ Wk) {
    __shared__ float sWq[1024];    // [c][j]
    __shared__ float sWkT[1024];   // [j][c]
    int tid = threadIdx.x;
    for (int i = tid; i < 1024; i += 256) {
        sWq[i] = Wq[i];
        int c = i >> 5, j = i & 31;
        sWkT[j * 32 + c] = Wk[i];
    }
    __syncthreads();
    int warp = tid >> 5, lane = tid & 31;
    int n = blockIdx.x * 8 + warp;
    if (n >= Nn) return;
    float f = node_l0[(size_t)n * 32 + lane];
    g_f0[(size_t)n * 32 + lane] = f;
    if (lane == 0) g_deg[n] = 0;
    float q = 0.f;
#pragma unroll
    for (int c = 0; c < 32; c++) {
        float fc = __shfl_sync(FULLMASK, f, c);
        q = fmaf(fc, sWq[c * 32 + lane], q);
    }
#pragma unroll
    for (int h = 0; h < 4; h++) {
        float kt = 0.f;
#pragma unroll
        for (int d = 0; d < 8; d++) {
            float qd = __shfl_sync(FULLMASK, q, h * 8 + d);
            kt = fmaf(qd, sWkT[(h * 8 + d) * 32 + lane], kt);
        }
        g_kt[(size_t)n * 128 + kt_perm(h, lane)] = kt * LOGIT_SCALE;
    }
}

// ---------------- 2) geometry + degree histogram ----------------
__global__ void geom_hist_kernel(const float* __restrict__ pos,
                                 const int* __restrict__ esrc,
                                 const int* __restrict__ edst) {
    int e = blockIdx.x * blockDim.x + threadIdx.x;
    if (e >= Ee) return;
    int s = esrc[e], d = edst[e];
    float rx = pos[d * 3 + 0] - pos[s * 3 + 0];
    float ry = pos[d * 3 + 1] - pos[s * 3 + 1];
    float rz = pos[d * 3 + 2] - pos[s * 3 + 2];
    float r = sqrtf(rx * rx + ry * ry + rz * rz + 1e-8f);
    float inv = 1.0f / r;
    ((float4*)g_geom)[e] = make_float4(r, rx * inv, ry * inv, rz * inv);
    atomicAdd(&g_deg[d], 1);
}

// ---------------- 3) exclusive scan (writes g_off and g_cur) ----------------
__global__ void scan_kernel() {
    __shared__ int sp[1024];
    const int CH = 30;
    int t = threadIdx.x;
    int loc[CH];
    int base = t * CH;
    int s = 0;
#pragma unroll
    for (int i = 0; i < CH; i++) {
        int idx = base + i;
        int v = (idx < Nn) ? g_deg[idx] : 0;
        loc[i] = v;
        s += v;
    }
    sp[t] = s;
    __syncthreads();
    for (int off = 1; off < 1024; off <<= 1) {
        int v = (t >= off) ? sp[t - off] : 0;
        __syncthreads();
        sp[t] += v;
        __syncthreads();
    }
    int run = (t == 0) ? 0 : sp[t - 1];
#pragma unroll
    for (int i = 0; i < CH; i++) {
        int idx = base + i;
        if (idx < Nn) { g_off[idx] = run; g_cur[idx] = run; run += loc[i]; }
    }
    if (t == 1023) g_off[Nn] = sp[1023];
}

// ---------------- 4/7) edge kernel: warp per 8 edges ----------------
// FIRST (layer0): planes = (w0, w3, w5); stores m0 + (w3*f0s, w5*f0s); fused CSR scatter.
// !FIRST (layer1): planes = (w0, w1, w2); stores m0 only (agg1/agg2 dead).
template <bool FIRST>
__global__ __launch_bounds__(256) void edge_kernel(
    const float* __restrict__ edge_feat, const int* __restrict__ esrc,
    const int* __restrict__ edst, const float* __restrict__ Wr1,
    const float* __restrict__ br1, const float* __restrict__ Wr2) {
    __shared__ __align__(16) float sWr1[33 * 32];
    __shared__ float sbr1[32];
    __shared__ float sWp0[1024];   // [j][c] plane 0 (w0)
    __shared__ float sWp1[1024];   // plane 1 (w3 | w1)
    __shared__ float sWp2[1024];   // plane 2 (w5 | w2)
    __shared__ __align__(16) float sstage[8][256];  // [warp][i*8+k]
    int tid = threadIdx.x;
    for (int i = tid; i < 33 * 32; i += 256) sWr1[i] = Wr1[i];
    if (tid < 32) sbr1[tid] = br1[tid];
    const int off1 = FIRST ? 96 : 32, off2 = FIRST ? 160 : 64;
    for (int i = tid; i < 1024; i += 256) {
        int j = i >> 5, c = i & 31;
        const float* row = Wr2 + j * 224;
        sWp0[i] = row[c];
        sWp1[i] = row[off1 + c];
        sWp2[i] = row[off2 + c];
    }
    __syncthreads();
    int lane = tid & 31, warp = tid >> 5;
    int e0 = blockIdx.x * 64 + warp * 8;   // Ee % 64 == 0
    float* sst = sstage[warp];

    float t0, t1, t2, t3, t4, t5, t6, t7;
    t0 = edge_feat[(size_t)(e0 + 0) * 32 + lane];
    t1 = edge_feat[(size_t)(e0 + 1) * 32 + lane];
    t2 = edge_feat[(size_t)(e0 + 2) * 32 + lane];
    t3 = edge_feat[(size_t)(e0 + 3) * 32 + lane];
    t4 = edge_feat[(size_t)(e0 + 4) * 32 + lane];
    t5 = edge_feat[(size_t)(e0 + 5) * 32 + lane];
    t6 = edge_feat[(size_t)(e0 + 6) * 32 + lane];
    t7 = edge_feat[(size_t)(e0 + 7) * 32 + lane];
    {
        float4* sp = (float4*)(sst + lane * 8);
        sp[0] = make_float4(t0, t1, t2, t3);
        sp[1] = make_float4(t4, t5, t6, t7);
    }
    __syncwarp();

    float bia = sbr1[lane], w0l = sWr1[lane];
    t0 = fmaf(g_geom[(size_t)(e0 + 0) * 4], w0l, bia);
    t1 = fmaf(g_geom[(size_t)(e0 + 1) * 4], w0l, bia);
    t2 = fmaf(g_geom[(size_t)(e0 + 2) * 4], w0l, bia);
    t3 = fmaf(g_geom[(size_t)(e0 + 3) * 4], w0l, bia);
    t4 = fmaf(g_geom[(size_t)(e0 + 4) * 4], w0l, bia);
    t5 = fmaf(g_geom[(size_t)(e0 + 5) * 4], w0l, bia);
    t6 = fmaf(g_geom[(size_t)(e0 + 6) * 4], w0l, bia);
    t7 = fmaf(g_geom[(size_t)(e0 + 7) * 4], w0l, bia);
    ull h01, h23, h45, h67;
    PACK2(h01, t0, t1); PACK2(h23, t2, t3); PACK2(h45, t4, t5); PACK2(h67, t6, t7);
#pragma unroll
    for (int i = 0; i < 32; i++) {
        const ulonglong2* xp = (const ulonglong2*)(sst + i * 8);
        ulonglong2 xa = xp[0], xb = xp[1];   // LDS.128 x2 (broadcast)
        float wc = sWr1[(i + 1) * 32 + lane];
        ull wd; PACK2(wd, wc, wc);
        FMA2(h01, xa.x, wd); FMA2(h23, xa.y, wd); FMA2(h45, xb.x, wd); FMA2(h67, xb.y, wd);
    }
    UNPACK2(t0, t1, h01); UNPACK2(t2, t3, h23); UNPACK2(t4, t5, h45); UNPACK2(t6, t7, h67);
    t0 = fmaxf(t0, 0.f); t1 = fmaxf(t1, 0.f); t2 = fmaxf(t2, 0.f); t3 = fmaxf(t3, 0.f);
    t4 = fmaxf(t4, 0.f); t5 = fmaxf(t5, 0.f); t6 = fmaxf(t6, 0.f); t7 = fmaxf(t7, 0.f);
    __syncwarp();
    {
        float4* sp = (float4*)(sst + lane * 8);
        sp[0] = make_float4(t0, t1, t2, t3);
        sp[1] = make_float4(t4, t5, t6, t7);
    }
    __syncwarp();

    ull a0[4] = {0, 0, 0, 0}, a1[4] = {0, 0, 0, 0}, a2[4] = {0, 0, 0, 0};
#pragma unroll
    for (int j = 0; j < 32; j++) {
        const ulonglong2* hp = (const ulonglong2*)(sst + j * 8);
        ulonglong2 ha = hp[0], hb = hp[1];   // LDS.128 x2 (broadcast)
        float w0c = sWp0[j * 32 + lane];     // 3 scalar LDS.32 (1 wf each)
        float w1c = sWp1[j * 32 + lane];
        float w2c = sWp2[j * 32 + lane];
        ull p0, p1, p2;
        PACK2(p0, w0c, w0c); PACK2(p1, w1c, w1c); PACK2(p2, w2c, w2c);
        FMA2(a0[0], ha.x, p0); FMA2(a0[1], ha.y, p0); FMA2(a0[2], hb.x, p0); FMA2(a0[3], hb.y, p0);
        FMA2(a1[0], ha.x, p1); FMA2(a1[1], ha.y, p1); FMA2(a1[2], hb.x, p1); FMA2(a1[3], hb.y, p1);
        FMA2(a2[0], ha.x, p2); FMA2(a2[1], ha.y, p2); FMA2(a2[2], hb.x, p2); FMA2(a2[3], hb.y, p2);
    }

    int sub = lane & 7;
#pragma unroll
    for (int q2 = 0; q2 < 4; q2++) {
        float W0a, W0b, W1a, W1b, W2a, W2b;
        UNPACK2(W0a, W0b, a0[q2]);
        UNPACK2(W1a, W1b, a1[q2]);
        UNPACK2(W2a, W2b, a2[q2]);
#pragma unroll
        for (int kk = 0; kk < 2; kk++) {
            int e = e0 + q2 * 2 + kk;
            float W0 = kk ? W0b : W0a, W1 = kk ? W1b : W1a, W2 = kk ? W2b : W2a;
            int src = esrc[e], dst = edst[e];
            float f0s = g_f0[(size_t)src * 32 + lane];
            float m0;
            if (FIRST) {
                m0 = W0 * f0s;
                ((float2*)g_w)[(size_t)e * 32 + lane] = make_float2(W1 * f0s, W2 * f0s);
            } else {
                float4 gm = ((const float4*)g_geom)[e];
                float ux = gm.y, uy = gm.z, uz = gm.w;
                const float* f1p = &g_f1[(size_t)src * 96];
                const float* f2p = &g_f2[(size_t)src * 160];
                float d1 = f1p[lane] * ux + f1p[32 + lane] * uy + f1p[64 + lane] * uz;
                float s0 = ux * uy, s1 = uy * uz, s2 = 3.f * uz * uz - 1.f;
                float s3 = ux * uz, s4 = ux * ux - uy * uy;
                float d2 = f2p[lane] * s0 + f2p[32 + lane] * s1 + f2p[64 + lane] * s2 +
                           f2p[96 + lane] * s3 + f2p[128 + lane] * s4;
                m0 = fmaf(W1, d1, fmaf(W2, d2, W0 * f0s));
            }
            g_m0[(size_t)e * 32 + lane] = m0;
            const float* ktp = &g_kt[(size_t)dst * 128];
            float v = 0.f;
#pragma unroll
            for (int k2 = 0; k2 < 4; k2++) {
                float mc = __shfl_sync(FULLMASK, m0, sub + 8 * k2);
                v = fmaf(mc, ktp[k2 * 32 + lane], v);
            }
            v += __shfl_xor_sync(FULLMASK, v, 1);
            v += __shfl_xor_sync(FULLMASK, v, 2);
            v += __shfl_xor_sync(FULLMASK, v, 4);
            if (sub == 0)
                g_logit[(size_t)e * 4 + (lane >> 3)] = v;   // kt pre-scaled by 1/sqrt(8)
            if (FIRST && lane == 0) {   // fused CSR scatter (order within segment irrelevant)
                int p = atomicAdd(&g_cur[dst], 1);
                g_eid[p] = e;
            }
        }
    }
}

// ---------------- 5) layer-0 aggregation: ONLINE softmax, single pass ----------------
__global__ __launch_bounds__(256) void agg_l0_kernel() {
    int tid = threadIdx.x;
    int lane = tid & 31;
    int n = blockIdx.x * 8 + (tid >> 5);
    if (n >= Nn) return;
    int beg = g_off[n], end = g_off[n + 1];
    int grp = lane >> 3;

    float mx = -3.0e38f;
    float den = 0.f;
    float a0 = 0.f, a10 = 0.f, a11 = 0.f, a12 = 0.f;
    float a20 = 0.f, a21 = 0.f, a22 = 0.f, a23 = 0.f, a24 = 0.f;
    for (int i = beg; i < end; i++) {
        int eid = g_eid[i];
        float lg = g_logit[(size_t)eid * 4 + grp];
        if (lg > mx) {   // expected ~ln(deg) times; rescale accumulators
            float corr = __expf(mx - lg);   // first hit: exp(-3e38 - lg) -> 0 (accums are 0)
            den *= corr; a0 *= corr;
            a10 *= corr; a11 *= corr; a12 *= corr;
            a20 *= corr; a21 *= corr; a22 *= corr; a23 *= corr; a24 *= corr;
            mx = lg;
        }
        float ee = __expf(lg - mx);
        den += ee;
        float m0 = g_m0[(size_t)eid * 32 + lane];
        float4 gm = ((const float4*)g_geom)[eid];
        float ux = gm.y, uy = gm.z, uz = gm.w;
        a0 = fmaf(ee, m0, a0);
        float y0 = ux * uy, y1 = uy * uz, y2 = 3.f * uz * uz - 1.f;
        float y3 = ux * uz, y4 = ux * ux - uy * uy;
        float2 w = ((const float2*)g_w)[(size_t)eid * 32 + lane];
        float wf3 = w.x * ee, wf5 = w.y * ee;
        a10 = fmaf(wf3, ux, a10); a11 = fmaf(wf3, uy, a11); a12 = fmaf(wf3, uz, a12);
        a20 = fmaf(wf5, y0, a20); a21 = fmaf(wf5, y1, a21); a22 = fmaf(wf5, y2, a22);
        a23 = fmaf(wf5, y3, a23); a24 = fmaf(wf5, y4, a24);
    }
    float dinv = 1.f / (den + 1e-8f);
    float* ag = &g_agg[(size_t)n * 288];   // planar [9][32]
    ag[0 * 32 + lane] = a0 * dinv;
    ag[1 * 32 + lane] = a10 * dinv; ag[2 * 32 + lane] = a11 * dinv; ag[3 * 32 + lane] = a12 * dinv;
    ag[4 * 32 + lane] = a20 * dinv; ag[5 * 32 + lane] = a21 * dinv; ag[6 * 32 + lane] = a22 * dinv;
    ag[7 * 32 + lane] = a23 * dinv; ag[8 * 32 + lane] = a24 * dinv;
}

// ---------------- 6) layer-0 update (writes f0,f1,f2 planar) + kt for layer 1 ----------------
__global__ __launch_bounds__(256) void update_l0_kt_kernel(
    const float* __restrict__ Ws0, const float* __restrict__ Ws1,
    const float* __restrict__ Ws2, const float* __restrict__ Wsk,
    const float* __restrict__ Wq, const float* __restrict__ Wk) {
    __shared__ __align__(16) float s0[1024], s1[1024], s2[1024], sk[1024];
    __shared__ float sWq[1024], sWkT[1024];
    __shared__ __align__(16) float sag[8][384];   // [c][12] padded
    int tid = threadIdx.x;
    for (int i = tid; i < 1024; i += 256) {
        s0[i] = Ws0[i]; s1[i] = Ws1[i]; s2[i] = Ws2[i]; sk[i] = Wsk[i];
        sWq[i] = Wq[i];
        int c = i >> 5, j = i & 31;
        sWkT[j * 32 + c] = Wk[i];
    }
    __syncthreads();
    int warp = tid >> 5, lane = tid & 31;
    int n = blockIdx.x * 8 + warp;
    if (n >= Nn) return;
    float f = g_f0[(size_t)n * 32 + lane];
    {
        const float* ag = &g_agg[(size_t)n * 288];
#pragma unroll
        for (int s = 0; s < 9; s++)
            sag[warp][lane * 12 + s] = ag[s * 32 + lane];
    }
    __syncwarp();
    float o0 = 0.f, o10 = 0.f, o11 = 0.f, o12 = 0.f;
    float o20 = 0.f, o21 = 0.f, o22 = 0.f, o23 = 0.f, o24 = 0.f;
#pragma unroll 4
    for (int c = 0; c < 32; c++) {
        const float* ac = &sag[warp][c * 12];
        float4 A0 = *(const float4*)ac;
        float4 A1 = *(const float4*)(ac + 4);
        float A8 = ac[8];
        float fc = __shfl_sync(FULLMASK, f, c);
        o0 += A0.x * s0[c * 32 + lane] + fc * sk[c * 32 + lane];
        float w1 = s1[c * 32 + lane];
        o10 += A0.y * w1; o11 += A0.z * w1; o12 += A0.w * w1;
        float w2 = s2[c * 32 + lane];
        o20 += A1.x * w2; o21 += A1.y * w2; o22 += A1.z * w2;
        o23 += A1.w * w2; o24 += A8 * w2;
    }
    g_f0[(size_t)n * 32 + lane] = o0;
    float* f1w = &g_f1[(size_t)n * 96];
    f1w[0 * 32 + lane] = o10; f1w[1 * 32 + lane] = o11; f1w[2 * 32 + lane] = o12;
    float* f2w = &g_f2[(size_t)n * 160];
    f2w[0 * 32 + lane] = o20; f2w[1 * 32 + lane] = o21; f2w[2 * 32 + lane] = o22;
    f2w[3 * 32 + lane] = o23; f2w[4 * 32 + lane] = o24;
    float q = 0.f;
#pragma unroll
    for (int c = 0; c < 32; c++) {
        float fc = __shfl_sync(FULLMASK, o0, c);
        q = fmaf(fc, sWq[c * 32 + lane], q);
    }
#pragma unroll
    for (int h = 0; h < 4; h++) {
        float kt = 0.f;
#pragma unroll
        for (int d = 0; d < 8; d++) {
            float qd = __shfl_sync(FULLMASK, q, h * 8 + d);
            kt = fmaf(qd, sWkT[(h * 8 + d) * 32 + lane], kt);
        }
        g_kt[(size_t)n * 128 + kt_perm(h, lane)] = kt * LOGIT_SCALE;
    }
}

// ---------------- 8) fused layer-1 aggregation (online softmax) + f0 update + output ----------------
__global__ __launch_bounds__(256) void agg_update_out_kernel(
    const float* __restrict__ Ws0, const float* __restrict__ Wsk,
    const float* __restrict__ Wout, const float* __restrict__ Wc,
    float* __restrict__ out) {
    __shared__ __align__(16) float s0[1024], sk[1024], sWo[1024];
    __shared__ float sWc[480];
    int tid = threadIdx.x;
    for (int i = tid; i < 1024; i += 256) {
        s0[i] = Ws0[i]; sk[i] = Wsk[i]; sWo[i] = Wout[i];
    }
    for (int i = tid; i < 480; i += 256) sWc[i] = Wc[i];
    __syncthreads();
    int warp = tid >> 5, lane = tid & 31;
    int n = blockIdx.x * 8 + warp;
    if (n >= Nn) return;
    int beg = g_off[n], end = g_off[n + 1];
    int grp = lane >> 3;

    float mx = -3.0e38f;
    float den = 0.f, a0 = 0.f;
    for (int i = beg; i < end; i++) {
        int eid = g_eid[i];
        float lg = g_logit[(size_t)eid * 4 + grp];
        if (lg > mx) {
            float corr = __expf(mx - lg);
            den *= corr; a0 *= corr;
            mx = lg;
        }
        float ee = __expf(lg - mx);
        den += ee;
        a0 = fmaf(ee, g_m0[(size_t)eid * 32 + lane], a0);
    }
    float a = a0 / (den + 1e-8f);   // agg0[n][lane], stays in registers

    float f = g_f0[(size_t)n * 32 + lane];
    float o0 = 0.f;
#pragma unroll
    for (int c = 0; c < 32; c++) {
        float fc = __shfl_sync(FULLMASK, f, c);
        float ac = __shfl_sync(FULLMASK, a, c);
        o0 += ac * s0[c * 32 + lane] + fc * sk[c * 32 + lane];
    }
    float hs = 0.f;
#pragma unroll
    for (int c = 0; c < 32; c++) {
        float oc = __shfl_sync(FULLMASK, o0, c);
        hs = fmaf(oc, sWo[c * 32 + lane], hs);
    }
    out[(size_t)n * 32 + lane] = hs;
    float cacc = 0.f;
#pragma unroll
    for (int j = 0; j < 32; j++) {
        float hj = __shfl_sync(FULLMASK, hs, j);
        if (lane < 15) cacc = fmaf(hj, sWc[j * 15 + lane], cacc);
    }
    if (lane < 15) out[(size_t)Nn * 32 + (size_t)n * 15 + lane] = cacc;
}

// ---------------- launch ----------------
extern "C" void kernel_launch(void* const* d_in, const int* in_sizes, int n_in,
                              void* d_out, int out_size) {
    const float* pos       = (const float*)d_in[0];
    const float* node_l0   = (const float*)d_in[1];
    const float* edge_feat = (const float*)d_in[2];
    const int*   esrc      = (const int*)d_in[3];
    const int*   edst      = (const int*)d_in[4];
    const float* Wr1       = (const float*)d_in[5];
    const float* br1       = (const float*)d_in[6];
    const float* Wr2       = (const float*)d_in[7];
    const float* Wq        = (const float*)d_in[8];
    const float* Wk        = (const float*)d_in[9];
    const float* Ws0       = (const float*)d_in[10];
    const float* Ws1       = (const float*)d_in[11];
    const float* Ws2       = (const float*)d_in[12];
    const float* Wsk       = (const float*)d_in[13];
    const float* Wout      = (const float*)d_in[14];
    const float* Wc        = (const float*)d_in[15];
    float* out = (float*)d_out;

    const int NODE_BLKS = (Nn + 7) / 8;
    const int EDGE_BLKS = Ee / 64;   // warp per 8 edges, 8 warps / block

    init_kt_kernel<<<NODE_BLKS, 256>>>(node_l0, Wq, Wk);                           // 1
    geom_hist_kernel<<<(Ee + 255) / 256, 256>>>(pos, esrc, edst);                  // 2
    scan_kernel<<<1, 1024>>>();                                                    // 3
    edge_kernel<true><<<EDGE_BLKS, 256>>>(edge_feat, esrc, edst, Wr1, br1, Wr2);   // 4 (profiled; fused scatter)
    agg_l0_kernel<<<NODE_BLKS, 256>>>();                                           // 5
    update_l0_kt_kernel<<<NODE_BLKS, 256>>>(Ws0, Ws1, Ws2, Wsk,
                                            Wq + 1024, Wk + 1024);                 // 6
    edge_kernel<false><<<EDGE_BLKS, 256>>>(edge_feat, esrc, edst, Wr1 + 1056,
                                           br1 + 32, Wr2 + 7168);                  // 7
    agg_update_out_kernel<<<NODE_BLKS, 256>>>(Ws0 + 1024, Wsk + 1024, Wout, Wc, out); // 8
}

// round 11
// speedup vs baseline: 1.0492x; 1.0017x over previous
#include <cuda_runtime.h>

#define Nn 30000
#define Ee 480000
#define FULLMASK 0xffffffffu
#define NODE_BLKS_C 3750      // (Nn+7)/8
#define GEOM_BLKS_C 1875      // Ee/256

typedef unsigned long long ull;

// packed fp32x2 helpers (Blackwell FFMA2 path — PTX only)
#define PACK2(d, lo, hi) asm("mov.b64 %0, {%1, %2};" : "=l"(d) : "f"(lo), "f"(hi))
#define UNPACK2(lo, hi, s) asm("mov.b64 {%0, %1}, %2;" : "=f"(lo), "=f"(hi) : "l"(s))
#define FMA2(acc, a, b) asm("fma.rn.f32x2 %0, %1, %2, %0;" : "+l"(acc) : "l"(a), "l"(b))

// ---------------- scratch (static device allocations; no cudaMalloc) ----------------
__device__ __align__(16) float g_geom[Ee * 4];   // r, ux, uy, uz
__device__ __align__(16) float g_m0[Ee * 32];
__device__ __align__(16) float g_w[Ee * 64];     // layer0: [E][32] float2 (w3*f0s, w5*f0s)
__device__ __align__(16) float g_logit[Ee * 4];
__device__ __align__(16) float g_kt[Nn * 128];   // permuted + pre-scaled by 1/sqrt(8)
__device__ float g_f0[Nn * 32];
__device__ float g_f1[Nn * 96];    // planar [n][3][32]
__device__ float g_f2[Nn * 160];   // planar [n][5][32]
__device__ float g_agg[Nn * 288];  // planar [n][9][32]
__device__ int g_deg[Nn];          // zero-init at load; re-zeroed by last kernel each call
__device__ int g_off[Nn + 1];
__device__ int g_cur[Nn];
__device__ int g_eid[Ee];

// kt permutation: value for (head h, channel c) stored at (c>>3)*32 + h*8 + (c&7)
__device__ __forceinline__ int kt_perm(int h, int c) {
    return ((c >> 3) << 5) + (h << 3) + (c & 7);
}

#define LOGIT_SCALE 0.35355339059327373f   // 1/sqrt(8), folded into kt

// ---------------- 1) fused init: node blocks do f0-copy + kt(L0); edge blocks do geom+hist ----------------
__global__ __launch_bounds__(256) void init_geom_kernel(
    const float* __restrict__ node_l0, const float* __restrict__ Wq,
    const float* __restrict__ Wk, const float* __restrict__ pos,
    const int* __restrict__ esrc, const int* __restrict__ edst) {
    __shared__ float sWq[1024];    // [c][j]
    __shared__ float sWkT[1024];   // [j][c]
    int tid = threadIdx.x;
    if (blockIdx.x < NODE_BLKS_C) {
        // -------- node part (identical math to old init_kt; deg-zero moved out) --------
        for (int i = tid; i < 1024; i += 256) {
            sWq[i] = Wq[i];
            int c = i >> 5, j = i & 31;
            sWkT[j * 32 + c] = Wk[i];
        }
        __syncthreads();
        int warp = tid >> 5, lane = tid & 31;
        int n = blockIdx.x * 8 + warp;
        if (n >= Nn) return;
        float f = node_l0[(size_t)n * 32 + lane];
        g_f0[(size_t)n * 32 + lane] = f;
        float q = 0.f;
#pragma unroll
        for (int c = 0; c < 32; c++) {
            float fc = __shfl_sync(FULLMASK, f, c);
            q = fmaf(fc, sWq[c * 32 + lane], q);
        }
#pragma unroll
        for (int h = 0; h < 4; h++) {
            float kt = 0.f;
#pragma unroll
            for (int d = 0; d < 8; d++) {
                float qd = __shfl_sync(FULLMASK, q, h * 8 + d);
                kt = fmaf(qd, sWkT[(h * 8 + d) * 32 + lane], kt);
            }
            g_kt[(size_t)n * 128 + kt_perm(h, lane)] = kt * LOGIT_SCALE;
        }
    } else {
        // -------- edge part: geometry + degree histogram (g_deg pre-zeroed) --------
        int e = (blockIdx.x - NODE_BLKS_C) * 256 + tid;
        if (e >= Ee) return;
        int s = esrc[e], d = edst[e];
        float rx = pos[d * 3 + 0] - pos[s * 3 + 0];
        float ry = pos[d * 3 + 1] - pos[s * 3 + 1];
        float rz = pos[d * 3 + 2] - pos[s * 3 + 2];
        float r = sqrtf(rx * rx + ry * ry + rz * rz + 1e-8f);
        float inv = 1.0f / r;
        ((float4*)g_geom)[e] = make_float4(r, rx * inv, ry * inv, rz * inv);
        atomicAdd(&g_deg[d], 1);
    }
}

// ---------------- 2) exclusive scan (writes g_off and g_cur) ----------------
__global__ void scan_kernel() {
    __shared__ int sp[1024];
    const int CH = 30;
    int t = threadIdx.x;
    int loc[CH];
    int base = t * CH;
    int s = 0;
#pragma unroll
    for (int i = 0; i < CH; i++) {
        int idx = base + i;
        int v = (idx < Nn) ? g_deg[idx] : 0;
        loc[i] = v;
        s += v;
    }
    sp[t] = s;
    __syncthreads();
    for (int off = 1; off < 1024; off <<= 1) {
        int v = (t >= off) ? sp[t - off] : 0;
        __syncthreads();
        sp[t] += v;
        __syncthreads();
    }
    int run = (t == 0) ? 0 : sp[t - 1];
#pragma unroll
    for (int i = 0; i < CH; i++) {
        int idx = base + i;
        if (idx < Nn) { g_off[idx] = run; g_cur[idx] = run; run += loc[i]; }
    }
    if (t == 1023) g_off[Nn] = sp[1023];
}

// ---------------- 3/5) edge kernel: warp per 8 edges ----------------
// FIRST (layer0): planes = (w0, w3, w5); stores m0 + (w3*f0s, w5*f0s); fused CSR scatter.
// !FIRST (layer1): planes = (w0, w1, w2); stores m0 only (agg1/agg2 dead).
template <bool FIRST>
__global__ __launch_bounds__(256) void edge_kernel(
    const float* __restrict__ edge_feat, const int* __restrict__ esrc,
    const int* __restrict__ edst, const float* __restrict__ Wr1,
    const float* __restrict__ br1, const float* __restrict__ Wr2) {
    __shared__ __align__(16) float sWr1[33 * 32];
    __shared__ float sbr1[32];
    __shared__ float sWp0[1024];   // [j][c] plane 0 (w0)
    __shared__ float sWp1[1024];   // plane 1 (w3 | w1)
    __shared__ float sWp2[1024];   // plane 2 (w5 | w2)
    __shared__ __align__(16) float sstage[8][256];  // [warp][i*8+k]
    int tid = threadIdx.x;
    for (int i = tid; i < 33 * 32; i += 256) sWr1[i] = Wr1[i];
    if (tid < 32) sbr1[tid] = br1[tid];
    const int off1 = FIRST ? 96 : 32, off2 = FIRST ? 160 : 64;
    for (int i = tid; i < 1024; i += 256) {
        int j = i >> 5, c = i & 31;
        const float* row = Wr2 + j * 224;
        sWp0[i] = row[c];
        sWp1[i] = row[off1 + c];
        sWp2[i] = row[off2 + c];
    }
    __syncthreads();
    int lane = tid & 31, warp = tid >> 5;
    int e0 = blockIdx.x * 64 + warp * 8;   // Ee % 64 == 0
    float* sst = sstage[warp];

    float t0, t1, t2, t3, t4, t5, t6, t7;
    t0 = edge_feat[(size_t)(e0 + 0) * 32 + lane];
    t1 = edge_feat[(size_t)(e0 + 1) * 32 + lane];
    t2 = edge_feat[(size_t)(e0 + 2) * 32 + lane];
    t3 = edge_feat[(size_t)(e0 + 3) * 32 + lane];
    t4 = edge_feat[(size_t)(e0 + 4) * 32 + lane];
    t5 = edge_feat[(size_t)(e0 + 5) * 32 + lane];
    t6 = edge_feat[(size_t)(e0 + 6) * 32 + lane];
    t7 = edge_feat[(size_t)(e0 + 7) * 32 + lane];
    {
        float4* sp = (float4*)(sst + lane * 8);
        sp[0] = make_float4(t0, t1, t2, t3);
        sp[1] = make_float4(t4, t5, t6, t7);
    }
    __syncwarp();

    float bia = sbr1[lane], w0l = sWr1[lane];
    t0 = fmaf(g_geom[(size_t)(e0 + 0) * 4], w0l, bia);
    t1 = fmaf(g_geom[(size_t)(e0 + 1) * 4], w0l, bia);
    t2 = fmaf(g_geom[(size_t)(e0 + 2) * 4], w0l, bia);
    t3 = fmaf(g_geom[(size_t)(e0 + 3) * 4], w0l, bia);
    t4 = fmaf(g_geom[(size_t)(e0 + 4) * 4], w0l, bia);
    t5 = fmaf(g_geom[(size_t)(e0 + 5) * 4], w0l, bia);
    t6 = fmaf(g_geom[(size_t)(e0 + 6) * 4], w0l, bia);
    t7 = fmaf(g_geom[(size_t)(e0 + 7) * 4], w0l, bia);
    ull h01, h23, h45, h67;
    PACK2(h01, t0, t1); PACK2(h23, t2, t3); PACK2(h45, t4, t5); PACK2(h67, t6, t7);
#pragma unroll
    for (int i = 0; i < 32; i++) {
        const ulonglong2* xp = (const ulonglong2*)(sst + i * 8);
        ulonglong2 xa = xp[0], xb = xp[1];   // LDS.128 x2 (broadcast)
        float wc = sWr1[(i + 1) * 32 + lane];
        ull wd; PACK2(wd, wc, wc);
        FMA2(h01, xa.x, wd); FMA2(h23, xa.y, wd); FMA2(h45, xb.x, wd); FMA2(h67, xb.y, wd);
    }
    UNPACK2(t0, t1, h01); UNPACK2(t2, t3, h23); UNPACK2(t4, t5, h45); UNPACK2(t6, t7, h67);
    t0 = fmaxf(t0, 0.f); t1 = fmaxf(t1, 0.f); t2 = fmaxf(t2, 0.f); t3 = fmaxf(t3, 0.f);
    t4 = fmaxf(t4, 0.f); t5 = fmaxf(t5, 0.f); t6 = fmaxf(t6, 0.f); t7 = fmaxf(t7, 0.f);
    __syncwarp();
    {
        float4* sp = (float4*)(sst + lane * 8);
        sp[0] = make_float4(t0, t1, t2, t3);
        sp[1] = make_float4(t4, t5, t6, t7);
    }
    __syncwarp();

    ull a0[4] = {0, 0, 0, 0}, a1[4] = {0, 0, 0, 0}, a2[4] = {0, 0, 0, 0};
#pragma unroll
    for (int j = 0; j < 32; j++) {
        const ulonglong2* hp = (const ulonglong2*)(sst + j * 8);
        ulonglong2 ha = hp[0], hb = hp[1];   // LDS.128 x2 (broadcast)
        float w0c = sWp0[j * 32 + lane];     // 3 scalar LDS.32 (1 wf each)
        float w1c = sWp1[j * 32 + lane];
        float w2c = sWp2[j * 32 + lane];
        ull p0, p1, p2;
        PACK2(p0, w0c, w0c); PACK2(p1, w1c, w1c); PACK2(p2, w2c, w2c);
        FMA2(a0[0], ha.x, p0); FMA2(a0[1], ha.y, p0); FMA2(a0[2], hb.x, p0); FMA2(a0[3], hb.y, p0);
        FMA2(a1[0], ha.x, p1); FMA2(a1[1], ha.y, p1); FMA2(a1[2], hb.x, p1); FMA2(a1[3], hb.y, p1);
        FMA2(a2[0], ha.x, p2); FMA2(a2[1], ha.y, p2); FMA2(a2[2], hb.x, p2); FMA2(a2[3], hb.y, p2);
    }

    int sub = lane & 7;
#pragma unroll
    for (int q2 = 0; q2 < 4; q2++) {
        float W0a, W0b, W1a, W1b, W2a, W2b;
        UNPACK2(W0a, W0b, a0[q2]);
        UNPACK2(W1a, W1b, a1[q2]);
        UNPACK2(W2a, W2b, a2[q2]);
#pragma unroll
        for (int kk = 0; kk < 2; kk++) {
            int e = e0 + q2 * 2 + kk;
            float W0 = kk ? W0b : W0a, W1 = kk ? W1b : W1a, W2 = kk ? W2b : W2a;
            int src = esrc[e], dst = edst[e];
            float f0s = g_f0[(size_t)src * 32 + lane];
            float m0;
            if (FIRST) {
                m0 = W0 * f0s;
                ((float2*)g_w)[(size_t)e * 32 + lane] = make_float2(W1 * f0s, W2 * f0s);
            } else {
                float4 gm = ((const float4*)g_geom)[e];
                float ux = gm.y, uy = gm.z, uz = gm.w;
                const float* f1p = &g_f1[(size_t)src * 96];
                const float* f2p = &g_f2[(size_t)src * 160];
                float d1 = f1p[lane] * ux + f1p[32 + lane] * uy + f1p[64 + lane] * uz;
                float s0 = ux * uy, s1 = uy * uz, s2 = 3.f * uz * uz - 1.f;
                float s3 = ux * uz, s4 = ux * ux - uy * uy;
                float d2 = f2p[lane] * s0 + f2p[32 + lane] * s1 + f2p[64 + lane] * s2 +
                           f2p[96 + lane] * s3 + f2p[128 + lane] * s4;
                m0 = fmaf(W1, d1, fmaf(W2, d2, W0 * f0s));
            }
            g_m0[(size_t)e * 32 + lane] = m0;
            const float* ktp = &g_kt[(size_t)dst * 128];
            float v = 0.f;
#pragma unroll
            for (int k2 = 0; k2 < 4; k2++) {
                float mc = __shfl_sync(FULLMASK, m0, sub + 8 * k2);
                v = fmaf(mc, ktp[k2 * 32 + lane], v);
            }
            v += __shfl_xor_sync(FULLMASK, v, 1);
            v += __shfl_xor_sync(FULLMASK, v, 2);
            v += __shfl_xor_sync(FULLMASK, v, 4);
            if (sub == 0)
                g_logit[(size_t)e * 4 + (lane >> 3)] = v;   // kt pre-scaled by 1/sqrt(8)
            if (FIRST && lane == 0) {   // fused CSR scatter (order within segment irrelevant)
                int p = atomicAdd(&g_cur[dst], 1);
                g_eid[p] = e;
            }
        }
    }
}

// ---------------- 4) layer-0 aggregation: ONLINE softmax, single pass (profiled slot) ----------------
__global__ __launch_bounds__(256) void agg_l0_kernel() {
    int tid = threadIdx.x;
    int lane = tid & 31;
    int n = blockIdx.x * 8 + (tid >> 5);
    if (n >= Nn) return;
    int beg = g_off[n], end = g_off[n + 1];
    int grp = lane >> 3;

    float mx = -3.0e38f;
    float den = 0.f;
    float a0 = 0.f, a10 = 0.f, a11 = 0.f, a12 = 0.f;
    float a20 = 0.f, a21 = 0.f, a22 = 0.f, a23 = 0.f, a24 = 0.f;
    for (int i = beg; i < end; i++) {
        int eid = g_eid[i];
        float lg = g_logit[(size_t)eid * 4 + grp];
        if (lg > mx) {   // expected ~ln(deg) times; rescale accumulators
            float corr = __expf(mx - lg);   // first hit: exp(-3e38 - lg) -> 0 (accums are 0)
            den *= corr; a0 *= corr;
            a10 *= corr; a11 *= corr; a12 *= corr;
            a20 *= corr; a21 *= corr; a22 *= corr; a23 *= corr; a24 *= corr;
            mx = lg;
        }
        float ee = __expf(lg - mx);
        den += ee;
        float m0 = g_m0[(size_t)eid * 32 + lane];
        float4 gm = ((const float4*)g_geom)[eid];
        float ux = gm.y, uy = gm.z, uz = gm.w;
        a0 = fmaf(ee, m0, a0);
        float y0 = ux * uy, y1 = uy * uz, y2 = 3.f * uz * uz - 1.f;
        float y3 = ux * uz, y4 = ux * ux - uy * uy;
        float2 w = ((const float2*)g_w)[(size_t)eid * 32 + lane];
        float wf3 = w.x * ee, wf5 = w.y * ee;
        a10 = fmaf(wf3, ux, a10); a11 = fmaf(wf3, uy, a11); a12 = fmaf(wf3, uz, a12);
        a20 = fmaf(wf5, y0, a20); a21 = fmaf(wf5, y1, a21); a22 = fmaf(wf5, y2, a22);
        a23 = fmaf(wf5, y3, a23); a24 = fmaf(wf5, y4, a24);
    }
    float dinv = 1.f / (den + 1e-8f);
    float* ag = &g_agg[(size_t)n * 288];   // planar [9][32]
    ag[0 * 32 + lane] = a0 * dinv;
    ag[1 * 32 + lane] = a10 * dinv; ag[2 * 32 + lane] = a11 * dinv; ag[3 * 32 + lane] = a12 * dinv;
    ag[4 * 32 + lane] = a20 * dinv; ag[5 * 32 + lane] = a21 * dinv; ag[6 * 32 + lane] = a22 * dinv;
    ag[7 * 32 + lane] = a23 * dinv; ag[8 * 32 + lane] = a24 * dinv;
}

// ---------------- 5) layer-0 update (writes f0,f1,f2 planar) + kt for layer 1 ----------------
__global__ __launch_bounds__(256) void update_l0_kt_kernel(
    const float* __restrict__ Ws0, const float* __restrict__ Ws1,
    const float* __restrict__ Ws2, const float* __restrict__ Wsk,
    const float* __restrict__ Wq, const float* __restrict__ Wk) {
    __shared__ __align__(16) float s0[1024], s1[1024], s2[1024], sk[1024];
    __shared__ float sWq[1024], sWkT[1024];
    __shared__ __align__(16) float sag[8][384];   // [c][12] padded
    int tid = threadIdx.x;
    for (int i = tid; i < 1024; i += 256) {
        s0[i] = Ws0[i]; s1[i] = Ws1[i]; s2[i] = Ws2[i]; sk[i] = Wsk[i];
        sWq[i] = Wq[i];
        int c = i >> 5, j = i & 31;
        sWkT[j * 32 + c] = Wk[i];
    }
    __syncthreads();
    int warp = tid >> 5, lane = tid & 31;
    int n = blockIdx.x * 8 + warp;
    if (n >= Nn) return;
    float f = g_f0[(size_t)n * 32 + lane];
    {
        const float* ag = &g_agg[(size_t)n * 288];
#pragma unroll
        for (int s = 0; s < 9; s++)
            sag[warp][lane * 12 + s] = ag[s * 32 + lane];
    }
    __syncwarp();
    float o0 = 0.f, o10 = 0.f, o11 = 0.f, o12 = 0.f;
    float o20 = 0.f, o21 = 0.f, o22 = 0.f, o23 = 0.f, o24 = 0.f;
#pragma unroll 4
    for (int c = 0; c < 32; c++) {
        const float* ac = &sag[warp][c * 12];
        float4 A0 = *(const float4*)ac;
        float4 A1 = *(const float4*)(ac + 4);
        float A8 = ac[8];
        float fc = __shfl_sync(FULLMASK, f, c);
        o0 += A0.x * s0[c * 32 + lane] + fc * sk[c * 32 + lane];
        float w1 = s1[c * 32 + lane];
        o10 += A0.y * w1; o11 += A0.z * w1; o12 += A0.w * w1;
        float w2 = s2[c * 32 + lane];
        o20 += A1.x * w2; o21 += A1.y * w2; o22 += A1.z * w2;
        o23 += A1.w * w2; o24 += A8 * w2;
    }
    g_f0[(size_t)n * 32 + lane] = o0;
    float* f1w = &g_f1[(size_t)n * 96];
    f1w[0 * 32 + lane] = o10; f1w[1 * 32 + lane] = o11; f1w[2 * 32 + lane] = o12;
    float* f2w = &g_f2[(size_t)n * 160];
    f2w[0 * 32 + lane] = o20; f2w[1 * 32 + lane] = o21; f2w[2 * 32 + lane] = o22;
    f2w[3 * 32 + lane] = o23; f2w[4 * 32 + lane] = o24;
    float q = 0.f;
#pragma unroll
    for (int c = 0; c < 32; c++) {
        float fc = __shfl_sync(FULLMASK, o0, c);
        q = fmaf(fc, sWq[c * 32 + lane], q);
    }
#pragma unroll
    for (int h = 0; h < 4; h++) {
        float kt = 0.f;
#pragma unroll
        for (int d = 0; d < 8; d++) {
            float qd = __shfl_sync(FULLMASK, q, h * 8 + d);
            kt = fmaf(qd, sWkT[(h * 8 + d) * 32 + lane], kt);
        }
        g_kt[(size_t)n * 128 + kt_perm(h, lane)] = kt * LOGIT_SCALE;
    }
}

// ---------------- 7) fused layer-1 aggregation (online softmax) + f0 update + output + deg re-zero ----------------
__global__ __launch_bounds__(256) void agg_update_out_kernel(
    const float* __restrict__ Ws0, const float* __restrict__ Wsk,
    const float* __restrict__ Wout, const float* __restrict__ Wc,
    float* __restrict__ out) {
    __shared__ __align__(16) float s0[1024], sk[1024], sWo[1024];
    __shared__ float sWc[480];
    int tid = threadIdx.x;
    for (int i = tid; i < 1024; i += 256) {
        s0[i] = Ws0[i]; sk[i] = Wsk[i]; sWo[i] = Wout[i];
    }
    for (int i = tid; i < 480; i += 256) sWc[i] = Wc[i];
    __syncthreads();
    int warp = tid >> 5, lane = tid & 31;
    int n = blockIdx.x * 8 + warp;
    if (n >= Nn) return;
    if (lane == 0) g_deg[n] = 0;   // leave deg zeroed for the next invocation
    int beg = g_off[n], end = g_off[n + 1];
    int grp = lane >> 3;

    float mx = -3.0e38f;
    float den = 0.f, a0 = 0.f;
    for (int i = beg; i < end; i++) {
        int eid = g_eid[i];
        float lg = g_logit[(size_t)eid * 4 + grp];
        if (lg > mx) {
            float corr = __expf(mx - lg);
            den *= corr; a0 *= corr;
            mx = lg;
        }
        float ee = __expf(lg - mx);
        den += ee;
        a0 = fmaf(ee, g_m0[(size_t)eid * 32 + lane], a0);
    }
    float a = a0 / (den + 1e-8f);   // agg0[n][lane], stays in registers

    float f = g_f0[(size_t)n * 32 + lane];
    float o0 = 0.f;
#pragma unroll
    for (int c = 0; c < 32; c++) {
        float fc = __shfl_sync(FULLMASK, f, c);
        float ac = __shfl_sync(FULLMASK, a, c);
        o0 += ac * s0[c * 32 + lane] + fc * sk[c * 32 + lane];
    }
    float hs = 0.f;
#pragma unroll
    for (int c = 0; c < 32; c++) {
        float oc = __shfl_sync(FULLMASK, o0, c);
        hs = fmaf(oc, sWo[c * 32 + lane], hs);
    }
    out[(size_t)n * 32 + lane] = hs;
    float cacc = 0.f;
#pragma unroll
    for (int j = 0; j < 32; j++) {
        float hj = __shfl_sync(FULLMASK, hs, j);
        if (lane < 15) cacc = fmaf(hj, sWc[j * 15 + lane], cacc);
    }
    if (lane < 15) out[(size_t)Nn * 32 + (size_t)n * 15 + lane] = cacc;
}

// ---------------- launch ----------------
extern "C" void kernel_launch(void* const* d_in, const int* in_sizes, int n_in,
                              void* d_out, int out_size) {
    const float* pos       = (const float*)d_in[0];
    const float* node_l0   = (const float*)d_in[1];
    const float* edge_feat = (const float*)d_in[2];
    const int*   esrc      = (const int*)d_in[3];
    const int*   edst      = (const int*)d_in[4];
    const float* Wr1       = (const float*)d_in[5];
    const float* br1       = (const float*)d_in[6];
    const float* Wr2       = (const float*)d_in[7];
    const float* Wq        = (const float*)d_in[8];
    const float* Wk        = (const float*)d_in[9];
    const float* Ws0       = (const float*)d_in[10];
    const float* Ws1       = (const float*)d_in[11];
    const float* Ws2       = (const float*)d_in[12];
    const float* Wsk       = (const float*)d_in[13];
    const float* Wout      = (const float*)d_in[14];
    const float* Wc        = (const float*)d_in[15];
    float* out = (float*)d_out;

    const int NODE_BLKS = NODE_BLKS_C;
    const int EDGE_BLKS = Ee / 64;   // warp per 8 edges, 8 warps / block

    init_geom_kernel<<<NODE_BLKS_C + GEOM_BLKS_C, 256>>>(node_l0, Wq, Wk,
                                                         pos, esrc, edst);         // 1
    scan_kernel<<<1, 1024>>>();                                                    // 2
    edge_kernel<true><<<EDGE_BLKS, 256>>>(edge_feat, esrc, edst, Wr1, br1, Wr2);   // 3
    agg_l0_kernel<<<NODE_BLKS, 256>>>();                                           // 4 (profiled slot)
    update_l0_kt_kernel<<<NODE_BLKS, 256>>>(Ws0, Ws1, Ws2, Wsk,
                                            Wq + 1024, Wk + 1024);                 // 5
    edge_kernel<false><<<EDGE_BLKS, 256>>>(edge_feat, esrc, edst, Wr1 + 1056,
                                           br1 + 32, Wr2 + 7168);                  // 6
    agg_update_out_kernel<<<NODE_BLKS, 256>>>(Ws0 + 1024, Wsk + 1024, Wout, Wc, out); // 7
}

// round 12
// speedup vs baseline: 1.0673x; 1.0173x over previous
#include <cuda_runtime.h>

#define Nn 30000
#define Ee 480000
#define FULLMASK 0xffffffffu
#define NODE_BLKS_C 3750      // (Nn+7)/8
#define GEOM_BLKS_C 1875      // Ee/256

typedef unsigned long long ull;

// packed fp32x2 helpers (Blackwell FFMA2 path — PTX only)
#define PACK2(d, lo, hi) asm("mov.b64 %0, {%1, %2};" : "=l"(d) : "f"(lo), "f"(hi))
#define UNPACK2(lo, hi, s) asm("mov.b64 {%0, %1}, %2;" : "=f"(lo), "=f"(hi) : "l"(s))
#define FMA2(acc, a, b) asm("fma.rn.f32x2 %0, %1, %2, %0;" : "+l"(acc) : "l"(a), "l"(b))

// ---------------- scratch (static device allocations; no cudaMalloc) ----------------
__device__ __align__(16) float g_geom[Ee * 4];    // edge-order: r, ux, uy, uz
__device__ __align__(16) float g_geomp[Ee * 4];   // CSR-order copy (agg_l0 stream)
__device__ __align__(16) float g_m0[Ee * 32];     // CSR-order
__device__ __align__(16) float g_w[Ee * 64];      // CSR-order, layer0: [p][32] float2 (w3*f0s, w5*f0s)
__device__ __align__(16) float g_logit[Ee * 4];   // CSR-order
__device__ __align__(16) float g_kt[Nn * 128];    // permuted + pre-scaled by 1/sqrt(8)
__device__ float g_f0[Nn * 32];
__device__ float g_f1[Nn * 96];    // planar [n][3][32]
__device__ float g_f2[Nn * 160];   // planar [n][5][32]
__device__ float g_agg[Nn * 288];  // planar [n][9][32]
__device__ int g_deg[Nn];          // zero-init at load; re-zeroed by last kernel each call
__device__ int g_off[Nn + 1];
__device__ int g_cur[Nn];
__device__ int g_pos[Ee];          // edge -> CSR slot (set by edge_l0, used by edge_l1)

// kt permutation: value for (head h, channel c) stored at (c>>3)*32 + h*8 + (c&7)
__device__ __forceinline__ int kt_perm(int h, int c) {
    return ((c >> 3) << 5) + (h << 3) + (c & 7);
}

#define LOGIT_SCALE 0.35355339059327373f   // 1/sqrt(8), folded into kt

// ---------------- 1) fused init: node blocks do f0-copy + kt(L0); edge blocks do geom+hist ----------------
__global__ __launch_bounds__(256) void init_geom_kernel(
    const float* __restrict__ node_l0, const float* __restrict__ Wq,
    const float* __restrict__ Wk, const float* __restrict__ pos,
    const int* __restrict__ esrc, const int* __restrict__ edst) {
    __shared__ float sWq[1024];    // [c][j]
    __shared__ float sWkT[1024];   // [j][c]
    int tid = threadIdx.x;
    if (blockIdx.x < NODE_BLKS_C) {
        for (int i = tid; i < 1024; i += 256) {
            sWq[i] = Wq[i];
            int c = i >> 5, j = i & 31;
            sWkT[j * 32 + c] = Wk[i];
        }
        __syncthreads();
        int warp = tid >> 5, lane = tid & 31;
        int n = blockIdx.x * 8 + warp;
        if (n >= Nn) return;
        float f = node_l0[(size_t)n * 32 + lane];
        g_f0[(size_t)n * 32 + lane] = f;
        float q = 0.f;
#pragma unroll
        for (int c = 0; c < 32; c++) {
            float fc = __shfl_sync(FULLMASK, f, c);
            q = fmaf(fc, sWq[c * 32 + lane], q);
        }
#pragma unroll
        for (int h = 0; h < 4; h++) {
            float kt = 0.f;
#pragma unroll
            for (int d = 0; d < 8; d++) {
                float qd = __shfl_sync(FULLMASK, q, h * 8 + d);
                kt = fmaf(qd, sWkT[(h * 8 + d) * 32 + lane], kt);
            }
            g_kt[(size_t)n * 128 + kt_perm(h, lane)] = kt * LOGIT_SCALE;
        }
    } else {
        int e = (blockIdx.x - NODE_BLKS_C) * 256 + tid;
        if (e >= Ee) return;
        int s = esrc[e], d = edst[e];
        float rx = pos[d * 3 + 0] - pos[s * 3 + 0];
        float ry = pos[d * 3 + 1] - pos[s * 3 + 1];
        float rz = pos[d * 3 + 2] - pos[s * 3 + 2];
        float r = sqrtf(rx * rx + ry * ry + rz * rz + 1e-8f);
        float inv = 1.0f / r;
        ((float4*)g_geom)[e] = make_float4(r, rx * inv, ry * inv, rz * inv);
        atomicAdd(&g_deg[d], 1);
    }
}

// ---------------- 2) exclusive scan (writes g_off and g_cur) ----------------
__global__ void scan_kernel() {
    __shared__ int sp[1024];
    const int CH = 30;
    int t = threadIdx.x;
    int loc[CH];
    int base = t * CH;
    int s = 0;
#pragma unroll
    for (int i = 0; i < CH; i++) {
        int idx = base + i;
        int v = (idx < Nn) ? g_deg[idx] : 0;
        loc[i] = v;
        s += v;
    }
    sp[t] = s;
    __syncthreads();
    for (int off = 1; off < 1024; off <<= 1) {
        int v = (t >= off) ? sp[t - off] : 0;
        __syncthreads();
        sp[t] += v;
        __syncthreads();
    }
    int run = (t == 0) ? 0 : sp[t - 1];
#pragma unroll
    for (int i = 0; i < CH; i++) {
        int idx = base + i;
        if (idx < Nn) { g_off[idx] = run; g_cur[idx] = run; run += loc[i]; }
    }
    if (t == 1023) g_off[Nn] = sp[1023];
}

// ---------------- 3/5) edge kernel: warp per 8 edges; payloads stored in CSR order ----------------
// FIRST (layer0): planes = (w0, w3, w5); stores m0/w/logit/geomp at CSR slot p; records g_pos.
// !FIRST (layer1): planes = (w0, w1, w2); stores m0/logit at p = g_pos[e].
template <bool FIRST>
__global__ __launch_bounds__(256) void edge_kernel(
    const float* __restrict__ edge_feat, const int* __restrict__ esrc,
    const int* __restrict__ edst, const float* __restrict__ Wr1,
    const float* __restrict__ br1, const float* __restrict__ Wr2) {
    __shared__ __align__(16) float sWr1[33 * 32];
    __shared__ float sbr1[32];
    __shared__ float sWp0[1024];   // [j][c] plane 0 (w0)
    __shared__ float sWp1[1024];   // plane 1 (w3 | w1)
    __shared__ float sWp2[1024];   // plane 2 (w5 | w2)
    __shared__ __align__(16) float sstage[8][256];  // [warp][i*8+k]
    int tid = threadIdx.x;
    for (int i = tid; i < 33 * 32; i += 256) sWr1[i] = Wr1[i];
    if (tid < 32) sbr1[tid] = br1[tid];
    const int off1 = FIRST ? 96 : 32, off2 = FIRST ? 160 : 64;
    for (int i = tid; i < 1024; i += 256) {
        int j = i >> 5, c = i & 31;
        const float* row = Wr2 + j * 224;
        sWp0[i] = row[c];
        sWp1[i] = row[off1 + c];
        sWp2[i] = row[off2 + c];
    }
    __syncthreads();
    int lane = tid & 31, warp = tid >> 5;
    int e0 = blockIdx.x * 64 + warp * 8;   // Ee % 64 == 0
    float* sst = sstage[warp];

    float t0, t1, t2, t3, t4, t5, t6, t7;
    t0 = edge_feat[(size_t)(e0 + 0) * 32 + lane];
    t1 = edge_feat[(size_t)(e0 + 1) * 32 + lane];
    t2 = edge_feat[(size_t)(e0 + 2) * 32 + lane];
    t3 = edge_feat[(size_t)(e0 + 3) * 32 + lane];
    t4 = edge_feat[(size_t)(e0 + 4) * 32 + lane];
    t5 = edge_feat[(size_t)(e0 + 5) * 32 + lane];
    t6 = edge_feat[(size_t)(e0 + 6) * 32 + lane];
    t7 = edge_feat[(size_t)(e0 + 7) * 32 + lane];
    {
        float4* sp = (float4*)(sst + lane * 8);
        sp[0] = make_float4(t0, t1, t2, t3);
        sp[1] = make_float4(t4, t5, t6, t7);
    }
    __syncwarp();

    float bia = sbr1[lane], w0l = sWr1[lane];
    t0 = fmaf(g_geom[(size_t)(e0 + 0) * 4], w0l, bia);
    t1 = fmaf(g_geom[(size_t)(e0 + 1) * 4], w0l, bia);
    t2 = fmaf(g_geom[(size_t)(e0 + 2) * 4], w0l, bia);
    t3 = fmaf(g_geom[(size_t)(e0 + 3) * 4], w0l, bia);
    t4 = fmaf(g_geom[(size_t)(e0 + 4) * 4], w0l, bia);
    t5 = fmaf(g_geom[(size_t)(e0 + 5) * 4], w0l, bia);
    t6 = fmaf(g_geom[(size_t)(e0 + 6) * 4], w0l, bia);
    t7 = fmaf(g_geom[(size_t)(e0 + 7) * 4], w0l, bia);
    ull h01, h23, h45, h67;
    PACK2(h01, t0, t1); PACK2(h23, t2, t3); PACK2(h45, t4, t5); PACK2(h67, t6, t7);
#pragma unroll
    for (int i = 0; i < 32; i++) {
        const ulonglong2* xp = (const ulonglong2*)(sst + i * 8);
        ulonglong2 xa = xp[0], xb = xp[1];   // LDS.128 x2 (broadcast)
        float wc = sWr1[(i + 1) * 32 + lane];
        ull wd; PACK2(wd, wc, wc);
        FMA2(h01, xa.x, wd); FMA2(h23, xa.y, wd); FMA2(h45, xb.x, wd); FMA2(h67, xb.y, wd);
    }
    UNPACK2(t0, t1, h01); UNPACK2(t2, t3, h23); UNPACK2(t4, t5, h45); UNPACK2(t6, t7, h67);
    t0 = fmaxf(t0, 0.f); t1 = fmaxf(t1, 0.f); t2 = fmaxf(t2, 0.f); t3 = fmaxf(t3, 0.f);
    t4 = fmaxf(t4, 0.f); t5 = fmaxf(t5, 0.f); t6 = fmaxf(t6, 0.f); t7 = fmaxf(t7, 0.f);
    __syncwarp();
    {
        float4* sp = (float4*)(sst + lane * 8);
        sp[0] = make_float4(t0, t1, t2, t3);
        sp[1] = make_float4(t4, t5, t6, t7);
    }
    __syncwarp();

    ull a0[4] = {0, 0, 0, 0}, a1[4] = {0, 0, 0, 0}, a2[4] = {0, 0, 0, 0};
#pragma unroll
    for (int j = 0; j < 32; j++) {
        const ulonglong2* hp = (const ulonglong2*)(sst + j * 8);
        ulonglong2 ha = hp[0], hb = hp[1];   // LDS.128 x2 (broadcast)
        float w0c = sWp0[j * 32 + lane];     // 3 scalar LDS.32 (1 wf each)
        float w1c = sWp1[j * 32 + lane];
        float w2c = sWp2[j * 32 + lane];
        ull p0, p1, p2;
        PACK2(p0, w0c, w0c); PACK2(p1, w1c, w1c); PACK2(p2, w2c, w2c);
        FMA2(a0[0], ha.x, p0); FMA2(a0[1], ha.y, p0); FMA2(a0[2], hb.x, p0); FMA2(a0[3], hb.y, p0);
        FMA2(a1[0], ha.x, p1); FMA2(a1[1], ha.y, p1); FMA2(a1[2], hb.x, p1); FMA2(a1[3], hb.y, p1);
        FMA2(a2[0], ha.x, p2); FMA2(a2[1], ha.y, p2); FMA2(a2[2], hb.x, p2); FMA2(a2[3], hb.y, p2);
    }

    int sub = lane & 7;
#pragma unroll
    for (int q2 = 0; q2 < 4; q2++) {
        float W0a, W0b, W1a, W1b, W2a, W2b;
        UNPACK2(W0a, W0b, a0[q2]);
        UNPACK2(W1a, W1b, a1[q2]);
        UNPACK2(W2a, W2b, a2[q2]);
#pragma unroll
        for (int kk = 0; kk < 2; kk++) {
            int e = e0 + q2 * 2 + kk;
            float W0 = kk ? W0b : W0a, W1 = kk ? W1b : W1a, W2 = kk ? W2b : W2a;
            int src = esrc[e], dst = edst[e];
            float f0s = g_f0[(size_t)src * 32 + lane];
            float m0;
            float4 gm;
            int p;
            if (FIRST) {
                m0 = W0 * f0s;
                gm = ((const float4*)g_geom)[e];   // broadcast; copied to CSR order below
                if (lane == 0) p = atomicAdd(&g_cur[dst], 1);
                p = __shfl_sync(FULLMASK, p, 0);
                if (lane == 0) {
                    g_pos[e] = p;
                    ((float4*)g_geomp)[p] = gm;
                }
                ((float2*)g_w)[(size_t)p * 32 + lane] = make_float2(W1 * f0s, W2 * f0s);
            } else {
                gm = ((const float4*)g_geom)[e];
                float ux = gm.y, uy = gm.z, uz = gm.w;
                const float* f1p = &g_f1[(size_t)src * 96];
                const float* f2p = &g_f2[(size_t)src * 160];
                float d1 = f1p[lane] * ux + f1p[32 + lane] * uy + f1p[64 + lane] * uz;
                float s0 = ux * uy, s1 = uy * uz, s2 = 3.f * uz * uz - 1.f;
                float s3 = ux * uz, s4 = ux * ux - uy * uy;
                float d2 = f2p[lane] * s0 + f2p[32 + lane] * s1 + f2p[64 + lane] * s2 +
                           f2p[96 + lane] * s3 + f2p[128 + lane] * s4;
                m0 = fmaf(W1, d1, fmaf(W2, d2, W0 * f0s));
                p = g_pos[e];   // broadcast load
            }
            g_m0[(size_t)p * 32 + lane] = m0;
            const float* ktp = &g_kt[(size_t)dst * 128];
            float v = 0.f;
#pragma unroll
            for (int k2 = 0; k2 < 4; k2++) {
                float mc = __shfl_sync(FULLMASK, m0, sub + 8 * k2);
                v = fmaf(mc, ktp[k2 * 32 + lane], v);
            }
            v += __shfl_xor_sync(FULLMASK, v, 1);
            v += __shfl_xor_sync(FULLMASK, v, 2);
            v += __shfl_xor_sync(FULLMASK, v, 4);
            if (sub == 0)
                g_logit[(size_t)p * 4 + (lane >> 3)] = v;   // kt pre-scaled by 1/sqrt(8)
        }
    }
}

// ---------------- 4) layer-0 aggregation: online softmax, PURE sequential streams ----------------
__global__ __launch_bounds__(256) void agg_l0_kernel() {
    int tid = threadIdx.x;
    int lane = tid & 31;
    int n = blockIdx.x * 8 + (tid >> 5);
    if (n >= Nn) return;
    int beg = g_off[n], end = g_off[n + 1];
    int grp = lane >> 3;

    float mx = -3.0e38f;
    float den = 0.f;
    float a0 = 0.f, a10 = 0.f, a11 = 0.f, a12 = 0.f;
    float a20 = 0.f, a21 = 0.f, a22 = 0.f, a23 = 0.f, a24 = 0.f;
#pragma unroll 2
    for (int i = beg; i < end; i++) {
        float lg = g_logit[(size_t)i * 4 + grp];
        float m0 = g_m0[(size_t)i * 32 + lane];
        float4 gm = ((const float4*)g_geomp)[i];
        float2 w = ((const float2*)g_w)[(size_t)i * 32 + lane];
        if (lg > mx) {   // rescale accumulators (expected ~ln(deg) hits)
            float corr = __expf(mx - lg);   // first hit: -> 0 with zero accums
            den *= corr; a0 *= corr;
            a10 *= corr; a11 *= corr; a12 *= corr;
            a20 *= corr; a21 *= corr; a22 *= corr; a23 *= corr; a24 *= corr;
            mx = lg;
        }
        float ee = __expf(lg - mx);
        den += ee;
        float ux = gm.y, uy = gm.z, uz = gm.w;
        a0 = fmaf(ee, m0, a0);
        float y0 = ux * uy, y1 = uy * uz, y2 = 3.f * uz * uz - 1.f;
        float y3 = ux * uz, y4 = ux * ux - uy * uy;
        float wf3 = w.x * ee, wf5 = w.y * ee;
        a10 = fmaf(wf3, ux, a10); a11 = fmaf(wf3, uy, a11); a12 = fmaf(wf3, uz, a12);
        a20 = fmaf(wf5, y0, a20); a21 = fmaf(wf5, y1, a21); a22 = fmaf(wf5, y2, a22);
        a23 = fmaf(wf5, y3, a23); a24 = fmaf(wf5, y4, a24);
    }
    float dinv = 1.f / (den + 1e-8f);
    float* ag = &g_agg[(size_t)n * 288];   // planar [9][32]
    ag[0 * 32 + lane] = a0 * dinv;
    ag[1 * 32 + lane] = a10 * dinv; ag[2 * 32 + lane] = a11 * dinv; ag[3 * 32 + lane] = a12 * dinv;
    ag[4 * 32 + lane] = a20 * dinv; ag[5 * 32 + lane] = a21 * dinv; ag[6 * 32 + lane] = a22 * dinv;
    ag[7 * 32 + lane] = a23 * dinv; ag[8 * 32 + lane] = a24 * dinv;
}

// ---------------- 5) layer-0 update (writes f0,f1,f2 planar) + kt for layer 1 ----------------
__global__ __launch_bounds__(256) void update_l0_kt_kernel(
    const float* __restrict__ Ws0, const float* __restrict__ Ws1,
    const float* __restrict__ Ws2, const float* __restrict__ Wsk,
    const float* __restrict__ Wq, const float* __restrict__ Wk) {
    __shared__ __align__(16) float s0[1024], s1[1024], s2[1024], sk[1024];
    __shared__ float sWq[1024], sWkT[1024];
    __shared__ __align__(16) float sag[8][384];   // [c][12] padded
    int tid = threadIdx.x;
    for (int i = tid; i < 1024; i += 256) {
        s0[i] = Ws0[i]; s1[i] = Ws1[i]; s2[i] = Ws2[i]; sk[i] = Wsk[i];
        sWq[i] = Wq[i];
        int c = i >> 5, j = i & 31;
        sWkT[j * 32 + c] = Wk[i];
    }
    __syncthreads();
    int warp = tid >> 5, lane = tid & 31;
    int n = blockIdx.x * 8 + warp;
    if (n >= Nn) return;
    float f = g_f0[(size_t)n * 32 + lane];
    {
        const float* ag = &g_agg[(size_t)n * 288];
#pragma unroll
        for (int s = 0; s < 9; s++)
            sag[warp][lane * 12 + s] = ag[s * 32 + lane];
    }
    __syncwarp();
    float o0 = 0.f, o10 = 0.f, o11 = 0.f, o12 = 0.f;
    float o20 = 0.f, o21 = 0.f, o22 = 0.f, o23 = 0.f, o24 = 0.f;
#pragma unroll 4
    for (int c = 0; c < 32; c++) {
        const float* ac = &sag[warp][c * 12];
        float4 A0 = *(const float4*)ac;
        float4 A1 = *(const float4*)(ac + 4);
        float A8 = ac[8];
        float fc = __shfl_sync(FULLMASK, f, c);
        o0 += A0.x * s0[c * 32 + lane] + fc * sk[c * 32 + lane];
        float w1 = s1[c * 32 + lane];
        o10 += A0.y * w1; o11 += A0.z * w1; o12 += A0.w * w1;
        float w2 = s2[c * 32 + lane];
        o20 += A1.x * w2; o21 += A1.y * w2; o22 += A1.z * w2;
        o23 += A1.w * w2; o24 += A8 * w2;
    }
    g_f0[(size_t)n * 32 + lane] = o0;
    float* f1w = &g_f1[(size_t)n * 96];
    f1w[0 * 32 + lane] = o10; f1w[1 * 32 + lane] = o11; f1w[2 * 32 + lane] = o12;
    float* f2w = &g_f2[(size_t)n * 160];
    f2w[0 * 32 + lane] = o20; f2w[1 * 32 + lane] = o21; f2w[2 * 32 + lane] = o22;
    f2w[3 * 32 + lane] = o23; f2w[4 * 32 + lane] = o24;
    float q = 0.f;
#pragma unroll
    for (int c = 0; c < 32; c++) {
        float fc = __shfl_sync(FULLMASK, o0, c);
        q = fmaf(fc, sWq[c * 32 + lane], q);
    }
#pragma unroll
    for (int h = 0; h < 4; h++) {
        float kt = 0.f;
#pragma unroll
        for (int d = 0; d < 8; d++) {
            float qd = __shfl_sync(FULLMASK, q, h * 8 + d);
            kt = fmaf(qd, sWkT[(h * 8 + d) * 32 + lane], kt);
        }
        g_kt[(size_t)n * 128 + kt_perm(h, lane)] = kt * LOGIT_SCALE;
    }
}

// ---------------- 7) fused layer-1 agg (sequential streams) + f0 update + output + deg re-zero ----------------
__global__ __launch_bounds__(256) void agg_update_out_kernel(
    const float* __restrict__ Ws0, const float* __restrict__ Wsk,
    const float* __restrict__ Wout, const float* __restrict__ Wc,
    float* __restrict__ out) {
    __shared__ __align__(16) float s0[1024], sk[1024], sWo[1024];
    __shared__ float sWc[480];
    int tid = threadIdx.x;
    for (int i = tid; i < 1024; i += 256) {
        s0[i] = Ws0[i]; sk[i] = Wsk[i]; sWo[i] = Wout[i];
    }
    for (int i = tid; i < 480; i += 256) sWc[i] = Wc[i];
    __syncthreads();
    int warp = tid >> 5, lane = tid & 31;
    int n = blockIdx.x * 8 + warp;
    if (n >= Nn) return;
    if (lane == 0) g_deg[n] = 0;   // leave deg zeroed for the next invocation
    int beg = g_off[n], end = g_off[n + 1];
    int grp = lane >> 3;

    float mx = -3.0e38f;
    float den = 0.f, a0 = 0.f;
#pragma unroll 2
    for (int i = beg; i < end; i++) {
        float lg = g_logit[(size_t)i * 4 + grp];
        float m0 = g_m0[(size_t)i * 32 + lane];
        if (lg > mx) {
            float corr = __expf(mx - lg);
            den *= corr; a0 *= corr;
            mx = lg;
        }
        float ee = __expf(lg - mx);
        den += ee;
        a0 = fmaf(ee, m0, a0);
    }
    float a = a0 / (den + 1e-8f);   // agg0[n][lane], stays in registers

    float f = g_f0[(size_t)n * 32 + lane];
    float o0 = 0.f;
#pragma unroll
    for (int c = 0; c < 32; c++) {
        float fc = __shfl_sync(FULLMASK, f, c);
        float ac = __shfl_sync(FULLMASK, a, c);
        o0 += ac * s0[c * 32 + lane] + fc * sk[c * 32 + lane];
    }
    float hs = 0.f;
#pragma unroll
    for (int c = 0; c < 32; c++) {
        float oc = __shfl_sync(FULLMASK, o0, c);
        hs = fmaf(oc, sWo[c * 32 + lane], hs);
    }
    out[(size_t)n * 32 + lane] = hs;
    float cacc = 0.f;
#pragma unroll
    for (int j = 0; j < 32; j++) {
        float hj = __shfl_sync(FULLMASK, hs, j);
        if (lane < 15) cacc = fmaf(hj, sWc[j * 15 + lane], cacc);
    }
    if (lane < 15) out[(size_t)Nn * 32 + (size_t)n * 15 + lane] = cacc;
}

// ---------------- launch ----------------
extern "C" void kernel_launch(void* const* d_in, const int* in_sizes, int n_in,
                              void* d_out, int out_size) {
    const float* pos       = (const float*)d_in[0];
    const float* node_l0   = (const float*)d_in[1];
    const float* edge_feat = (const float*)d_in[2];
    const int*   esrc      = (const int*)d_in[3];
    const int*   edst      = (const int*)d_in[4];
    const float* Wr1       = (const float*)d_in[5];
    const float* br1       = (const float*)d_in[6];
    const float* Wr2       = (const float*)d_in[7];
    const float* Wq        = (const float*)d_in[8];
    const float* Wk        = (const float*)d_in[9];
    const float* Ws0       = (const float*)d_in[10];
    const float* Ws1       = (const float*)d_in[11];
    const float* Ws2       = (const float*)d_in[12];
    const float* Wsk       = (const float*)d_in[13];
    const float* Wout      = (const float*)d_in[14];
    const float* Wc        = (const float*)d_in[15];
    float* out = (float*)d_out;

    const int NODE_BLKS = NODE_BLKS_C;
    const int EDGE_BLKS = Ee / 64;   // warp per 8 edges, 8 warps / block

    init_geom_kernel<<<NODE_BLKS_C + GEOM_BLKS_C, 256>>>(node_l0, Wq, Wk,
                                                         pos, esrc, edst);         // 1
    scan_kernel<<<1, 1024>>>();                                                    // 2
    edge_kernel<true><<<EDGE_BLKS, 256>>>(edge_feat, esrc, edst, Wr1, br1, Wr2);   // 3
    agg_l0_kernel<<<NODE_BLKS, 256>>>();                                           // 4 (profiled slot)
    update_l0_kt_kernel<<<NODE_BLKS, 256>>>(Ws0, Ws1, Ws2, Wsk,
                                            Wq + 1024, Wk + 1024);                 // 5
    edge_kernel<false><<<EDGE_BLKS, 256>>>(edge_feat, esrc, edst, Wr1 + 1056,
                                           br1 + 32, Wr2 + 7168);                  // 6
    agg_update_out_kernel<<<NODE_BLKS, 256>>>(Ws0 + 1024, Wsk + 1024, Wout, Wc, out); // 7
}

// round 13
// speedup vs baseline: 1.0874x; 1.0188x over previous
#include <cuda_runtime.h>
#include <cuda_fp16.h>

#define Nn 30000
#define Ee 480000
#define FULLMASK 0xffffffffu
#define NODE_BLKS_C 3750      // (Nn+7)/8
#define GEOM_BLKS_C 1875      // Ee/256

typedef unsigned long long ull;

// packed fp32x2 helpers (Blackwell FFMA2 path — PTX only)
#define PACK2(d, lo, hi) asm("mov.b64 %0, {%1, %2};" : "=l"(d) : "f"(lo), "f"(hi))
#define UNPACK2(lo, hi, s) asm("mov.b64 {%0, %1}, %2;" : "=f"(lo), "=f"(hi) : "l"(s))
#define FMA2(acc, a, b) asm("fma.rn.f32x2 %0, %1, %2, %0;" : "+l"(acc) : "l"(a), "l"(b))

// ---------------- scratch (static device allocations; no cudaMalloc) ----------------
__device__ __align__(16) float g_geom[Ee * 4];    // edge-order: r, ux, uy, uz
__device__ __align__(16) float g_geomp[Ee * 4];   // CSR-order copy (agg_l0 stream)
__device__ __align__(16) float g_m0[Ee * 32];     // CSR-order
__device__ __align__(16) __half2 g_wh[Ee * 32];   // CSR-order, layer0: [p][32] half2 (w3*f0s, w5*f0s)
__device__ __align__(16) float g_logit[Ee * 4];   // CSR-order
__device__ __align__(16) float g_kt[Nn * 128];    // permuted + pre-scaled by 1/sqrt(8)
__device__ float g_f0[Nn * 32];
__device__ float g_f1[Nn * 96];    // planar [n][3][32]
__device__ float g_f2[Nn * 160];   // planar [n][5][32]
__device__ float g_agg[Nn * 288];  // planar [n][9][32]
__device__ int g_deg[Nn];          // zero-init at load; re-zeroed by last kernel each call
__device__ int g_off[Nn + 1];
__device__ int g_cur[Nn];
__device__ int g_pos[Ee];          // edge -> CSR slot (set by edge_l0, used by edge_l1)

// kt permutation: value for (head h, channel c) stored at (c>>3)*32 + h*8 + (c&7)
__device__ __forceinline__ int kt_perm(int h, int c) {
    return ((c >> 3) << 5) + (h << 3) + (c & 7);
}

#define LOGIT_SCALE 0.35355339059327373f   // 1/sqrt(8), folded into kt

// ---------------- 1) fused init: node blocks do f0-copy + kt(L0); edge blocks do geom+hist ----------------
__global__ __launch_bounds__(256) void init_geom_kernel(
    const float* __restrict__ node_l0, const float* __restrict__ Wq,
    const float* __restrict__ Wk, const float* __restrict__ pos,
    const int* __restrict__ esrc, const int* __restrict__ edst) {
    __shared__ float sWq[1024];    // [c][j]
    __shared__ float sWkT[1024];   // [j][c]
    int tid = threadIdx.x;
    if (blockIdx.x < NODE_BLKS_C) {
        for (int i = tid; i < 1024; i += 256) {
            sWq[i] = Wq[i];
            int c = i >> 5, j = i & 31;
            sWkT[j * 32 + c] = Wk[i];
        }
        __syncthreads();
        int warp = tid >> 5, lane = tid & 31;
        int n = blockIdx.x * 8 + warp;
        if (n >= Nn) return;
        float f = node_l0[(size_t)n * 32 + lane];
        g_f0[(size_t)n * 32 + lane] = f;
        float q = 0.f;
#pragma unroll
        for (int c = 0; c < 32; c++) {
            float fc = __shfl_sync(FULLMASK, f, c);
            q = fmaf(fc, sWq[c * 32 + lane], q);
        }
#pragma unroll
        for (int h = 0; h < 4; h++) {
            float kt = 0.f;
#pragma unroll
            for (int d = 0; d < 8; d++) {
                float qd = __shfl_sync(FULLMASK, q, h * 8 + d);
                kt = fmaf(qd, sWkT[(h * 8 + d) * 32 + lane], kt);
            }
            g_kt[(size_t)n * 128 + kt_perm(h, lane)] = kt * LOGIT_SCALE;
        }
    } else {
        int e = (blockIdx.x - NODE_BLKS_C) * 256 + tid;
        if (e >= Ee) return;
        int s = esrc[e], d = edst[e];
        float rx = pos[d * 3 + 0] - pos[s * 3 + 0];
        float ry = pos[d * 3 + 1] - pos[s * 3 + 1];
        float rz = pos[d * 3 + 2] - pos[s * 3 + 2];
        float r = sqrtf(rx * rx + ry * ry + rz * rz + 1e-8f);
        float inv = 1.0f / r;
        ((float4*)g_geom)[e] = make_float4(r, rx * inv, ry * inv, rz * inv);
        atomicAdd(&g_deg[d], 1);
    }
}

// ---------------- 2) exclusive scan (writes g_off and g_cur) ----------------
__global__ void scan_kernel() {
    __shared__ int sp[1024];
    const int CH = 30;
    int t = threadIdx.x;
    int loc[CH];
    int base = t * CH;
    int s = 0;
#pragma unroll
    for (int i = 0; i < CH; i++) {
        int idx = base + i;
        int v = (idx < Nn) ? g_deg[idx] : 0;
        loc[i] = v;
        s += v;
    }
    sp[t] = s;
    __syncthreads();
    for (int off = 1; off < 1024; off <<= 1) {
        int v = (t >= off) ? sp[t - off] : 0;
        __syncthreads();
        sp[t] += v;
        __syncthreads();
    }
    int run = (t == 0) ? 0 : sp[t - 1];
#pragma unroll
    for (int i = 0; i < CH; i++) {
        int idx = base + i;
        if (idx < Nn) { g_off[idx] = run; g_cur[idx] = run; run += loc[i]; }
    }
    if (t == 1023) g_off[Nn] = sp[1023];
}

// ---------------- 3/5) edge kernel: warp per 8 edges; payloads stored in CSR order ----------------
// FIRST (layer0): planes = (w0, w3, w5); stores m0/wh/logit/geomp at CSR slot p; records g_pos.
// !FIRST (layer1): planes = (w0, w1, w2); stores m0/logit at p = g_pos[e].
template <bool FIRST>
__global__ __launch_bounds__(256) void edge_kernel(
    const float* __restrict__ edge_feat, const int* __restrict__ esrc,
    const int* __restrict__ edst, const float* __restrict__ Wr1,
    const float* __restrict__ br1, const float* __restrict__ Wr2) {
    __shared__ __align__(16) float sWr1[33 * 32];
    __shared__ float sbr1[32];
    __shared__ float sWp0[1024];   // [j][c] plane 0 (w0)
    __shared__ float sWp1[1024];   // plane 1 (w3 | w1)
    __shared__ float sWp2[1024];   // plane 2 (w5 | w2)
    __shared__ __align__(16) float sstage[8][256];  // [warp][i*8+k]
    int tid = threadIdx.x;
    for (int i = tid; i < 33 * 32; i += 256) sWr1[i] = Wr1[i];
    if (tid < 32) sbr1[tid] = br1[tid];
    const int off1 = FIRST ? 96 : 32, off2 = FIRST ? 160 : 64;
    for (int i = tid; i < 1024; i += 256) {
        int j = i >> 5, c = i & 31;
        const float* row = Wr2 + j * 224;
        sWp0[i] = row[c];
        sWp1[i] = row[off1 + c];
        sWp2[i] = row[off2 + c];
    }
    __syncthreads();
    int lane = tid & 31, warp = tid >> 5;
    int e0 = blockIdx.x * 64 + warp * 8;   // Ee % 64 == 0
    float* sst = sstage[warp];

    float t0, t1, t2, t3, t4, t5, t6, t7;
    t0 = edge_feat[(size_t)(e0 + 0) * 32 + lane];
    t1 = edge_feat[(size_t)(e0 + 1) * 32 + lane];
    t2 = edge_feat[(size_t)(e0 + 2) * 32 + lane];
    t3 = edge_feat[(size_t)(e0 + 3) * 32 + lane];
    t4 = edge_feat[(size_t)(e0 + 4) * 32 + lane];
    t5 = edge_feat[(size_t)(e0 + 5) * 32 + lane];
    t6 = edge_feat[(size_t)(e0 + 6) * 32 + lane];
    t7 = edge_feat[(size_t)(e0 + 7) * 32 + lane];
    {
        float4* sp = (float4*)(sst + lane * 8);
        sp[0] = make_float4(t0, t1, t2, t3);
        sp[1] = make_float4(t4, t5, t6, t7);
    }
    __syncwarp();

    float bia = sbr1[lane], w0l = sWr1[lane];
    t0 = fmaf(g_geom[(size_t)(e0 + 0) * 4], w0l, bia);
    t1 = fmaf(g_geom[(size_t)(e0 + 1) * 4], w0l, bia);
    t2 = fmaf(g_geom[(size_t)(e0 + 2) * 4], w0l, bia);
    t3 = fmaf(g_geom[(size_t)(e0 + 3) * 4], w0l, bia);
    t4 = fmaf(g_geom[(size_t)(e0 + 4) * 4], w0l, bia);
    t5 = fmaf(g_geom[(size_t)(e0 + 5) * 4], w0l, bia);
    t6 = fmaf(g_geom[(size_t)(e0 + 6) * 4], w0l, bia);
    t7 = fmaf(g_geom[(size_t)(e0 + 7) * 4], w0l, bia);
    ull h01, h23, h45, h67;
    PACK2(h01, t0, t1); PACK2(h23, t2, t3); PACK2(h45, t4, t5); PACK2(h67, t6, t7);
#pragma unroll
    for (int i = 0; i < 32; i++) {
        const ulonglong2* xp = (const ulonglong2*)(sst + i * 8);
        ulonglong2 xa = xp[0], xb = xp[1];   // LDS.128 x2 (broadcast)
        float wc = sWr1[(i + 1) * 32 + lane];
        ull wd; PACK2(wd, wc, wc);
        FMA2(h01, xa.x, wd); FMA2(h23, xa.y, wd); FMA2(h45, xb.x, wd); FMA2(h67, xb.y, wd);
    }
    UNPACK2(t0, t1, h01); UNPACK2(t2, t3, h23); UNPACK2(t4, t5, h45); UNPACK2(t6, t7, h67);
    t0 = fmaxf(t0, 0.f); t1 = fmaxf(t1, 0.f); t2 = fmaxf(t2, 0.f); t3 = fmaxf(t3, 0.f);
    t4 = fmaxf(t4, 0.f); t5 = fmaxf(t5, 0.f); t6 = fmaxf(t6, 0.f); t7 = fmaxf(t7, 0.f);
    __syncwarp();
    {
        float4* sp = (float4*)(sst + lane * 8);
        sp[0] = make_float4(t0, t1, t2, t3);
        sp[1] = make_float4(t4, t5, t6, t7);
    }
    __syncwarp();

    ull a0[4] = {0, 0, 0, 0}, a1[4] = {0, 0, 0, 0}, a2[4] = {0, 0, 0, 0};
#pragma unroll
    for (int j = 0; j < 32; j++) {
        const ulonglong2* hp = (const ulonglong2*)(sst + j * 8);
        ulonglong2 ha = hp[0], hb = hp[1];   // LDS.128 x2 (broadcast)
        float w0c = sWp0[j * 32 + lane];     // 3 scalar LDS.32 (1 wf each)
        float w1c = sWp1[j * 32 + lane];
        float w2c = sWp2[j * 32 + lane];
        ull p0, p1, p2;
        PACK2(p0, w0c, w0c); PACK2(p1, w1c, w1c); PACK2(p2, w2c, w2c);
        FMA2(a0[0], ha.x, p0); FMA2(a0[1], ha.y, p0); FMA2(a0[2], hb.x, p0); FMA2(a0[3], hb.y, p0);
        FMA2(a1[0], ha.x, p1); FMA2(a1[1], ha.y, p1); FMA2(a1[2], hb.x, p1); FMA2(a1[3], hb.y, p1);
        FMA2(a2[0], ha.x, p2); FMA2(a2[1], ha.y, p2); FMA2(a2[2], hb.x, p2); FMA2(a2[3], hb.y, p2);
    }

    int sub = lane & 7;
#pragma unroll
    for (int q2 = 0; q2 < 4; q2++) {
        float W0a, W0b, W1a, W1b, W2a, W2b;
        UNPACK2(W0a, W0b, a0[q2]);
        UNPACK2(W1a, W1b, a1[q2]);
        UNPACK2(W2a, W2b, a2[q2]);
#pragma unroll
        for (int kk = 0; kk < 2; kk++) {
            int e = e0 + q2 * 2 + kk;
            float W0 = kk ? W0b : W0a, W1 = kk ? W1b : W1a, W2 = kk ? W2b : W2a;
            int src = esrc[e], dst = edst[e];
            float f0s = g_f0[(size_t)src * 32 + lane];
            float m0;
            float4 gm;
            int p;
            if (FIRST) {
                m0 = W0 * f0s;
                gm = ((const float4*)g_geom)[e];   // broadcast; copied to CSR order below
                if (lane == 0) p = atomicAdd(&g_cur[dst], 1);
                p = __shfl_sync(FULLMASK, p, 0);
                if (lane == 0) {
                    g_pos[e] = p;
                    ((float4*)g_geomp)[p] = gm;
                }
                g_wh[(size_t)p * 32 + lane] = __floats2half2_rn(W1 * f0s, W2 * f0s);
            } else {
                gm = ((const float4*)g_geom)[e];
                float ux = gm.y, uy = gm.z, uz = gm.w;
                const float* f1p = &g_f1[(size_t)src * 96];
                const float* f2p = &g_f2[(size_t)src * 160];
                float d1 = f1p[lane] * ux + f1p[32 + lane] * uy + f1p[64 + lane] * uz;
                float s0 = ux * uy, s1 = uy * uz, s2 = 3.f * uz * uz - 1.f;
                float s3 = ux * uz, s4 = ux * ux - uy * uy;
                float d2 = f2p[lane] * s0 + f2p[32 + lane] * s1 + f2p[64 + lane] * s2 +
                           f2p[96 + lane] * s3 + f2p[128 + lane] * s4;
                m0 = fmaf(W1, d1, fmaf(W2, d2, W0 * f0s));
                p = g_pos[e];   // broadcast load
            }
            g_m0[(size_t)p * 32 + lane] = m0;
            const float* ktp = &g_kt[(size_t)dst * 128];
            float v = 0.f;
#pragma unroll
            for (int k2 = 0; k2 < 4; k2++) {
                float mc = __shfl_sync(FULLMASK, m0, sub + 8 * k2);
                v = fmaf(mc, ktp[k2 * 32 + lane], v);
            }
            v += __shfl_xor_sync(FULLMASK, v, 1);
            v += __shfl_xor_sync(FULLMASK, v, 2);
            v += __shfl_xor_sync(FULLMASK, v, 4);
            if (sub == 0)
                g_logit[(size_t)p * 4 + (lane >> 3)] = v;   // kt pre-scaled by 1/sqrt(8)
        }
    }
}

// ---------------- 4) layer-0 aggregation: online softmax, sequential streams, fp16 w ----------------
__global__ __launch_bounds__(256) void agg_l0_kernel() {
    int tid = threadIdx.x;
    int lane = tid & 31;
    int n = blockIdx.x * 8 + (tid >> 5);
    if (n >= Nn) return;
    int beg = g_off[n], end = g_off[n + 1];
    int grp = lane >> 3;

    float mx = -3.0e38f;
    float den = 0.f;
    float a0 = 0.f, a10 = 0.f, a11 = 0.f, a12 = 0.f;
    float a20 = 0.f, a21 = 0.f, a22 = 0.f, a23 = 0.f, a24 = 0.f;
#pragma unroll 2
    for (int i = beg; i < end; i++) {
        float lg = g_logit[(size_t)i * 4 + grp];
        float m0 = g_m0[(size_t)i * 32 + lane];
        float4 gm = ((const float4*)g_geomp)[i];
        float2 w = __half22float2(g_wh[(size_t)i * 32 + lane]);
        if (lg > mx) {   // rescale accumulators (expected ~ln(deg) hits)
            float corr = __expf(mx - lg);   // first hit: -> 0 with zero accums
            den *= corr; a0 *= corr;
            a10 *= corr; a11 *= corr; a12 *= corr;
            a20 *= corr; a21 *= corr; a22 *= corr; a23 *= corr; a24 *= corr;
            mx = lg;
        }
        float ee = __expf(lg - mx);
        den += ee;
        float ux = gm.y, uy = gm.z, uz = gm.w;
        a0 = fmaf(ee, m0, a0);
        float y0 = ux * uy, y1 = uy * uz, y2 = 3.f * uz * uz - 1.f;
        float y3 = ux * uz, y4 = ux * ux - uy * uy;
        float wf3 = w.x * ee, wf5 = w.y * ee;
        a10 = fmaf(wf3, ux, a10); a11 = fmaf(wf3, uy, a11); a12 = fmaf(wf3, uz, a12);
        a20 = fmaf(wf5, y0, a20); a21 = fmaf(wf5, y1, a21); a22 = fmaf(wf5, y2, a22);
        a23 = fmaf(wf5, y3, a23); a24 = fmaf(wf5, y4, a24);
    }
    float dinv = 1.f / (den + 1e-8f);
    float* ag = &g_agg[(size_t)n * 288];   // planar [9][32]
    ag[0 * 32 + lane] = a0 * dinv;
    ag[1 * 32 + lane] = a10 * dinv; ag[2 * 32 + lane] = a11 * dinv; ag[3 * 32 + lane] = a12 * dinv;
    ag[4 * 32 + lane] = a20 * dinv; ag[5 * 32 + lane] = a21 * dinv; ag[6 * 32 + lane] = a22 * dinv;
    ag[7 * 32 + lane] = a23 * dinv; ag[8 * 32 + lane] = a24 * dinv;
}

// ---------------- 5) layer-0 update (writes f0,f1,f2 planar) + kt for layer 1 ----------------
__global__ __launch_bounds__(256) void update_l0_kt_kernel(
    const float* __restrict__ Ws0, const float* __restrict__ Ws1,
    const float* __restrict__ Ws2, const float* __restrict__ Wsk,
    const float* __restrict__ Wq, const float* __restrict__ Wk) {
    __shared__ __align__(16) float s0[1024], s1[1024], s2[1024], sk[1024];
    __shared__ float sWq[1024], sWkT[1024];
    __shared__ __align__(16) float sag[8][384];   // [c][12] padded
    int tid = threadIdx.x;
    for (int i = tid; i < 1024; i += 256) {
        s0[i] = Ws0[i]; s1[i] = Ws1[i]; s2[i] = Ws2[i]; sk[i] = Wsk[i];
        sWq[i] = Wq[i];
        int c = i >> 5, j = i & 31;
        sWkT[j * 32 + c] = Wk[i];
    }
    __syncthreads();
    int warp = tid >> 5, lane = tid & 31;
    int n = blockIdx.x * 8 + warp;
    if (n >= Nn) return;
    float f = g_f0[(size_t)n * 32 + lane];
    {
        const float* ag = &g_agg[(size_t)n * 288];
#pragma unroll
        for (int s = 0; s < 9; s++)
            sag[warp][lane * 12 + s] = ag[s * 32 + lane];
    }
    __syncwarp();
    float o0 = 0.f, o10 = 0.f, o11 = 0.f, o12 = 0.f;
    float o20 = 0.f, o21 = 0.f, o22 = 0.f, o23 = 0.f, o24 = 0.f;
#pragma unroll 4
    for (int c = 0; c < 32; c++) {
        const float* ac = &sag[warp][c * 12];
        float4 A0 = *(const float4*)ac;
        float4 A1 = *(const float4*)(ac + 4);
        float A8 = ac[8];
        float fc = __shfl_sync(FULLMASK, f, c);
        o0 += A0.x * s0[c * 32 + lane] + fc * sk[c * 32 + lane];
        float w1 = s1[c * 32 + lane];
        o10 += A0.y * w1; o11 += A0.z * w1; o12 += A0.w * w1;
        float w2 = s2[c * 32 + lane];
        o20 += A1.x * w2; o21 += A1.y * w2; o22 += A1.z * w2;
        o23 += A1.w * w2; o24 += A8 * w2;
    }
    g_f0[(size_t)n * 32 + lane] = o0;
    float* f1w = &g_f1[(size_t)n * 96];
    f1w[0 * 32 + lane] = o10; f1w[1 * 32 + lane] = o11; f1w[2 * 32 + lane] = o12;
    float* f2w = &g_f2[(size_t)n * 160];
    f2w[0 * 32 + lane] = o20; f2w[1 * 32 + lane] = o21; f2w[2 * 32 + lane] = o22;
    f2w[3 * 32 + lane] = o23; f2w[4 * 32 + lane] = o24;
    float q = 0.f;
#pragma unroll
    for (int c = 0; c < 32; c++) {
        float fc = __shfl_sync(FULLMASK, o0, c);
        q = fmaf(fc, sWq[c * 32 + lane], q);
    }
#pragma unroll
    for (int h = 0; h < 4; h++) {
        float kt = 0.f;
#pragma unroll
        for (int d = 0; d < 8; d++) {
            float qd = __shfl_sync(FULLMASK, q, h * 8 + d);
            kt = fmaf(qd, sWkT[(h * 8 + d) * 32 + lane], kt);
        }
        g_kt[(size_t)n * 128 + kt_perm(h, lane)] = kt * LOGIT_SCALE;
    }
}

// ---------------- 7) fused layer-1 agg (sequential streams) + f0 update + output + deg re-zero ----------------
__global__ __launch_bounds__(256) void agg_update_out_kernel(
    const float* __restrict__ Ws0, const float* __restrict__ Wsk,
    const float* __restrict__ Wout, const float* __restrict__ Wc,
    float* __restrict__ out) {
    __shared__ __align__(16) float s0[1024], sk[1024], sWo[1024];
    __shared__ float sWc[480];
    int tid = threadIdx.x;
    for (int i = tid; i < 1024; i += 256) {
        s0[i] = Ws0[i]; sk[i] = Wsk[i]; sWo[i] = Wout[i];
    }
    for (int i = tid; i < 480; i += 256) sWc[i] = Wc[i];
    __syncthreads();
    int warp = tid >> 5, lane = tid & 31;
    int n = blockIdx.x * 8 + warp;
    if (n >= Nn) return;
    if (lane == 0) g_deg[n] = 0;   // leave deg zeroed for the next invocation
    int beg = g_off[n], end = g_off[n + 1];
    int grp = lane >> 3;

    float mx = -3.0e38f;
    float den = 0.f, a0 = 0.f;
#pragma unroll 2
    for (int i = beg; i < end; i++) {
        float lg = g_logit[(size_t)i * 4 + grp];
        float m0 = g_m0[(size_t)i * 32 + lane];
        if (lg > mx) {
            float corr = __expf(mx - lg);
            den *= corr; a0 *= corr;
            mx = lg;
        }
        float ee = __expf(lg - mx);
        den += ee;
        a0 = fmaf(ee, m0, a0);
    }
    float a = a0 / (den + 1e-8f);   // agg0[n][lane], stays in registers

    float f = g_f0[(size_t)n * 32 + lane];
    float o0 = 0.f;
#pragma unroll
    for (int c = 0; c < 32; c++) {
        float fc = __shfl_sync(FULLMASK, f, c);
        float ac = __shfl_sync(FULLMASK, a, c);
        o0 += ac * s0[c * 32 + lane] + fc * sk[c * 32 + lane];
    }
    float hs = 0.f;
#pragma unroll
    for (int c = 0; c < 32; c++) {
        float oc = __shfl_sync(FULLMASK, o0, c);
        hs = fmaf(oc, sWo[c * 32 + lane], hs);
    }
    out[(size_t)n * 32 + lane] = hs;
    float cacc = 0.f;
#pragma unroll
    for (int j = 0; j < 32; j++) {
        float hj = __shfl_sync(FULLMASK, hs, j);
        if (lane < 15) cacc = fmaf(hj, sWc[j * 15 + lane], cacc);
    }
    if (lane < 15) out[(size_t)Nn * 32 + (size_t)n * 15 + lane] = cacc;
}

// ---------------- launch ----------------
extern "C" void kernel_launch(void* const* d_in, const int* in_sizes, int n_in,
                              void* d_out, int out_size) {
    const float* pos       = (const float*)d_in[0];
    const float* node_l0   = (const float*)d_in[1];
    const float* edge_feat = (const float*)d_in[2];
    const int*   esrc      = (const int*)d_in[3];
    const int*   edst      = (const int*)d_in[4];
    const float* Wr1       = (const float*)d_in[5];
    const float* br1       = (const float*)d_in[6];
    const float* Wr2       = (const float*)d_in[7];
    const float* Wq        = (const float*)d_in[8];
    const float* Wk        = (const float*)d_in[9];
    const float* Ws0       = (const float*)d_in[10];
    const float* Ws1       = (const float*)d_in[11];
    const float* Ws2       = (const float*)d_in[12];
    const float* Wsk       = (const float*)d_in[13];
    const float* Wout      = (const float*)d_in[14];
    const float* Wc        = (const float*)d_in[15];
    float* out = (float*)d_out;

    const int NODE_BLKS = NODE_BLKS_C;
    const int EDGE_BLKS = Ee / 64;   // warp per 8 edges, 8 warps / block

    init_geom_kernel<<<NODE_BLKS_C + GEOM_BLKS_C, 256>>>(node_l0, Wq, Wk,
                                                         pos, esrc, edst);         // 1
    scan_kernel<<<1, 1024>>>();                                                    // 2
    edge_kernel<true><<<EDGE_BLKS, 256>>>(edge_feat, esrc, edst, Wr1, br1, Wr2);   // 3
    agg_l0_kernel<<<NODE_BLKS, 256>>>();                                           // 4 (profiled slot)
    update_l0_kt_kernel<<<NODE_BLKS, 256>>>(Ws0, Ws1, Ws2, Wsk,
                                            Wq + 1024, Wk + 1024);                 // 5
    edge_kernel<false><<<EDGE_BLKS, 256>>>(edge_feat, esrc, edst, Wr1 + 1056,
                                           br1 + 32, Wr2 + 7168);                  // 6
    agg_update_out_kernel<<<NODE_BLKS, 256>>>(Ws0 + 1024, Wsk + 1024, Wout, Wc, out); // 7
}

// round 14
// speedup vs baseline: 1.0944x; 1.0064x over previous
#include <cuda_runtime.h>
#include <cuda_fp16.h>

#define Nn 30000
#define Ee 480000
#define FULLMASK 0xffffffffu
#define NODE_BLKS_C 3750      // (Nn+7)/8
#define GEOM_BLKS_C 1875      // Ee/256

typedef unsigned long long ull;

// packed fp32x2 helpers (Blackwell FFMA2 path — PTX only)
#define PACK2(d, lo, hi) asm("mov.b64 %0, {%1, %2};" : "=l"(d) : "f"(lo), "f"(hi))
#define UNPACK2(lo, hi, s) asm("mov.b64 {%0, %1}, %2;" : "=f"(lo), "=f"(hi) : "l"(s))
#define FMA2(acc, a, b) asm("fma.rn.f32x2 %0, %1, %2, %0;" : "+l"(acc) : "l"(a), "l"(b))

// ---------------- scratch (static device allocations; no cudaMalloc) ----------------
__device__ __align__(16) float g_geom[Ee * 4];    // edge-order: r, ux, uy, uz
__device__ __align__(16) float g_geomp[Ee * 4];   // CSR-order copy (agg_l0 stream)
__device__ __align__(16) __half g_m0h[Ee * 32];   // CSR-order, fp16 (logits use fp32 reg copy)
__device__ __align__(16) __half2 g_wh[Ee * 32];   // CSR-order, layer0: [p][32] half2 (w3*f0s, w5*f0s)
__device__ __align__(16) float g_logit[Ee * 4];   // CSR-order
__device__ __align__(16) float g_kt[Nn * 128];    // permuted + pre-scaled by 1/sqrt(8)
__device__ float g_f0[Nn * 32];
__device__ float g_f1[Nn * 96];    // planar [n][3][32]
__device__ float g_f2[Nn * 160];   // planar [n][5][32]
__device__ float g_agg[Nn * 288];  // planar [n][9][32]
__device__ int g_deg[Nn];          // zero-init at load; re-zeroed by last kernel each call
__device__ int g_off[Nn + 1];
__device__ int g_cur[Nn];
__device__ int g_pos[Ee];          // edge -> CSR slot (set by edge_l0, used by edge_l1)

// kt permutation: value for (head h, channel c) stored at (c>>3)*32 + h*8 + (c&7)
__device__ __forceinline__ int kt_perm(int h, int c) {
    return ((c >> 3) << 5) + (h << 3) + (c & 7);
}

#define LOGIT_SCALE 0.35355339059327373f   // 1/sqrt(8), folded into kt

// ---------------- 1) fused init: node blocks do f0-copy + kt(L0); edge blocks do geom+hist ----------------
__global__ __launch_bounds__(256) void init_geom_kernel(
    const float* __restrict__ node_l0, const float* __restrict__ Wq,
    const float* __restrict__ Wk, const float* __restrict__ pos,
    const int* __restrict__ esrc, const int* __restrict__ edst) {
    __shared__ float sWq[1024];    // [c][j]
    __shared__ float sWkT[1024];   // [j][c]
    int tid = threadIdx.x;
    if (blockIdx.x < NODE_BLKS_C) {
        for (int i = tid; i < 1024; i += 256) {
            sWq[i] = Wq[i];
            int c = i >> 5, j = i & 31;
            sWkT[j * 32 + c] = Wk[i];
        }
        __syncthreads();
        int warp = tid >> 5, lane = tid & 31;
        int n = blockIdx.x * 8 + warp;
        if (n >= Nn) return;
        float f = node_l0[(size_t)n * 32 + lane];
        g_f0[(size_t)n * 32 + lane] = f;
        float q = 0.f;
#pragma unroll
        for (int c = 0; c < 32; c++) {
            float fc = __shfl_sync(FULLMASK, f, c);
            q = fmaf(fc, sWq[c * 32 + lane], q);
        }
#pragma unroll
        for (int h = 0; h < 4; h++) {
            float kt = 0.f;
#pragma unroll
            for (int d = 0; d < 8; d++) {
                float qd = __shfl_sync(FULLMASK, q, h * 8 + d);
                kt = fmaf(qd, sWkT[(h * 8 + d) * 32 + lane], kt);
            }
            g_kt[(size_t)n * 128 + kt_perm(h, lane)] = kt * LOGIT_SCALE;
        }
    } else {
        int e = (blockIdx.x - NODE_BLKS_C) * 256 + tid;
        if (e >= Ee) return;
        int s = esrc[e], d = edst[e];
        float rx = pos[d * 3 + 0] - pos[s * 3 + 0];
        float ry = pos[d * 3 + 1] - pos[s * 3 + 1];
        float rz = pos[d * 3 + 2] - pos[s * 3 + 2];
        float r = sqrtf(rx * rx + ry * ry + rz * rz + 1e-8f);
        float inv = 1.0f / r;
        ((float4*)g_geom)[e] = make_float4(r, rx * inv, ry * inv, rz * inv);
        atomicAdd(&g_deg[d], 1);
    }
}

// ---------------- 2) exclusive scan (writes g_off and g_cur) ----------------
__global__ void scan_kernel() {
    __shared__ int sp[1024];
    const int CH = 30;
    int t = threadIdx.x;
    int loc[CH];
    int base = t * CH;
    int s = 0;
#pragma unroll
    for (int i = 0; i < CH; i++) {
        int idx = base + i;
        int v = (idx < Nn) ? g_deg[idx] : 0;
        loc[i] = v;
        s += v;
    }
    sp[t] = s;
    __syncthreads();
    for (int off = 1; off < 1024; off <<= 1) {
        int v = (t >= off) ? sp[t - off] : 0;
        __syncthreads();
        sp[t] += v;
        __syncthreads();
    }
    int run = (t == 0) ? 0 : sp[t - 1];
#pragma unroll
    for (int i = 0; i < CH; i++) {
        int idx = base + i;
        if (idx < Nn) { g_off[idx] = run; g_cur[idx] = run; run += loc[i]; }
    }
    if (t == 1023) g_off[Nn] = sp[1023];
}

// ---------------- 3/5) edge kernel: warp per 8 edges; payloads stored in CSR order ----------------
// FIRST (layer0): planes = (w0, w3, w5); stores m0h/wh/logit/geomp at CSR slot p; records g_pos.
// !FIRST (layer1): planes = (w0, w1, w2); stores m0h/logit at p = g_pos[e].
template <bool FIRST>
__global__ __launch_bounds__(256) void edge_kernel(
    const float* __restrict__ edge_feat, const int* __restrict__ esrc,
    const int* __restrict__ edst, const float* __restrict__ Wr1,
    const float* __restrict__ br1, const float* __restrict__ Wr2) {
    __shared__ __align__(16) float sWr1[33 * 32];
    __shared__ float sbr1[32];
    __shared__ float sWp0[1024];   // [j][c] plane 0 (w0)
    __shared__ float sWp1[1024];   // plane 1 (w3 | w1)
    __shared__ float sWp2[1024];   // plane 2 (w5 | w2)
    __shared__ __align__(16) float sstage[8][256];  // [warp][i*8+k]
    int tid = threadIdx.x;
    for (int i = tid; i < 33 * 32; i += 256) sWr1[i] = Wr1[i];
    if (tid < 32) sbr1[tid] = br1[tid];
    const int off1 = FIRST ? 96 : 32, off2 = FIRST ? 160 : 64;
    for (int i = tid; i < 1024; i += 256) {
        int j = i >> 5, c = i & 31;
        const float* row = Wr2 + j * 224;
        sWp0[i] = row[c];
        sWp1[i] = row[off1 + c];
        sWp2[i] = row[off2 + c];
    }
    __syncthreads();
    int lane = tid & 31, warp = tid >> 5;
    int e0 = blockIdx.x * 64 + warp * 8;   // Ee % 64 == 0
    float* sst = sstage[warp];

    float t0, t1, t2, t3, t4, t5, t6, t7;
    t0 = edge_feat[(size_t)(e0 + 0) * 32 + lane];
    t1 = edge_feat[(size_t)(e0 + 1) * 32 + lane];
    t2 = edge_feat[(size_t)(e0 + 2) * 32 + lane];
    t3 = edge_feat[(size_t)(e0 + 3) * 32 + lane];
    t4 = edge_feat[(size_t)(e0 + 4) * 32 + lane];
    t5 = edge_feat[(size_t)(e0 + 5) * 32 + lane];
    t6 = edge_feat[(size_t)(e0 + 6) * 32 + lane];
    t7 = edge_feat[(size_t)(e0 + 7) * 32 + lane];
    {
        float4* sp = (float4*)(sst + lane * 8);
        sp[0] = make_float4(t0, t1, t2, t3);
        sp[1] = make_float4(t4, t5, t6, t7);
    }
    __syncwarp();

    float bia = sbr1[lane], w0l = sWr1[lane];
    t0 = fmaf(g_geom[(size_t)(e0 + 0) * 4], w0l, bia);
    t1 = fmaf(g_geom[(size_t)(e0 + 1) * 4], w0l, bia);
    t2 = fmaf(g_geom[(size_t)(e0 + 2) * 4], w0l, bia);
    t3 = fmaf(g_geom[(size_t)(e0 + 3) * 4], w0l, bia);
    t4 = fmaf(g_geom[(size_t)(e0 + 4) * 4], w0l, bia);
    t5 = fmaf(g_geom[(size_t)(e0 + 5) * 4], w0l, bia);
    t6 = fmaf(g_geom[(size_t)(e0 + 6) * 4], w0l, bia);
    t7 = fmaf(g_geom[(size_t)(e0 + 7) * 4], w0l, bia);
    ull h01, h23, h45, h67;
    PACK2(h01, t0, t1); PACK2(h23, t2, t3); PACK2(h45, t4, t5); PACK2(h67, t6, t7);
#pragma unroll
    for (int i = 0; i < 32; i++) {
        const ulonglong2* xp = (const ulonglong2*)(sst + i * 8);
        ulonglong2 xa = xp[0], xb = xp[1];   // LDS.128 x2 (broadcast)
        float wc = sWr1[(i + 1) * 32 + lane];
        ull wd; PACK2(wd, wc, wc);
        FMA2(h01, xa.x, wd); FMA2(h23, xa.y, wd); FMA2(h45, xb.x, wd); FMA2(h67, xb.y, wd);
    }
    UNPACK2(t0, t1, h01); UNPACK2(t2, t3, h23); UNPACK2(t4, t5, h45); UNPACK2(t6, t7, h67);
    t0 = fmaxf(t0, 0.f); t1 = fmaxf(t1, 0.f); t2 = fmaxf(t2, 0.f); t3 = fmaxf(t3, 0.f);
    t4 = fmaxf(t4, 0.f); t5 = fmaxf(t5, 0.f); t6 = fmaxf(t6, 0.f); t7 = fmaxf(t7, 0.f);
    __syncwarp();
    {
        float4* sp = (float4*)(sst + lane * 8);
        sp[0] = make_float4(t0, t1, t2, t3);
        sp[1] = make_float4(t4, t5, t6, t7);
    }
    __syncwarp();

    ull a0[4] = {0, 0, 0, 0}, a1[4] = {0, 0, 0, 0}, a2[4] = {0, 0, 0, 0};
#pragma unroll
    for (int j = 0; j < 32; j++) {
        const ulonglong2* hp = (const ulonglong2*)(sst + j * 8);
        ulonglong2 ha = hp[0], hb = hp[1];   // LDS.128 x2 (broadcast)
        float w0c = sWp0[j * 32 + lane];     // 3 scalar LDS.32 (1 wf each)
        float w1c = sWp1[j * 32 + lane];
        float w2c = sWp2[j * 32 + lane];
        ull p0, p1, p2;
        PACK2(p0, w0c, w0c); PACK2(p1, w1c, w1c); PACK2(p2, w2c, w2c);
        FMA2(a0[0], ha.x, p0); FMA2(a0[1], ha.y, p0); FMA2(a0[2], hb.x, p0); FMA2(a0[3], hb.y, p0);
        FMA2(a1[0], ha.x, p1); FMA2(a1[1], ha.y, p1); FMA2(a1[2], hb.x, p1); FMA2(a1[3], hb.y, p1);
        FMA2(a2[0], ha.x, p2); FMA2(a2[1], ha.y, p2); FMA2(a2[2], hb.x, p2); FMA2(a2[3], hb.y, p2);
    }

    int sub = lane & 7;
#pragma unroll
    for (int q2 = 0; q2 < 4; q2++) {
        float W0a, W0b, W1a, W1b, W2a, W2b;
        UNPACK2(W0a, W0b, a0[q2]);
        UNPACK2(W1a, W1b, a1[q2]);
        UNPACK2(W2a, W2b, a2[q2]);
#pragma unroll
        for (int kk = 0; kk < 2; kk++) {
            int e = e0 + q2 * 2 + kk;
            float W0 = kk ? W0b : W0a, W1 = kk ? W1b : W1a, W2 = kk ? W2b : W2a;
            int src = esrc[e], dst = edst[e];
            float f0s = g_f0[(size_t)src * 32 + lane];
            float m0;
            float4 gm;
            int p;
            if (FIRST) {
                m0 = W0 * f0s;
                gm = ((const float4*)g_geom)[e];   // broadcast; copied to CSR order below
                if (lane == 0) p = atomicAdd(&g_cur[dst], 1);
                p = __shfl_sync(FULLMASK, p, 0);
                if (lane == 0) {
                    g_pos[e] = p;
                    ((float4*)g_geomp)[p] = gm;
                }
                g_wh[(size_t)p * 32 + lane] = __floats2half2_rn(W1 * f0s, W2 * f0s);
            } else {
                gm = ((const float4*)g_geom)[e];
                float ux = gm.y, uy = gm.z, uz = gm.w;
                const float* f1p = &g_f1[(size_t)src * 96];
                const float* f2p = &g_f2[(size_t)src * 160];
                float d1 = f1p[lane] * ux + f1p[32 + lane] * uy + f1p[64 + lane] * uz;
                float s0 = ux * uy, s1 = uy * uz, s2 = 3.f * uz * uz - 1.f;
                float s3 = ux * uz, s4 = ux * ux - uy * uy;
                float d2 = f2p[lane] * s0 + f2p[32 + lane] * s1 + f2p[64 + lane] * s2 +
                           f2p[96 + lane] * s3 + f2p[128 + lane] * s4;
                m0 = fmaf(W1, d1, fmaf(W2, d2, W0 * f0s));
                p = g_pos[e];   // broadcast load
            }
            g_m0h[(size_t)p * 32 + lane] = __float2half_rn(m0);
            const float* ktp = &g_kt[(size_t)dst * 128];
            float v = 0.f;
#pragma unroll
            for (int k2 = 0; k2 < 4; k2++) {
                float mc = __shfl_sync(FULLMASK, m0, sub + 8 * k2);   // fp32 logit path
                v = fmaf(mc, ktp[k2 * 32 + lane], v);
            }
            v += __shfl_xor_sync(FULLMASK, v, 1);
            v += __shfl_xor_sync(FULLMASK, v, 2);
            v += __shfl_xor_sync(FULLMASK, v, 4);
            if (sub == 0)
                g_logit[(size_t)p * 4 + (lane >> 3)] = v;   // kt pre-scaled by 1/sqrt(8)
        }
    }
}

// ---------------- 4) layer-0 aggregation: online softmax, sequential fp16 streams ----------------
__global__ __launch_bounds__(256) void agg_l0_kernel() {
    int tid = threadIdx.x;
    int lane = tid & 31;
    int n = blockIdx.x * 8 + (tid >> 5);
    if (n >= Nn) return;
    int beg = g_off[n], end = g_off[n + 1];
    int grp = lane >> 3;

    float mx = -3.0e38f;
    float den = 0.f;
    float a0 = 0.f, a10 = 0.f, a11 = 0.f, a12 = 0.f;
    float a20 = 0.f, a21 = 0.f, a22 = 0.f, a23 = 0.f, a24 = 0.f;
#pragma unroll 2
    for (int i = beg; i < end; i++) {
        float lg = g_logit[(size_t)i * 4 + grp];
        float m0 = __half2float(g_m0h[(size_t)i * 32 + lane]);
        float4 gm = ((const float4*)g_geomp)[i];
        float2 w = __half22float2(g_wh[(size_t)i * 32 + lane]);
        if (lg > mx) {   // rescale accumulators (expected ~ln(deg) hits)
            float corr = __expf(mx - lg);   // first hit: -> 0 with zero accums
            den *= corr; a0 *= corr;
            a10 *= corr; a11 *= corr; a12 *= corr;
            a20 *= corr; a21 *= corr; a22 *= corr; a23 *= corr; a24 *= corr;
            mx = lg;
        }
        float ee = __expf(lg - mx);
        den += ee;
        float ux = gm.y, uy = gm.z, uz = gm.w;
        a0 = fmaf(ee, m0, a0);
        float y0 = ux * uy, y1 = uy * uz, y2 = 3.f * uz * uz - 1.f;
        float y3 = ux * uz, y4 = ux * ux - uy * uy;
        float wf3 = w.x * ee, wf5 = w.y * ee;
        a10 = fmaf(wf3, ux, a10); a11 = fmaf(wf3, uy, a11); a12 = fmaf(wf3, uz, a12);
        a20 = fmaf(wf5, y0, a20); a21 = fmaf(wf5, y1, a21); a22 = fmaf(wf5, y2, a22);
        a23 = fmaf(wf5, y3, a23); a24 = fmaf(wf5, y4, a24);
    }
    float dinv = 1.f / (den + 1e-8f);
    float* ag = &g_agg[(size_t)n * 288];   // planar [9][32]
    ag[0 * 32 + lane] = a0 * dinv;
    ag[1 * 32 + lane] = a10 * dinv; ag[2 * 32 + lane] = a11 * dinv; ag[3 * 32 + lane] = a12 * dinv;
    ag[4 * 32 + lane] = a20 * dinv; ag[5 * 32 + lane] = a21 * dinv; ag[6 * 32 + lane] = a22 * dinv;
    ag[7 * 32 + lane] = a23 * dinv; ag[8 * 32 + lane] = a24 * dinv;
}

// ---------------- 5) layer-0 update (writes f0,f1,f2 planar) + kt for layer 1 ----------------
__global__ __launch_bounds__(256) void update_l0_kt_kernel(
    const float* __restrict__ Ws0, const float* __restrict__ Ws1,
    const float* __restrict__ Ws2, const float* __restrict__ Wsk,
    const float* __restrict__ Wq, const float* __restrict__ Wk) {
    __shared__ __align__(16) float s0[1024], s1[1024], s2[1024], sk[1024];
    __shared__ float sWq[1024], sWkT[1024];
    __shared__ __align__(16) float sag[8][384];   // [c][12] padded
    int tid = threadIdx.x;
    for (int i = tid; i < 1024; i += 256) {
        s0[i] = Ws0[i]; s1[i] = Ws1[i]; s2[i] = Ws2[i]; sk[i] = Wsk[i];
        sWq[i] = Wq[i];
        int c = i >> 5, j = i & 31;
        sWkT[j * 32 + c] = Wk[i];
    }
    __syncthreads();
    int warp = tid >> 5, lane = tid & 31;
    int n = blockIdx.x * 8 + warp;
    if (n >= Nn) return;
    float f = g_f0[(size_t)n * 32 + lane];
    {
        const float* ag = &g_agg[(size_t)n * 288];
#pragma unroll
        for (int s = 0; s < 9; s++)
            sag[warp][lane * 12 + s] = ag[s * 32 + lane];
    }
    __syncwarp();
    float o0 = 0.f, o10 = 0.f, o11 = 0.f, o12 = 0.f;
    float o20 = 0.f, o21 = 0.f, o22 = 0.f, o23 = 0.f, o24 = 0.f;
#pragma unroll 4
    for (int c = 0; c < 32; c++) {
        const float* ac = &sag[warp][c * 12];
        float4 A0 = *(const float4*)ac;
        float4 A1 = *(const float4*)(ac + 4);
        float A8 = ac[8];
        float fc = __shfl_sync(FULLMASK, f, c);
        o0 += A0.x * s0[c * 32 + lane] + fc * sk[c * 32 + lane];
        float w1 = s1[c * 32 + lane];
        o10 += A0.y * w1; o11 += A0.z * w1; o12 += A0.w * w1;
        float w2 = s2[c * 32 + lane];
        o20 += A1.x * w2; o21 += A1.y * w2; o22 += A1.z * w2;
        o23 += A1.w * w2; o24 += A8 * w2;
    }
    g_f0[(size_t)n * 32 + lane] = o0;
    float* f1w = &g_f1[(size_t)n * 96];
    f1w[0 * 32 + lane] = o10; f1w[1 * 32 + lane] = o11; f1w[2 * 32 + lane] = o12;
    float* f2w = &g_f2[(size_t)n * 160];
    f2w[0 * 32 + lane] = o20; f2w[1 * 32 + lane] = o21; f2w[2 * 32 + lane] = o22;
    f2w[3 * 32 + lane] = o23; f2w[4 * 32 + lane] = o24;
    float q = 0.f;
#pragma unroll
    for (int c = 0; c < 32; c++) {
        float fc = __shfl_sync(FULLMASK, o0, c);
        q = fmaf(fc, sWq[c * 32 + lane], q);
    }
#pragma unroll
    for (int h = 0; h < 4; h++) {
        float kt = 0.f;
#pragma unroll
        for (int d = 0; d < 8; d++) {
            float qd = __shfl_sync(FULLMASK, q, h * 8 + d);
            kt = fmaf(qd, sWkT[(h * 8 + d) * 32 + lane], kt);
        }
        g_kt[(size_t)n * 128 + kt_perm(h, lane)] = kt * LOGIT_SCALE;
    }
}

// ---------------- 7) fused layer-1 agg (fp16 m0 stream) + f0 update + output + deg re-zero ----------------
__global__ __launch_bounds__(256) void agg_update_out_kernel(
    const float* __restrict__ Ws0, const float* __restrict__ Wsk,
    const float* __restrict__ Wout, const float* __restrict__ Wc,
    float* __restrict__ out) {
    __shared__ __align__(16) float s0[1024], sk[1024], sWo[1024];
    __shared__ float sWc[480];
    int tid = threadIdx.x;
    for (int i = tid; i < 1024; i += 256) {
        s0[i] = Ws0[i]; sk[i] = Wsk[i]; sWo[i] = Wout[i];
    }
    for (int i = tid; i < 480; i += 256) sWc[i] = Wc[i];
    __syncthreads();
    int warp = tid >> 5, lane = tid & 31;
    int n = blockIdx.x * 8 + warp;
    if (n >= Nn) return;
    if (lane == 0) g_deg[n] = 0;   // leave deg zeroed for the next invocation
    int beg = g_off[n], end = g_off[n + 1];
    int grp = lane >> 3;

    float mx = -3.0e38f;
    float den = 0.f, a0 = 0.f;
#pragma unroll 2
    for (int i = beg; i < end; i++) {
        float lg = g_logit[(size_t)i * 4 + grp];
        float m0 = __half2float(g_m0h[(size_t)i * 32 + lane]);
        if (lg > mx) {
            float corr = __expf(mx - lg);
            den *= corr; a0 *= corr;
            mx = lg;
        }
        float ee = __expf(lg - mx);
        den += ee;
        a0 = fmaf(ee, m0, a0);
    }
    float a = a0 / (den + 1e-8f);   // agg0[n][lane], stays in registers

    float f = g_f0[(size_t)n * 32 + lane];
    float o0 = 0.f;
#pragma unroll
    for (int c = 0; c < 32; c++) {
        float fc = __shfl_sync(FULLMASK, f, c);
        float ac = __shfl_sync(FULLMASK, a, c);
        o0 += ac * s0[c * 32 + lane] + fc * sk[c * 32 + lane];
    }
    float hs = 0.f;
#pragma unroll
    for (int c = 0; c < 32; c++) {
        float oc = __shfl_sync(FULLMASK, o0, c);
        hs = fmaf(oc, sWo[c * 32 + lane], hs);
    }
    out[(size_t)n * 32 + lane] = hs;
    float cacc = 0.f;
#pragma unroll
    for (int j = 0; j < 32; j++) {
        float hj = __shfl_sync(FULLMASK, hs, j);
        if (lane < 15) cacc = fmaf(hj, sWc[j * 15 + lane], cacc);
    }
    if (lane < 15) out[(size_t)Nn * 32 + (size_t)n * 15 + lane] = cacc;
}

// ---------------- launch ----------------
extern "C" void kernel_launch(void* const* d_in, const int* in_sizes, int n_in,
                              void* d_out, int out_size) {
    const float* pos       = (const float*)d_in[0];
    const float* node_l0   = (const float*)d_in[1];
    const float* edge_feat = (const float*)d_in[2];
    const int*   esrc      = (const int*)d_in[3];
    const int*   edst      = (const int*)d_in[4];
    const float* Wr1       = (const float*)d_in[5];
    const float* br1       = (const float*)d_in[6];
    const float* Wr2       = (const float*)d_in[7];
    const float* Wq        = (const float*)d_in[8];
    const float* Wk        = (const float*)d_in[9];
    const float* Ws0       = (const float*)d_in[10];
    const float* Ws1       = (const float*)d_in[11];
    const float* Ws2       = (const float*)d_in[12];
    const float* Wsk       = (const float*)d_in[13];
    const float* Wout      = (const float*)d_in[14];
    const float* Wc        = (const float*)d_in[15];
    float* out = (float*)d_out;

    const int NODE_BLKS = NODE_BLKS_C;
    const int EDGE_BLKS = Ee / 64;   // warp per 8 edges, 8 warps / block

    init_geom_kernel<<<NODE_BLKS_C + GEOM_BLKS_C, 256>>>(node_l0, Wq, Wk,
                                                         pos, esrc, edst);         // 1
    scan_kernel<<<1, 1024>>>();                                                    // 2
    edge_kernel<true><<<EDGE_BLKS, 256>>>(edge_feat, esrc, edst, Wr1, br1, Wr2);   // 3
    agg_l0_kernel<<<NODE_BLKS, 256>>>();                                           // 4 (profiled slot)
    update_l0_kt_kernel<<<NODE_BLKS, 256>>>(Ws0, Ws1, Ws2, Wsk,
                                            Wq + 1024, Wk + 1024);                 // 5
    edge_kernel<false><<<EDGE_BLKS, 256>>>(edge_feat, esrc, edst, Wr1 + 1056,
                                           br1 + 32, Wr2 + 7168);                  // 6
    agg_update_out_kernel<<<NODE_BLKS, 256>>>(Ws0 + 1024, Wsk + 1024, Wout, Wc, out); // 7
}

// round 15
// speedup vs baseline: 1.1222x; 1.0253x over previous
#include <cuda_runtime.h>
#include <cuda_fp16.h>

#define Nn 30000
#define Ee 480000
#define FULLMASK 0xffffffffu
#define NODE_BLKS_C 3750      // (Nn+7)/8
#define GEOM_BLKS_C 1875      // Ee/256

typedef unsigned long long ull;

// packed fp32x2 helpers (Blackwell FFMA2 path — PTX only)
#define PACK2(d, lo, hi) asm("mov.b64 %0, {%1, %2};" : "=l"(d) : "f"(lo), "f"(hi))
#define UNPACK2(lo, hi, s) asm("mov.b64 {%0, %1}, %2;" : "=f"(lo), "=f"(hi) : "l"(s))
#define FMA2(acc, a, b) asm("fma.rn.f32x2 %0, %1, %2, %0;" : "+l"(acc) : "l"(a), "l"(b))

// ---------------- scratch (static device allocations; no cudaMalloc) ----------------
__device__ __align__(16) float g_geom[Ee * 4];    // edge-order: r, ux, uy, uz
__device__ __align__(16) float g_geomp[Ee * 4];   // CSR-order copy (agg_l0 stream)
__device__ __align__(16) __half g_m0h[Ee * 32];   // CSR-order, fp16 (logits use fp32 reg copy)
__device__ __align__(16) __half2 g_wh[Ee * 32];   // CSR-order, layer0: [p][32] half2 (w3*f0s, w5*f0s)
__device__ __align__(16) float g_logit[Ee * 4];   // CSR-order
__device__ __align__(16) float g_kt[Nn * 128];    // permuted + pre-scaled by 1/sqrt(8)
__device__ float g_f0[Nn * 32];
__device__ __align__(16) __half g_f1h[Nn * 96];   // planar [n][3][32], fp16 (l=1 correction path)
__device__ __align__(16) __half g_f2h[Nn * 160];  // planar [n][5][32], fp16
__device__ float g_agg[Nn * 288];  // planar [n][9][32]
__device__ int g_deg[Nn];          // zero-init at load; re-zeroed by last kernel each call
__device__ int g_off[Nn + 1];
__device__ int g_cur[Nn];
__device__ int g_pos[Ee];          // edge -> CSR slot (set by edge_l0, used by edge_l1)

// kt permutation: value for (head h, channel c) stored at (c>>3)*32 + h*8 + (c&7)
__device__ __forceinline__ int kt_perm(int h, int c) {
    return ((c >> 3) << 5) + (h << 3) + (c & 7);
}

#define LOGIT_SCALE 0.35355339059327373f   // 1/sqrt(8), folded into kt

// ---------------- 1) fused init: node blocks do f0-copy + kt(L0); edge blocks do geom+hist ----------------
__global__ __launch_bounds__(256) void init_geom_kernel(
    const float* __restrict__ node_l0, const float* __restrict__ Wq,
    const float* __restrict__ Wk, const float* __restrict__ pos,
    const int* __restrict__ esrc, const int* __restrict__ edst) {
    __shared__ float sWq[1024];    // [c][j]
    __shared__ float sWkT[1024];   // [j][c]
    int tid = threadIdx.x;
    if (blockIdx.x < NODE_BLKS_C) {
        for (int i = tid; i < 1024; i += 256) {
            sWq[i] = Wq[i];
            int c = i >> 5, j = i & 31;
            sWkT[j * 32 + c] = Wk[i];
        }
        __syncthreads();
        int warp = tid >> 5, lane = tid & 31;
        int n = blockIdx.x * 8 + warp;
        if (n >= Nn) return;
        float f = node_l0[(size_t)n * 32 + lane];
        g_f0[(size_t)n * 32 + lane] = f;
        float q = 0.f;
#pragma unroll
        for (int c = 0; c < 32; c++) {
            float fc = __shfl_sync(FULLMASK, f, c);
            q = fmaf(fc, sWq[c * 32 + lane], q);
        }
#pragma unroll
        for (int h = 0; h < 4; h++) {
            float kt = 0.f;
#pragma unroll
            for (int d = 0; d < 8; d++) {
                float qd = __shfl_sync(FULLMASK, q, h * 8 + d);
                kt = fmaf(qd, sWkT[(h * 8 + d) * 32 + lane], kt);
            }
            g_kt[(size_t)n * 128 + kt_perm(h, lane)] = kt * LOGIT_SCALE;
        }
    } else {
        int e = (blockIdx.x - NODE_BLKS_C) * 256 + tid;
        if (e >= Ee) return;
        int s = esrc[e], d = edst[e];
        float rx = pos[d * 3 + 0] - pos[s * 3 + 0];
        float ry = pos[d * 3 + 1] - pos[s * 3 + 1];
        float rz = pos[d * 3 + 2] - pos[s * 3 + 2];
        float r = sqrtf(rx * rx + ry * ry + rz * rz + 1e-8f);
        float inv = 1.0f / r;
        ((float4*)g_geom)[e] = make_float4(r, rx * inv, ry * inv, rz * inv);
        atomicAdd(&g_deg[d], 1);
    }
}

// ---------------- 2) exclusive scan (writes g_off and g_cur) ----------------
__global__ void scan_kernel() {
    __shared__ int sp[1024];
    const int CH = 30;
    int t = threadIdx.x;
    int loc[CH];
    int base = t * CH;
    int s = 0;
#pragma unroll
    for (int i = 0; i < CH; i++) {
        int idx = base + i;
        int v = (idx < Nn) ? g_deg[idx] : 0;
        loc[i] = v;
        s += v;
    }
    sp[t] = s;
    __syncthreads();
    for (int off = 1; off < 1024; off <<= 1) {
        int v = (t >= off) ? sp[t - off] : 0;
        __syncthreads();
        sp[t] += v;
        __syncthreads();
    }
    int run = (t == 0) ? 0 : sp[t - 1];
#pragma unroll
    for (int i = 0; i < CH; i++) {
        int idx = base + i;
        if (idx < Nn) { g_off[idx] = run; g_cur[idx] = run; run += loc[i]; }
    }
    if (t == 1023) g_off[Nn] = sp[1023];
}

// ---------------- 3/5) edge kernel: warp per 8 edges, 2 tiles per block (preamble amortized) ----------------
// FIRST (layer0): planes = (w0, w3, w5); stores m0h/wh/logit/geomp at CSR slot p; records g_pos.
// !FIRST (layer1): planes = (w0, w1, w2); reads fp16 f1/f2; stores m0h/logit at p = g_pos[e].
template <bool FIRST>
__global__ __launch_bounds__(256) void edge_kernel(
    const float* __restrict__ edge_feat, const int* __restrict__ esrc,
    const int* __restrict__ edst, const float* __restrict__ Wr1,
    const float* __restrict__ br1, const float* __restrict__ Wr2) {
    __shared__ __align__(16) float sWr1[33 * 32];
    __shared__ float sbr1[32];
    __shared__ float sWp0[1024];   // [j][c] plane 0 (w0)
    __shared__ float sWp1[1024];   // plane 1 (w3 | w1)
    __shared__ float sWp2[1024];   // plane 2 (w5 | w2)
    __shared__ __align__(16) float sstage[8][256];  // [warp][i*8+k]
    int tid = threadIdx.x;
    for (int i = tid; i < 33 * 32; i += 256) sWr1[i] = Wr1[i];
    if (tid < 32) sbr1[tid] = br1[tid];
    const int off1 = FIRST ? 96 : 32, off2 = FIRST ? 160 : 64;
    for (int i = tid; i < 1024; i += 256) {
        int j = i >> 5, c = i & 31;
        const float* row = Wr2 + j * 224;
        sWp0[i] = row[c];
        sWp1[i] = row[off1 + c];
        sWp2[i] = row[off2 + c];
    }
    __syncthreads();
    int lane = tid & 31, warp = tid >> 5;
    int sub = lane & 7;
    float* sst = sstage[warp];

#pragma unroll 1
    for (int tile = 0; tile < 2; tile++) {
        int e0 = (blockIdx.x * 2 + tile) * 64 + warp * 8;   // Ee % 128 == 0

        float t0, t1, t2, t3, t4, t5, t6, t7;
        t0 = edge_feat[(size_t)(e0 + 0) * 32 + lane];
        t1 = edge_feat[(size_t)(e0 + 1) * 32 + lane];
        t2 = edge_feat[(size_t)(e0 + 2) * 32 + lane];
        t3 = edge_feat[(size_t)(e0 + 3) * 32 + lane];
        t4 = edge_feat[(size_t)(e0 + 4) * 32 + lane];
        t5 = edge_feat[(size_t)(e0 + 5) * 32 + lane];
        t6 = edge_feat[(size_t)(e0 + 6) * 32 + lane];
        t7 = edge_feat[(size_t)(e0 + 7) * 32 + lane];
        __syncwarp();
        {
            float4* sp = (float4*)(sst + lane * 8);
            sp[0] = make_float4(t0, t1, t2, t3);
            sp[1] = make_float4(t4, t5, t6, t7);
        }
        __syncwarp();

        float bia = sbr1[lane], w0l = sWr1[lane];
        t0 = fmaf(g_geom[(size_t)(e0 + 0) * 4], w0l, bia);
        t1 = fmaf(g_geom[(size_t)(e0 + 1) * 4], w0l, bia);
        t2 = fmaf(g_geom[(size_t)(e0 + 2) * 4], w0l, bia);
        t3 = fmaf(g_geom[(size_t)(e0 + 3) * 4], w0l, bia);
        t4 = fmaf(g_geom[(size_t)(e0 + 4) * 4], w0l, bia);
        t5 = fmaf(g_geom[(size_t)(e0 + 5) * 4], w0l, bia);
        t6 = fmaf(g_geom[(size_t)(e0 + 6) * 4], w0l, bia);
        t7 = fmaf(g_geom[(size_t)(e0 + 7) * 4], w0l, bia);
        ull h01, h23, h45, h67;
        PACK2(h01, t0, t1); PACK2(h23, t2, t3); PACK2(h45, t4, t5); PACK2(h67, t6, t7);
#pragma unroll
        for (int i = 0; i < 32; i++) {
            const ulonglong2* xp = (const ulonglong2*)(sst + i * 8);
            ulonglong2 xa = xp[0], xb = xp[1];   // LDS.128 x2 (broadcast)
            float wc = sWr1[(i + 1) * 32 + lane];
            ull wd; PACK2(wd, wc, wc);
            FMA2(h01, xa.x, wd); FMA2(h23, xa.y, wd); FMA2(h45, xb.x, wd); FMA2(h67, xb.y, wd);
        }
        UNPACK2(t0, t1, h01); UNPACK2(t2, t3, h23); UNPACK2(t4, t5, h45); UNPACK2(t6, t7, h67);
        t0 = fmaxf(t0, 0.f); t1 = fmaxf(t1, 0.f); t2 = fmaxf(t2, 0.f); t3 = fmaxf(t3, 0.f);
        t4 = fmaxf(t4, 0.f); t5 = fmaxf(t5, 0.f); t6 = fmaxf(t6, 0.f); t7 = fmaxf(t7, 0.f);
        __syncwarp();
        {
            float4* sp = (float4*)(sst + lane * 8);
            sp[0] = make_float4(t0, t1, t2, t3);
            sp[1] = make_float4(t4, t5, t6, t7);
        }
        __syncwarp();

        ull a0[4] = {0, 0, 0, 0}, a1[4] = {0, 0, 0, 0}, a2[4] = {0, 0, 0, 0};
#pragma unroll
        for (int j = 0; j < 32; j++) {
            const ulonglong2* hp = (const ulonglong2*)(sst + j * 8);
            ulonglong2 ha = hp[0], hb = hp[1];   // LDS.128 x2 (broadcast)
            float w0c = sWp0[j * 32 + lane];     // 3 scalar LDS.32 (1 wf each)
            float w1c = sWp1[j * 32 + lane];
            float w2c = sWp2[j * 32 + lane];
            ull p0, p1, p2;
            PACK2(p0, w0c, w0c); PACK2(p1, w1c, w1c); PACK2(p2, w2c, w2c);
            FMA2(a0[0], ha.x, p0); FMA2(a0[1], ha.y, p0); FMA2(a0[2], hb.x, p0); FMA2(a0[3], hb.y, p0);
            FMA2(a1[0], ha.x, p1); FMA2(a1[1], ha.y, p1); FMA2(a1[2], hb.x, p1); FMA2(a1[3], hb.y, p1);
            FMA2(a2[0], ha.x, p2); FMA2(a2[1], ha.y, p2); FMA2(a2[2], hb.x, p2); FMA2(a2[3], hb.y, p2);
        }

#pragma unroll
        for (int q2 = 0; q2 < 4; q2++) {
            float W0a, W0b, W1a, W1b, W2a, W2b;
            UNPACK2(W0a, W0b, a0[q2]);
            UNPACK2(W1a, W1b, a1[q2]);
            UNPACK2(W2a, W2b, a2[q2]);
#pragma unroll
            for (int kk = 0; kk < 2; kk++) {
                int e = e0 + q2 * 2 + kk;
                float W0 = kk ? W0b : W0a, W1 = kk ? W1b : W1a, W2 = kk ? W2b : W2a;
                int src = esrc[e], dst = edst[e];
                float f0s = g_f0[(size_t)src * 32 + lane];
                float m0;
                int p;
                if (FIRST) {
                    m0 = W0 * f0s;
                    float4 gm = ((const float4*)g_geom)[e];
                    if (lane == 0) p = atomicAdd(&g_cur[dst], 1);
                    p = __shfl_sync(FULLMASK, p, 0);
                    if (lane == 0) {
                        g_pos[e] = p;
                        ((float4*)g_geomp)[p] = gm;
                    }
                    g_wh[(size_t)p * 32 + lane] = __floats2half2_rn(W1 * f0s, W2 * f0s);
                } else {
                    float4 gm = ((const float4*)g_geom)[e];
                    float ux = gm.y, uy = gm.z, uz = gm.w;
                    const __half* f1p = &g_f1h[(size_t)src * 96];
                    const __half* f2p = &g_f2h[(size_t)src * 160];
                    float d1 = __half2float(f1p[lane]) * ux + __half2float(f1p[32 + lane]) * uy +
                               __half2float(f1p[64 + lane]) * uz;
                    float s0 = ux * uy, s1 = uy * uz, s2 = 3.f * uz * uz - 1.f;
                    float s3 = ux * uz, s4 = ux * ux - uy * uy;
                    float d2 = __half2float(f2p[lane]) * s0 + __half2float(f2p[32 + lane]) * s1 +
                               __half2float(f2p[64 + lane]) * s2 + __half2float(f2p[96 + lane]) * s3 +
                               __half2float(f2p[128 + lane]) * s4;
                    m0 = fmaf(W1, d1, fmaf(W2, d2, W0 * f0s));
                    p = g_pos[e];   // broadcast load
                }
                g_m0h[(size_t)p * 32 + lane] = __float2half_rn(m0);
                const float* ktp = &g_kt[(size_t)dst * 128];
                float v = 0.f;
#pragma unroll
                for (int k2 = 0; k2 < 4; k2++) {
                    float mc = __shfl_sync(FULLMASK, m0, sub + 8 * k2);   // fp32 logit path
                    v = fmaf(mc, ktp[k2 * 32 + lane], v);
                }
                v += __shfl_xor_sync(FULLMASK, v, 1);
                v += __shfl_xor_sync(FULLMASK, v, 2);
                v += __shfl_xor_sync(FULLMASK, v, 4);
                if (sub == 0)
                    g_logit[(size_t)p * 4 + (lane >> 3)] = v;   // kt pre-scaled by 1/sqrt(8)
            }
        }
    }
}

// ---------------- 4) layer-0 aggregation: online softmax, sequential fp16 streams ----------------
__global__ __launch_bounds__(256) void agg_l0_kernel() {
    int tid = threadIdx.x;
    int lane = tid & 31;
    int n = blockIdx.x * 8 + (tid >> 5);
    if (n >= Nn) return;
    int beg = g_off[n], end = g_off[n + 1];
    int grp = lane >> 3;

    float mx = -3.0e38f;
    float den = 0.f;
    float a0 = 0.f, a10 = 0.f, a11 = 0.f, a12 = 0.f;
    float a20 = 0.f, a21 = 0.f, a22 = 0.f, a23 = 0.f, a24 = 0.f;
#pragma unroll 2
    for (int i = beg; i < end; i++) {
        float lg = g_logit[(size_t)i * 4 + grp];
        float m0 = __half2float(g_m0h[(size_t)i * 32 + lane]);
        float4 gm = ((const float4*)g_geomp)[i];
        float2 w = __half22float2(g_wh[(size_t)i * 32 + lane]);
        if (lg > mx) {   // rescale accumulators (expected ~ln(deg) hits)
            float corr = __expf(mx - lg);   // first hit: -> 0 with zero accums
            den *= corr; a0 *= corr;
            a10 *= corr; a11 *= corr; a12 *= corr;
            a20 *= corr; a21 *= corr; a22 *= corr; a23 *= corr; a24 *= corr;
            mx = lg;
        }
        float ee = __expf(lg - mx);
        den += ee;
        float ux = gm.y, uy = gm.z, uz = gm.w;
        a0 = fmaf(ee, m0, a0);
        float y0 = ux * uy, y1 = uy * uz, y2 = 3.f * uz * uz - 1.f;
        float y3 = ux * uz, y4 = ux * ux - uy * uy;
        float wf3 = w.x * ee, wf5 = w.y * ee;
        a10 = fmaf(wf3, ux, a10); a11 = fmaf(wf3, uy, a11); a12 = fmaf(wf3, uz, a12);
        a20 = fmaf(wf5, y0, a20); a21 = fmaf(wf5, y1, a21); a22 = fmaf(wf5, y2, a22);
        a23 = fmaf(wf5, y3, a23); a24 = fmaf(wf5, y4, a24);
    }
    float dinv = 1.f / (den + 1e-8f);
    float* ag = &g_agg[(size_t)n * 288];   // planar [9][32]
    ag[0 * 32 + lane] = a0 * dinv;
    ag[1 * 32 + lane] = a10 * dinv; ag[2 * 32 + lane] = a11 * dinv; ag[3 * 32 + lane] = a12 * dinv;
    ag[4 * 32 + lane] = a20 * dinv; ag[5 * 32 + lane] = a21 * dinv; ag[6 * 32 + lane] = a22 * dinv;
    ag[7 * 32 + lane] = a23 * dinv; ag[8 * 32 + lane] = a24 * dinv;
}

// ---------------- 5) layer-0 update (writes f0 fp32, f1/f2 fp16 planar) + kt for layer 1 ----------------
__global__ __launch_bounds__(256) void update_l0_kt_kernel(
    const float* __restrict__ Ws0, const float* __restrict__ Ws1,
    const float* __restrict__ Ws2, const float* __restrict__ Wsk,
    const float* __restrict__ Wq, const float* __restrict__ Wk) {
    __shared__ __align__(16) float s0[1024], s1[1024], s2[1024], sk[1024];
    __shared__ float sWq[1024], sWkT[1024];
    __shared__ __align__(16) float sag[8][384];   // [c][12] padded
    int tid = threadIdx.x;
    for (int i = tid; i < 1024; i += 256) {
        s0[i] = Ws0[i]; s1[i] = Ws1[i]; s2[i] = Ws2[i]; sk[i] = Wsk[i];
        sWq[i] = Wq[i];
        int c = i >> 5, j = i & 31;
        sWkT[j * 32 + c] = Wk[i];
    }
    __syncthreads();
    int warp = tid >> 5, lane = tid & 31;
    int n = blockIdx.x * 8 + warp;
    if (n >= Nn) return;
    float f = g_f0[(size_t)n * 32 + lane];
    {
        const float* ag = &g_agg[(size_t)n * 288];
#pragma unroll
        for (int s = 0; s < 9; s++)
            sag[warp][lane * 12 + s] = ag[s * 32 + lane];
    }
    __syncwarp();
    float o0 = 0.f, o10 = 0.f, o11 = 0.f, o12 = 0.f;
    float o20 = 0.f, o21 = 0.f, o22 = 0.f, o23 = 0.f, o24 = 0.f;
#pragma unroll 4
    for (int c = 0; c < 32; c++) {
        const float* ac = &sag[warp][c * 12];
        float4 A0 = *(const float4*)ac;
        float4 A1 = *(const float4*)(ac + 4);
        float A8 = ac[8];
        float fc = __shfl_sync(FULLMASK, f, c);
        o0 += A0.x * s0[c * 32 + lane] + fc * sk[c * 32 + lane];
        float w1 = s1[c * 32 + lane];
        o10 += A0.y * w1; o11 += A0.z * w1; o12 += A0.w * w1;
        float w2 = s2[c * 32 + lane];
        o20 += A1.x * w2; o21 += A1.y * w2; o22 += A1.z * w2;
        o23 += A1.w * w2; o24 += A8 * w2;
    }
    g_f0[(size_t)n * 32 + lane] = o0;
    __half* f1w = &g_f1h[(size_t)n * 96];
    f1w[0 * 32 + lane] = __float2half_rn(o10);
    f1w[1 * 32 + lane] = __float2half_rn(o11);
    f1w[2 * 32 + lane] = __float2half_rn(o12);
    __half* f2w = &g_f2h[(size_t)n * 160];
    f2w[0 * 32 + lane] = __float2half_rn(o20);
    f2w[1 * 32 + lane] = __float2half_rn(o21);
    f2w[2 * 32 + lane] = __float2half_rn(o22);
    f2w[3 * 32 + lane] = __float2half_rn(o23);
    f2w[4 * 32 + lane] = __float2half_rn(o24);
    float q = 0.f;
#pragma unroll
    for (int c = 0; c < 32; c++) {
        float fc = __shfl_sync(FULLMASK, o0, c);
        q = fmaf(fc, sWq[c * 32 + lane], q);
    }
#pragma unroll
    for (int h = 0; h < 4; h++) {
        float kt = 0.f;
#pragma unroll
        for (int d = 0; d < 8; d++) {
            float qd = __shfl_sync(FULLMASK, q, h * 8 + d);
            kt = fmaf(qd, sWkT[(h * 8 + d) * 32 + lane], kt);
        }
        g_kt[(size_t)n * 128 + kt_perm(h, lane)] = kt * LOGIT_SCALE;
    }
}

// ---------------- 7) fused layer-1 agg (fp16 m0 stream) + f0 update + output + deg re-zero ----------------
__global__ __launch_bounds__(256) void agg_update_out_kernel(
    const float* __restrict__ Ws0, const float* __restrict__ Wsk,
    const float* __restrict__ Wout, const float* __restrict__ Wc,
    float* __restrict__ out) {
    __shared__ __align__(16) float s0[1024], sk[1024], sWo[1024];
    __shared__ float sWc[480];
    int tid = threadIdx.x;
    for (int i = tid; i < 1024; i += 256) {
        s0[i] = Ws0[i]; sk[i] = Wsk[i]; sWo[i] = Wout[i];
    }
    for (int i = tid; i < 480; i += 256) sWc[i] = Wc[i];
    __syncthreads();
    int warp = tid >> 5, lane = tid & 31;
    int n = blockIdx.x * 8 + warp;
    if (n >= Nn) return;
    if (lane == 0) g_deg[n] = 0;   // leave deg zeroed for the next invocation
    int beg = g_off[n], end = g_off[n + 1];
    int grp = lane >> 3;

    float mx = -3.0e38f;
    float den = 0.f, a0 = 0.f;
#pragma unroll 2
    for (int i = beg; i < end; i++) {
        float lg = g_logit[(size_t)i * 4 + grp];
        float m0 = __half2float(g_m0h[(size_t)i * 32 + lane]);
        if (lg > mx) {
            float corr = __expf(mx - lg);
            den *= corr; a0 *= corr;
            mx = lg;
        }
        float ee = __expf(lg - mx);
        den += ee;
        a0 = fmaf(ee, m0, a0);
    }
    float a = a0 / (den + 1e-8f);   // agg0[n][lane], stays in registers

    float f = g_f0[(size_t)n * 32 + lane];
    float o0 = 0.f;
#pragma unroll
    for (int c = 0; c < 32; c++) {
        float fc = __shfl_sync(FULLMASK, f, c);
        float ac = __shfl_sync(FULLMASK, a, c);
        o0 += ac * s0[c * 32 + lane] + fc * sk[c * 32 + lane];
    }
    float hs = 0.f;
#pragma unroll
    for (int c = 0; c < 32; c++) {
        float oc = __shfl_sync(FULLMASK, o0, c);
        hs = fmaf(oc, sWo[c * 32 + lane], hs);
    }
    out[(size_t)n * 32 + lane] = hs;
    float cacc = 0.f;
#pragma unroll
    for (int j = 0; j < 32; j++) {
        float hj = __shfl_sync(FULLMASK, hs, j);
        if (lane < 15) cacc = fmaf(hj, sWc[j * 15 + lane], cacc);
    }
    if (lane < 15) out[(size_t)Nn * 32 + (size_t)n * 15 + lane] = cacc;
}

// ---------------- launch ----------------
extern "C" void kernel_launch(void* const* d_in, const int* in_sizes, int n_in,
                              void* d_out, int out_size) {
    const float* pos       = (const float*)d_in[0];
    const float* node_l0   = (const float*)d_in[1];
    const float* edge_feat = (const float*)d_in[2];
    const int*   esrc      = (const int*)d_in[3];
    const int*   edst      = (const int*)d_in[4];
    const float* Wr1       = (const float*)d_in[5];
    const float* br1       = (const float*)d_in[6];
    const float* Wr2       = (const float*)d_in[7];
    const float* Wq        = (const float*)d_in[8];
    const float* Wk        = (const float*)d_in[9];
    const float* Ws0       = (const float*)d_in[10];
    const float* Ws1       = (const float*)d_in[11];
    const float* Ws2       = (const float*)d_in[12];
    const float* Wsk       = (const float*)d_in[13];
    const float* Wout      = (const float*)d_in[14];
    const float* Wc        = (const float*)d_in[15];
    float* out = (float*)d_out;

    const int NODE_BLKS = NODE_BLKS_C;
    const int EDGE_BLKS = Ee / 128;   // warp per 8 edges, 8 warps, 2 tiles per block

    init_geom_kernel<<<NODE_BLKS_C + GEOM_BLKS_C, 256>>>(node_l0, Wq, Wk,
                                                         pos, esrc, edst);         // 1
    scan_kernel<<<1, 1024>>>();                                                    // 2
    edge_kernel<true><<<EDGE_BLKS, 256>>>(edge_feat, esrc, edst, Wr1, br1, Wr2);   // 3
    agg_l0_kernel<<<NODE_BLKS, 256>>>();                                           // 4 (profiled slot)
    update_l0_kt_kernel<<<NODE_BLKS, 256>>>(Ws0, Ws1, Ws2, Wsk,
                                            Wq + 1024, Wk + 1024);                 // 5
    edge_kernel<false><<<EDGE_BLKS, 256>>>(edge_feat, esrc, edst, Wr1 + 1056,
                                           br1 + 32, Wr2 + 7168);                  // 6
    agg_update_out_kernel<<<NODE_BLKS, 256>>>(Ws0 + 1024, Wsk + 1024, Wout, Wc, out); // 7
}

// round 16
// speedup vs baseline: 1.1936x; 1.0637x over previous
#include <cuda_runtime.h>
#include <cuda_fp16.h>

#define Nn 30000
#define Ee 480000
#define FULLMASK 0xffffffffu
#define NODE_BLKS_C 3750      // (Nn+7)/8
#define GEOM_BLKS_C 1875      // Ee/256

typedef unsigned long long ull;

// packed fp32x2 helpers (Blackwell FFMA2 path — PTX only)
#define PACK2(d, lo, hi) asm("mov.b64 %0, {%1, %2};" : "=l"(d) : "f"(lo), "f"(hi))
#define UNPACK2(lo, hi, s) asm("mov.b64 {%0, %1}, %2;" : "=f"(lo), "=f"(hi) : "l"(s))
#define FMA2(acc, a, b) asm("fma.rn.f32x2 %0, %1, %2, %0;" : "+l"(acc) : "l"(a), "l"(b))

// ---------------- scratch (static device allocations; no cudaMalloc) ----------------
__device__ __align__(16) float g_geom[Ee * 4];    // edge-order: r, ux, uy, uz
__device__ __align__(16) float g_geomp[Ee * 4];   // CSR-order copy (agg_l0 stream)
__device__ __align__(16) __half g_m0h[Ee * 32];   // CSR-order, fp16 (logits use fp32 reg copy)
__device__ __align__(16) __half2 g_wh[Ee * 32];   // CSR-order, layer0: [p][32] half2 (w3*f0s, w5*f0s)
__device__ __align__(16) float g_logit[Ee * 4];   // CSR-order
__device__ __align__(16) float g_kt[Nn * 128];    // permuted + pre-scaled by 1/sqrt(8)
__device__ float g_f0[Nn * 32];
__device__ __align__(16) __half g_f1h[Nn * 96];   // planar [n][3][32], fp16 (l=1 correction path)
__device__ __align__(16) __half g_f2h[Nn * 160];  // planar [n][5][32], fp16
__device__ int g_deg[Nn];          // zero-init at load; re-zeroed by last kernel each call
__device__ int g_off[Nn + 1];
__device__ int g_cur[Nn];
__device__ int g_pos[Ee];          // edge -> CSR slot (set by edge_l0, used by edge_l1)

// kt permutation: value for (head h, channel c) stored at (c>>3)*32 + h*8 + (c&7)
__device__ __forceinline__ int kt_perm(int h, int c) {
    return ((c >> 3) << 5) + (h << 3) + (c & 7);
}

#define LOGIT_SCALE 0.35355339059327373f   // 1/sqrt(8), folded into kt

// ---------------- 1) fused init: node blocks do f0-copy + kt(L0); edge blocks do geom+hist ----------------
__global__ __launch_bounds__(256) void init_geom_kernel(
    const float* __restrict__ node_l0, const float* __restrict__ Wq,
    const float* __restrict__ Wk, const float* __restrict__ pos,
    const int* __restrict__ esrc, const int* __restrict__ edst) {
    __shared__ float sWq[1024];    // [c][j]
    __shared__ float sWkT[1024];   // [j][c]
    int tid = threadIdx.x;
    if (blockIdx.x < NODE_BLKS_C) {
        for (int i = tid; i < 1024; i += 256) {
            sWq[i] = Wq[i];
            int c = i >> 5, j = i & 31;
            sWkT[j * 32 + c] = Wk[i];
        }
        __syncthreads();
        int warp = tid >> 5, lane = tid & 31;
        int n = blockIdx.x * 8 + warp;
        if (n >= Nn) return;
        float f = node_l0[(size_t)n * 32 + lane];
        g_f0[(size_t)n * 32 + lane] = f;
        float q = 0.f;
#pragma unroll
        for (int c = 0; c < 32; c++) {
            float fc = __shfl_sync(FULLMASK, f, c);
            q = fmaf(fc, sWq[c * 32 + lane], q);
        }
#pragma unroll
        for (int h = 0; h < 4; h++) {
            float kt = 0.f;
#pragma unroll
            for (int d = 0; d < 8; d++) {
                float qd = __shfl_sync(FULLMASK, q, h * 8 + d);
                kt = fmaf(qd, sWkT[(h * 8 + d) * 32 + lane], kt);
            }
            g_kt[(size_t)n * 128 + kt_perm(h, lane)] = kt * LOGIT_SCALE;
        }
    } else {
        int e = (blockIdx.x - NODE_BLKS_C) * 256 + tid;
        if (e >= Ee) return;
        int s = esrc[e], d = edst[e];
        float rx = pos[d * 3 + 0] - pos[s * 3 + 0];
        float ry = pos[d * 3 + 1] - pos[s * 3 + 1];
        float rz = pos[d * 3 + 2] - pos[s * 3 + 2];
        float r = sqrtf(rx * rx + ry * ry + rz * rz + 1e-8f);
        float inv = 1.0f / r;
        ((float4*)g_geom)[e] = make_float4(r, rx * inv, ry * inv, rz * inv);
        atomicAdd(&g_deg[d], 1);
    }
}

// ---------------- 2) exclusive scan (writes g_off and g_cur) ----------------
__global__ void scan_kernel() {
    __shared__ int sp[1024];
    const int CH = 30;
    int t = threadIdx.x;
    int loc[CH];
    int base = t * CH;
    int s = 0;
#pragma unroll
    for (int i = 0; i < CH; i++) {
        int idx = base + i;
        int v = (idx < Nn) ? g_deg[idx] : 0;
        loc[i] = v;
        s += v;
    }
    sp[t] = s;
    __syncthreads();
    for (int off = 1; off < 1024; off <<= 1) {
        int v = (t >= off) ? sp[t - off] : 0;
        __syncthreads();
        sp[t] += v;
        __syncthreads();
    }
    int run = (t == 0) ? 0 : sp[t - 1];
#pragma unroll
    for (int i = 0; i < CH; i++) {
        int idx = base + i;
        if (idx < Nn) { g_off[idx] = run; g_cur[idx] = run; run += loc[i]; }
    }
    if (t == 1023) g_off[Nn] = sp[1023];
}

// ---------------- 3/5) edge kernel: warp per 8 edges, 2 tiles per block (preamble amortized) ----------------
// FIRST (layer0): planes = (w0, w3, w5); stores m0h/wh/logit/geomp at CSR slot p; records g_pos.
// !FIRST (layer1): planes = (w0, w1, w2); reads fp16 f1/f2; stores m0h/logit at p = g_pos[e].
template <bool FIRST>
__global__ __launch_bounds__(256) void edge_kernel(
    const float* __restrict__ edge_feat, const int* __restrict__ esrc,
    const int* __restrict__ edst, const float* __restrict__ Wr1,
    const float* __restrict__ br1, const float* __restrict__ Wr2) {
    __shared__ __align__(16) float sWr1[33 * 32];
    __shared__ float sbr1[32];
    __shared__ float sWp0[1024];   // [j][c] plane 0 (w0)
    __shared__ float sWp1[1024];   // plane 1 (w3 | w1)
    __shared__ float sWp2[1024];   // plane 2 (w5 | w2)
    __shared__ __align__(16) float sstage[8][256];  // [warp][i*8+k]
    int tid = threadIdx.x;
    for (int i = tid; i < 33 * 32; i += 256) sWr1[i] = Wr1[i];
    if (tid < 32) sbr1[tid] = br1[tid];
    const int off1 = FIRST ? 96 : 32, off2 = FIRST ? 160 : 64;
    for (int i = tid; i < 1024; i += 256) {
        int j = i >> 5, c = i & 31;
        const float* row = Wr2 + j * 224;
        sWp0[i] = row[c];
        sWp1[i] = row[off1 + c];
        sWp2[i] = row[off2 + c];
    }
    __syncthreads();
    int lane = tid & 31, warp = tid >> 5;
    int sub = lane & 7;
    float* sst = sstage[warp];

#pragma unroll 1
    for (int tile = 0; tile < 2; tile++) {
        int e0 = (blockIdx.x * 2 + tile) * 64 + warp * 8;   // Ee % 128 == 0

        float t0, t1, t2, t3, t4, t5, t6, t7;
        t0 = edge_feat[(size_t)(e0 + 0) * 32 + lane];
        t1 = edge_feat[(size_t)(e0 + 1) * 32 + lane];
        t2 = edge_feat[(size_t)(e0 + 2) * 32 + lane];
        t3 = edge_feat[(size_t)(e0 + 3) * 32 + lane];
        t4 = edge_feat[(size_t)(e0 + 4) * 32 + lane];
        t5 = edge_feat[(size_t)(e0 + 5) * 32 + lane];
        t6 = edge_feat[(size_t)(e0 + 6) * 32 + lane];
        t7 = edge_feat[(size_t)(e0 + 7) * 32 + lane];
        __syncwarp();
        {
            float4* sp = (float4*)(sst + lane * 8);
            sp[0] = make_float4(t0, t1, t2, t3);
            sp[1] = make_float4(t4, t5, t6, t7);
        }
        __syncwarp();

        float bia = sbr1[lane], w0l = sWr1[lane];
        t0 = fmaf(g_geom[(size_t)(e0 + 0) * 4], w0l, bia);
        t1 = fmaf(g_geom[(size_t)(e0 + 1) * 4], w0l, bia);
        t2 = fmaf(g_geom[(size_t)(e0 + 2) * 4], w0l, bia);
        t3 = fmaf(g_geom[(size_t)(e0 + 3) * 4], w0l, bia);
        t4 = fmaf(g_geom[(size_t)(e0 + 4) * 4], w0l, bia);
        t5 = fmaf(g_geom[(size_t)(e0 + 5) * 4], w0l, bia);
        t6 = fmaf(g_geom[(size_t)(e0 + 6) * 4], w0l, bia);
        t7 = fmaf(g_geom[(size_t)(e0 + 7) * 4], w0l, bia);
        ull h01, h23, h45, h67;
        PACK2(h01, t0, t1); PACK2(h23, t2, t3); PACK2(h45, t4, t5); PACK2(h67, t6, t7);
#pragma unroll
        for (int i = 0; i < 32; i++) {
            const ulonglong2* xp = (const ulonglong2*)(sst + i * 8);
            ulonglong2 xa = xp[0], xb = xp[1];   // LDS.128 x2 (broadcast)
            float wc = sWr1[(i + 1) * 32 + lane];
            ull wd; PACK2(wd, wc, wc);
            FMA2(h01, xa.x, wd); FMA2(h23, xa.y, wd); FMA2(h45, xb.x, wd); FMA2(h67, xb.y, wd);
        }
        UNPACK2(t0, t1, h01); UNPACK2(t2, t3, h23); UNPACK2(t4, t5, h45); UNPACK2(t6, t7, h67);
        t0 = fmaxf(t0, 0.f); t1 = fmaxf(t1, 0.f); t2 = fmaxf(t2, 0.f); t3 = fmaxf(t3, 0.f);
        t4 = fmaxf(t4, 0.f); t5 = fmaxf(t5, 0.f); t6 = fmaxf(t6, 0.f); t7 = fmaxf(t7, 0.f);
        __syncwarp();
        {
            float4* sp = (float4*)(sst + lane * 8);
            sp[0] = make_float4(t0, t1, t2, t3);
            sp[1] = make_float4(t4, t5, t6, t7);
        }
        __syncwarp();

        ull a0[4] = {0, 0, 0, 0}, a1[4] = {0, 0, 0, 0}, a2[4] = {0, 0, 0, 0};
#pragma unroll
        for (int j = 0; j < 32; j++) {
            const ulonglong2* hp = (const ulonglong2*)(sst + j * 8);
            ulonglong2 ha = hp[0], hb = hp[1];   // LDS.128 x2 (broadcast)
            float w0c = sWp0[j * 32 + lane];     // 3 scalar LDS.32 (1 wf each)
            float w1c = sWp1[j * 32 + lane];
            float w2c = sWp2[j * 32 + lane];
            ull p0, p1, p2;
            PACK2(p0, w0c, w0c); PACK2(p1, w1c, w1c); PACK2(p2, w2c, w2c);
            FMA2(a0[0], ha.x, p0); FMA2(a0[1], ha.y, p0); FMA2(a0[2], hb.x, p0); FMA2(a0[3], hb.y, p0);
            FMA2(a1[0], ha.x, p1); FMA2(a1[1], ha.y, p1); FMA2(a1[2], hb.x, p1); FMA2(a1[3], hb.y, p1);
            FMA2(a2[0], ha.x, p2); FMA2(a2[1], ha.y, p2); FMA2(a2[2], hb.x, p2); FMA2(a2[3], hb.y, p2);
        }

#pragma unroll
        for (int q2 = 0; q2 < 4; q2++) {
            float W0a, W0b, W1a, W1b, W2a, W2b;
            UNPACK2(W0a, W0b, a0[q2]);
            UNPACK2(W1a, W1b, a1[q2]);
            UNPACK2(W2a, W2b, a2[q2]);
#pragma unroll
            for (int kk = 0; kk < 2; kk++) {
                int e = e0 + q2 * 2 + kk;
                float W0 = kk ? W0b : W0a, W1 = kk ? W1b : W1a, W2 = kk ? W2b : W2a;
                int src = esrc[e], dst = edst[e];
                float f0s = g_f0[(size_t)src * 32 + lane];
                float m0;
                int p;
                if (FIRST) {
                    m0 = W0 * f0s;
                    float4 gm = ((const float4*)g_geom)[e];
                    if (lane == 0) p = atomicAdd(&g_cur[dst], 1);
                    p = __shfl_sync(FULLMASK, p, 0);
                    if (lane == 0) {
                        g_pos[e] = p;
                        ((float4*)g_geomp)[p] = gm;
                    }
                    g_wh[(size_t)p * 32 + lane] = __floats2half2_rn(W1 * f0s, W2 * f0s);
                } else {
                    float4 gm = ((const float4*)g_geom)[e];
                    float ux = gm.y, uy = gm.z, uz = gm.w;
                    const __half* f1p = &g_f1h[(size_t)src * 96];
                    const __half* f2p = &g_f2h[(size_t)src * 160];
                    float d1 = __half2float(f1p[lane]) * ux + __half2float(f1p[32 + lane]) * uy +
                               __half2float(f1p[64 + lane]) * uz;
                    float s0 = ux * uy, s1 = uy * uz, s2 = 3.f * uz * uz - 1.f;
                    float s3 = ux * uz, s4 = ux * ux - uy * uy;
                    float d2 = __half2float(f2p[lane]) * s0 + __half2float(f2p[32 + lane]) * s1 +
                               __half2float(f2p[64 + lane]) * s2 + __half2float(f2p[96 + lane]) * s3 +
                               __half2float(f2p[128 + lane]) * s4;
                    m0 = fmaf(W1, d1, fmaf(W2, d2, W0 * f0s));
                    p = g_pos[e];   // broadcast load
                }
                g_m0h[(size_t)p * 32 + lane] = __float2half_rn(m0);
                const float* ktp = &g_kt[(size_t)dst * 128];
                float v = 0.f;
#pragma unroll
                for (int k2 = 0; k2 < 4; k2++) {
                    float mc = __shfl_sync(FULLMASK, m0, sub + 8 * k2);   // fp32 logit path
                    v = fmaf(mc, ktp[k2 * 32 + lane], v);
                }
                v += __shfl_xor_sync(FULLMASK, v, 1);
                v += __shfl_xor_sync(FULLMASK, v, 2);
                v += __shfl_xor_sync(FULLMASK, v, 4);
                if (sub == 0)
                    g_logit[(size_t)p * 4 + (lane >> 3)] = v;   // kt pre-scaled by 1/sqrt(8)
            }
        }
    }
}

// ---------------- 4) FUSED layer-0 aggregation + update + kt: agg accumulators pass via smem ----------------
__global__ __launch_bounds__(256) void agg_update_l0_kt_kernel(
    const float* __restrict__ Ws0, const float* __restrict__ Ws1,
    const float* __restrict__ Ws2, const float* __restrict__ Wsk,
    const float* __restrict__ Wq, const float* __restrict__ Wk) {
    __shared__ __align__(16) float s0[1024], s1[1024], s2[1024], sk[1024];
    __shared__ float sWq[1024], sWkT[1024];
    __shared__ __align__(16) float sag[8][384];   // [c][12] padded
    int tid = threadIdx.x;
    for (int i = tid; i < 1024; i += 256) {
        s0[i] = Ws0[i]; s1[i] = Ws1[i]; s2[i] = Ws2[i]; sk[i] = Wsk[i];
        sWq[i] = Wq[i];
        int c = i >> 5, j = i & 31;
        sWkT[j * 32 + c] = Wk[i];
    }
    __syncthreads();
    int warp = tid >> 5, lane = tid & 31;
    int n = blockIdx.x * 8 + warp;
    if (n >= Nn) return;
    int beg = g_off[n], end = g_off[n + 1];
    int grp = lane >> 3;

    // ---- aggregation (online softmax, sequential fp16 streams) ----
    float mx = -3.0e38f;
    float den = 0.f;
    float a0 = 0.f, a10 = 0.f, a11 = 0.f, a12 = 0.f;
    float a20 = 0.f, a21 = 0.f, a22 = 0.f, a23 = 0.f, a24 = 0.f;
#pragma unroll 2
    for (int i = beg; i < end; i++) {
        float lg = g_logit[(size_t)i * 4 + grp];
        float m0 = __half2float(g_m0h[(size_t)i * 32 + lane]);
        float4 gm = ((const float4*)g_geomp)[i];
        float2 w = __half22float2(g_wh[(size_t)i * 32 + lane]);
        if (lg > mx) {   // rescale accumulators (expected ~ln(deg) hits)
            float corr = __expf(mx - lg);   // first hit: -> 0 with zero accums
            den *= corr; a0 *= corr;
            a10 *= corr; a11 *= corr; a12 *= corr;
            a20 *= corr; a21 *= corr; a22 *= corr; a23 *= corr; a24 *= corr;
            mx = lg;
        }
        float ee = __expf(lg - mx);
        den += ee;
        float ux = gm.y, uy = gm.z, uz = gm.w;
        a0 = fmaf(ee, m0, a0);
        float y0 = ux * uy, y1 = uy * uz, y2 = 3.f * uz * uz - 1.f;
        float y3 = ux * uz, y4 = ux * ux - uy * uy;
        float wf3 = w.x * ee, wf5 = w.y * ee;
        a10 = fmaf(wf3, ux, a10); a11 = fmaf(wf3, uy, a11); a12 = fmaf(wf3, uz, a12);
        a20 = fmaf(wf5, y0, a20); a21 = fmaf(wf5, y1, a21); a22 = fmaf(wf5, y2, a22);
        a23 = fmaf(wf5, y3, a23); a24 = fmaf(wf5, y4, a24);
    }
    float dinv = 1.f / (den + 1e-8f);
    {   // stage normalized accumulators in smem (replaces g_agg round-trip)
        float* ac = &sag[warp][lane * 12];
        ac[0] = a0 * dinv;
        ac[1] = a10 * dinv; ac[2] = a11 * dinv; ac[3] = a12 * dinv;
        ac[4] = a20 * dinv; ac[5] = a21 * dinv; ac[6] = a22 * dinv;
        ac[7] = a23 * dinv; ac[8] = a24 * dinv;
    }
    __syncwarp();

    // ---- node update ----
    float f = g_f0[(size_t)n * 32 + lane];
    float o0 = 0.f, o10 = 0.f, o11 = 0.f, o12 = 0.f;
    float o20 = 0.f, o21 = 0.f, o22 = 0.f, o23 = 0.f, o24 = 0.f;
#pragma unroll 4
    for (int c = 0; c < 32; c++) {
        const float* ac = &sag[warp][c * 12];
        float4 A0 = *(const float4*)ac;
        float4 A1 = *(const float4*)(ac + 4);
        float A8 = ac[8];
        float fc = __shfl_sync(FULLMASK, f, c);
        o0 += A0.x * s0[c * 32 + lane] + fc * sk[c * 32 + lane];
        float w1 = s1[c * 32 + lane];
        o10 += A0.y * w1; o11 += A0.z * w1; o12 += A0.w * w1;
        float w2 = s2[c * 32 + lane];
        o20 += A1.x * w2; o21 += A1.y * w2; o22 += A1.z * w2;
        o23 += A1.w * w2; o24 += A8 * w2;
    }
    g_f0[(size_t)n * 32 + lane] = o0;
    __half* f1w = &g_f1h[(size_t)n * 96];
    f1w[0 * 32 + lane] = __float2half_rn(o10);
    f1w[1 * 32 + lane] = __float2half_rn(o11);
    f1w[2 * 32 + lane] = __float2half_rn(o12);
    __half* f2w = &g_f2h[(size_t)n * 160];
    f2w[0 * 32 + lane] = __float2half_rn(o20);
    f2w[1 * 32 + lane] = __float2half_rn(o21);
    f2w[2 * 32 + lane] = __float2half_rn(o22);
    f2w[3 * 32 + lane] = __float2half_rn(o23);
    f2w[4 * 32 + lane] = __float2half_rn(o24);

    // ---- kt for layer 1 from updated f0 ----
    float q = 0.f;
#pragma unroll
    for (int c = 0; c < 32; c++) {
        float fc = __shfl_sync(FULLMASK, o0, c);
        q = fmaf(fc, sWq[c * 32 + lane], q);
    }
#pragma unroll
    for (int h = 0; h < 4; h++) {
        float kt = 0.f;
#pragma unroll
        for (int d = 0; d < 8; d++) {
            float qd = __shfl_sync(FULLMASK, q, h * 8 + d);
            kt = fmaf(qd, sWkT[(h * 8 + d) * 32 + lane], kt);
        }
        g_kt[(size_t)n * 128 + kt_perm(h, lane)] = kt * LOGIT_SCALE;
    }
}

// ---------------- 6) fused layer-1 agg (fp16 m0 stream) + f0 update + output + deg re-zero ----------------
__global__ __launch_bounds__(256) void agg_update_out_kernel(
    const float* __restrict__ Ws0, const float* __restrict__ Wsk,
    const float* __restrict__ Wout, const float* __restrict__ Wc,
    float* __restrict__ out) {
    __shared__ __align__(16) float s0[1024], sk[1024], sWo[1024];
    __shared__ float sWc[480];
    int tid = threadIdx.x;
    for (int i = tid; i < 1024; i += 256) {
        s0[i] = Ws0[i]; sk[i] = Wsk[i]; sWo[i] = Wout[i];
    }
    for (int i = tid; i < 480; i += 256) sWc[i] = Wc[i];
    __syncthreads();
    int warp = tid >> 5, lane = tid & 31;
    int n = blockIdx.x * 8 + warp;
    if (n >= Nn) return;
    if (lane == 0) g_deg[n] = 0;   // leave deg zeroed for the next invocation
    int beg = g_off[n], end = g_off[n + 1];
    int grp = lane >> 3;

    float mx = -3.0e38f;
    float den = 0.f, a0 = 0.f;
#pragma unroll 2
    for (int i = beg; i < end; i++) {
        float lg = g_logit[(size_t)i * 4 + grp];
        float m0 = __half2float(g_m0h[(size_t)i * 32 + lane]);
        if (lg > mx) {
            float corr = __expf(mx - lg);
            den *= corr; a0 *= corr;
            mx = lg;
        }
        float ee = __expf(lg - mx);
        den += ee;
        a0 = fmaf(ee, m0, a0);
    }
    float a = a0 / (den + 1e-8f);   // agg0[n][lane], stays in registers

    float f = g_f0[(size_t)n * 32 + lane];
    float o0 = 0.f;
#pragma unroll
    for (int c = 0; c < 32; c++) {
        float fc = __shfl_sync(FULLMASK, f, c);
        float ac = __shfl_sync(FULLMASK, a, c);
        o0 += ac * s0[c * 32 + lane] + fc * sk[c * 32 + lane];
    }
    float hs = 0.f;
#pragma unroll
    for (int c = 0; c < 32; c++) {
        float oc = __shfl_sync(FULLMASK, o0, c);
        hs = fmaf(oc, sWo[c * 32 + lane], hs);
    }
    out[(size_t)n * 32 + lane] = hs;
    float cacc = 0.f;
#pragma unroll
    for (int j = 0; j < 32; j++) {
        float hj = __shfl_sync(FULLMASK, hs, j);
        if (lane < 15) cacc = fmaf(hj, sWc[j * 15 + lane], cacc);
    }
    if (lane < 15) out[(size_t)Nn * 32 + (size_t)n * 15 + lane] = cacc;
}

// ---------------- launch ----------------
extern "C" void kernel_launch(void* const* d_in, const int* in_sizes, int n_in,
                              void* d_out, int out_size) {
    const float* pos       = (const float*)d_in[0];
    const float* node_l0   = (const float*)d_in[1];
    const float* edge_feat = (const float*)d_in[2];
    const int*   esrc      = (const int*)d_in[3];
    const int*   edst      = (const int*)d_in[4];
    const float* Wr1       = (const float*)d_in[5];
    const float* br1       = (const float*)d_in[6];
    const float* Wr2       = (const float*)d_in[7];
    const float* Wq        = (const float*)d_in[8];
    const float* Wk        = (const float*)d_in[9];
    const float* Ws0       = (const float*)d_in[10];
    const float* Ws1       = (const float*)d_in[11];
    const float* Ws2       = (const float*)d_in[12];
    const float* Wsk       = (const float*)d_in[13];
    const float* Wout      = (const float*)d_in[14];
    const float* Wc        = (const float*)d_in[15];
    float* out = (float*)d_out;

    const int NODE_BLKS = NODE_BLKS_C;
    const int EDGE_BLKS = Ee / 128;   // warp per 8 edges, 8 warps, 2 tiles per block

    init_geom_kernel<<<NODE_BLKS_C + GEOM_BLKS_C, 256>>>(node_l0, Wq, Wk,
                                                         pos, esrc, edst);         // 1
    scan_kernel<<<1, 1024>>>();                                                    // 2
    edge_kernel<true><<<EDGE_BLKS, 256>>>(edge_feat, esrc, edst, Wr1, br1, Wr2);   // 3
    agg_update_l0_kt_kernel<<<NODE_BLKS, 256>>>(Ws0, Ws1, Ws2, Wsk,
                                                Wq + 1024, Wk + 1024);             // 4 (profiled slot)
    edge_kernel<false><<<EDGE_BLKS, 256>>>(edge_feat, esrc, edst, Wr1 + 1056,
                                           br1 + 32, Wr2 + 7168);                  // 5
    agg_update_out_kernel<<<NODE_BLKS, 256>>>(Ws0 + 1024, Wsk + 1024, Wout, Wc, out); // 6
}